// round 9
// baseline (speedup 1.0000x reference)
#include <cuda_runtime.h>
#include <cuda_fp16.h>
#include <cstdint>
#include <cstddef>

#define PADC 8

// ---------------- static device buffers ----------------
__device__ __align__(256) float g_corr[12577280];
__device__ __align__(256) float g_map [11141120];
__device__ __align__(256) __half g_wm_h[7667712];   // [lvl][chunk26][tap9][co256][ci32] swizzled
__device__ __align__(256) __half g_wo_h[2359296];   // [lvl][chunk8][tap9][co256][ci32]
__device__ __align__(256) __half g_am_h[37832704];  // [lvl][chunk][b][Hp][Wp][32] swizzled
__device__ __align__(256) __half g_am_l[37832704];
__device__ __align__(256) __half g_ao_h[11640832];
__device__ __align__(256) __half g_ao_l[11640832];

// ---------------- PTX helpers (compute_103 baseline-safe) ----------------
__device__ __forceinline__ uint32_t smem_u32(const void* p){
    uint32_t a;
    asm("{ .reg .u64 t; cvta.to.shared.u64 t, %1; cvt.u32.u64 %0, t; }" : "=r"(a) : "l"(p));
    return a;
}
__device__ __forceinline__ void mbar_init(uint32_t a, uint32_t cnt){
    asm volatile("mbarrier.init.shared.b64 [%0], %1;" :: "r"(a), "r"(cnt) : "memory");
}
__device__ __forceinline__ void mbar_expect(uint32_t a, uint32_t bytes){
    asm volatile("mbarrier.arrive.expect_tx.shared.b64 _, [%0], %1;" :: "r"(a), "r"(bytes) : "memory");
}
__device__ __forceinline__ void mbar_wait(uint32_t a, int parity){
    asm volatile(
        "{\n\t.reg .pred P;\n\t"
        "WL_%=:\n\t"
        "mbarrier.try_wait.parity.acquire.cta.shared::cta.b64 P, [%0], %1, 0x989680;\n\t"
        "@P bra WD_%=;\n\t"
        "bra WL_%=;\n\t"
        "WD_%=:\n\t}"
        :: "r"(a), "r"(parity) : "memory");
}
__device__ __forceinline__ void bulk_cp(uint32_t dst, const void* src, uint32_t bytes, uint32_t mbar){
    asm volatile(
        "cp.async.bulk.shared::cluster.global.mbarrier::complete_tx::bytes [%0], [%1], %2, [%3];"
        :: "r"(dst), "l"(src), "r"(bytes), "r"(mbar) : "memory");
}
__device__ __forceinline__ void ldmx4(uint32_t* r, uint32_t addr){
    asm volatile("ldmatrix.sync.aligned.m8n8.x4.shared.b16 {%0,%1,%2,%3}, [%4];"
                 : "=r"(r[0]), "=r"(r[1]), "=r"(r[2]), "=r"(r[3]) : "r"(addr));
}
__device__ __forceinline__ void mma16816(float* c, const uint32_t* a, uint32_t b0, uint32_t b1){
    asm volatile(
        "mma.sync.aligned.m16n8k16.row.col.f32.f16.f16.f32 "
        "{%0,%1,%2,%3}, {%4,%5,%6,%7}, {%8,%9}, {%0,%1,%2,%3};"
        : "+f"(c[0]), "+f"(c[1]), "+f"(c[2]), "+f"(c[3])
        : "r"(a[0]), "r"(a[1]), "r"(a[2]), "r"(a[3]), "r"(b0), "r"(b1));
}
// packed f32x2 helpers
__device__ __forceinline__ unsigned long long pk2(float a, float b){
    unsigned long long r; asm("mov.b64 %0, {%1,%2};" : "=l"(r) : "f"(a), "f"(b)); return r;
}
__device__ __forceinline__ void fma2(unsigned long long &d, unsigned long long a, unsigned long long b){
    asm("fma.rn.f32x2 %0, %1, %2, %0;" : "+l"(d) : "l"(a), "l"(b));
}
__device__ __forceinline__ float2 upk(unsigned long long v){
    float2 f; asm("mov.b64 {%0,%1}, %2;" : "=f"(f.x), "=f"(f.y) : "l"(v)); return f;
}

// ================= merged init bias (3 regions) =================
struct InitParams {
    float* out[3];
    const float* bias[3];
    int HW[3];
    long base[4];
};
__global__ void k_init_all(const __grid_constant__ InitParams P){
    long i = (long)blockIdx.x * blockDim.x + threadIdx.x;
    if (i >= P.base[3]) return;
    int r = 0;
    if (i >= P.base[1]) r = 1;
    if (i >= P.base[2]) r = 2;
    long loc = i - P.base[r];
    P.out[r][loc] = P.bias[r][(loc / P.HW[r]) & 255];
}

// ================= merged weight pack (8 tensors) =================
struct PackWParams {
    const float* src[8];
    __half* dst[8];
    int Cin[8];
    int Cpad[8];
    long base[9];
};
__global__ void k_pack_w_all(const __grid_constant__ PackWParams P){
    long i = (long)blockIdx.x * 256 + threadIdx.x;
    if (i >= P.base[8]) return;
    int t = 0;
    #pragma unroll
    for (int k = 1; k < 8; k++) if (i >= P.base[k]) t = k;
    long loc = i - P.base[t];
    int Cpad = P.Cpad[t], Cin = P.Cin[t];
    int co = (int)(loc / Cpad), ci = (int)(loc % Cpad);
    int c = ci >> 5, cl = ci & 31;
    int gsw = (cl >> 3) ^ ((co >> 1) & 3);
    const float* w = P.src[t];
    __half* oh = P.dst[t];
    #pragma unroll
    for (int tap = 0; tap < 9; tap++){
        float v = (ci < Cin) ? w[(size_t)(co * Cin + ci) * 9 + tap] : 0.f;
        size_t o = (((size_t)c * 9 + tap) * 256 + co) * 32 + (gsw << 3) + (cl & 7);
        oh[o] = __float2half_rn(v);
    }
}

// ================= merged correlation (4 levels), f32x2 packed inner =================
struct CorrParams {
    const float* x[4];
    const float* rx[4];
    float* out[4];
    int H[4];
    int GX[4];
    int grp[4];
    int blkBase[5];
};
__global__ void k_corr_all(const __grid_constant__ CorrParams P){
    const int bid = blockIdx.x;
    int l = 0;
    if (bid >= P.blkBase[1]) l = 1;
    if (bid >= P.blkBase[2]) l = 2;
    if (bid >= P.blkBase[3]) l = 3;
    const int rel = bid - P.blkBase[l];
    const int H = P.H[l], W = H;
    const int GX = P.GX[l], groups = P.grp[l];
    const int gx = rel % GX;
    const int t2 = rel / GX;
    const int h = t2 % H;
    const int b = t2 / H;

    int g  = threadIdx.x % groups;
    int dy = threadIdx.x / groups;
    if (dy >= 17) return;
    int wbase = gx * groups * 4 + g * 4;

    const float* x   = P.x[l];
    const float* ref = P.rx[l];
    float* corr      = P.out[l];

    // acc2[j][0] = (acc[j][p0], acc[j][p1]); acc2[j][1] = (acc[j][p2], acc[j][p3])
    unsigned long long acc2[17][2];
    #pragma unroll
    for (int j = 0; j < 17; j++){ acc2[j][0] = 0ull; acc2[j][1] = 0ull; }

    int r = h + dy - PADC;
    int HW = H * W;
    if (r >= 0 && r < H){
        const float* xb = x   + ((b * 256) * H + h) * W;
        const float* rb = ref + ((b * 256) * H + r) * W;
        int q0 = wbase - PADC;
        bool interior = (q0 >= 0) && (q0 + 20 <= W);
        if (interior){
            for (int c = 0; c < 256; c++){
                const float4 xv = *reinterpret_cast<const float4*>(xb + c * HW + wbase);
                unsigned long long ax01 = pk2(xv.x, xv.y);
                unsigned long long ax23 = pk2(xv.z, xv.w);
                const float* rr = rb + c * HW;
                float rv[20];
                #pragma unroll
                for (int t = 0; t < 5; t++){
                    float4 v = *reinterpret_cast<const float4*>(rr + q0 + t * 4);
                    rv[t*4+0]=v.x; rv[t*4+1]=v.y; rv[t*4+2]=v.z; rv[t*4+3]=v.w;
                }
                unsigned long long pr[19];
                #pragma unroll
                for (int t = 0; t < 19; t++) pr[t] = pk2(rv[t], rv[t+1]);
                #pragma unroll
                for (int j = 0; j < 17; j++){
                    fma2(acc2[j][0], ax01, pr[j]);
                    fma2(acc2[j][1], ax23, pr[j+2]);
                }
            }
        } else {
            for (int c = 0; c < 256; c++){
                const float4 xv = *reinterpret_cast<const float4*>(xb + c * HW + wbase);
                unsigned long long ax01 = pk2(xv.x, xv.y);
                unsigned long long ax23 = pk2(xv.z, xv.w);
                const float* rr = rb + c * HW;
                float rv[20];
                #pragma unroll
                for (int t = 0; t < 20; t++){
                    int q = q0 + t;
                    rv[t] = (q >= 0 && q < W) ? rr[q] : 0.f;
                }
                unsigned long long pr[19];
                #pragma unroll
                for (int t = 0; t < 19; t++) pr[t] = pk2(rv[t], rv[t+1]);
                #pragma unroll
                for (int j = 0; j < 17; j++){
                    fma2(acc2[j][0], ax01, pr[j]);
                    fma2(acc2[j][1], ax23, pr[j+2]);
                }
            }
        }
    }
    #pragma unroll
    for (int j = 0; j < 17; j++){
        int d = dy * 17 + j;
        float2 v01 = upk(acc2[j][0]);
        float2 v23 = upk(acc2[j][1]);
        float4 o; o.x=v01.x; o.y=v01.y; o.z=v23.x; o.w=v23.y;
        *reinterpret_cast<float4*>(corr + ((b * 289 + d) * H + h) * W + wbase) = o;
    }
}

// ================= merged map-act pack (4 levels, Cpad=832) =================
struct PackMapParams {
    const float* x[4];
    const float* rx[4];
    const float* corr[4];
    __half* Ph[4];
    __half* Pl[4];
    int H[4];
    int npb[4];
    int blkBase[5];
};
__global__ void k_pack_map_all(const __grid_constant__ PackMapParams P){
    __shared__ float t[32][33];
    const int bid = blockIdx.x;
    int l = 0;
    if (bid >= P.blkBase[1]) l = 1;
    if (bid >= P.blkBase[2]) l = 2;
    if (bid >= P.blkBase[3]) l = 3;
    const int rel = bid - P.blkBase[l];
    const int npb = P.npb[l];
    const int bxp = rel % npb;
    const int c0  = (rel / npb) * 32;
    const int H = P.H[l], W = H;
    const int Hp = H + 2, Wp = W + 2, HW = H * W, Np = 2 * Hp * Wp;
    const int p0 = bxp * 32;

    int px = p0 + threadIdx.x;
    int b = 0, pix = 0; bool inter = false;
    if (px < Np){
        b = px / (Hp * Wp); int r = px % (Hp * Wp); int hp = r / Wp, wp = r % Wp;
        if (hp >= 1 && hp <= H && wp >= 1 && wp <= W){ inter = true; pix = (hp - 1) * W + (wp - 1); }
    }
    const float* X  = P.x[l];
    const float* RX = P.rx[l];
    const float* CR = P.corr[l];
    #pragma unroll
    for (int dyy = 0; dyy < 32; dyy += 8){
        int ci = c0 + (int)threadIdx.y + dyy;
        float v = 0.f;
        if (inter){
            if (ci < 256)       v = X [(size_t)(b * 256 + ci) * HW + pix];
            else if (ci < 512)  v = RX[(size_t)(b * 256 + ci - 256) * HW + pix];
            else if (ci < 801)  v = CR[(size_t)(b * 289 + ci - 512) * HW + pix];
        }
        t[threadIdx.y + dyy][threadIdx.x] = v;
    }
    __syncthreads();
    int ft = threadIdx.y * 32 + threadIdx.x;
    int pl = ft >> 3, sub = ft & 7;
    int px2 = p0 + pl;
    if (px2 < Np){
        size_t chStride = (size_t)2 * Hp * Wp * 32;
        int gsw = (sub >> 1) ^ ((px2 >> 1) & 3);
        size_t base = (size_t)(c0 >> 5) * chStride + (size_t)px2 * 32 + (gsw << 3) + (sub & 1) * 4;
        float v0 = t[sub*4+0][pl], v1 = t[sub*4+1][pl], v2 = t[sub*4+2][pl], v3 = t[sub*4+3][pl];
        __half h0 = __float2half_rn(v0), h1 = __float2half_rn(v1);
        __half h2 = __float2half_rn(v2), h3 = __float2half_rn(v3);
        uint32_t uh0 = (uint32_t)__half_as_ushort(h0) | ((uint32_t)__half_as_ushort(h1) << 16);
        uint32_t uh1 = (uint32_t)__half_as_ushort(h2) | ((uint32_t)__half_as_ushort(h3) << 16);
        uint2 wh; wh.x = uh0; wh.y = uh1;
        *reinterpret_cast<uint2*>(P.Ph[l] + base) = wh;
        __half l0 = __float2half_rn(v0 - __half2float(h0));
        __half l1 = __float2half_rn(v1 - __half2float(h1));
        __half l2 = __float2half_rn(v2 - __half2float(h2));
        __half l3 = __float2half_rn(v3 - __half2float(h3));
        uint32_t ul0 = (uint32_t)__half_as_ushort(l0) | ((uint32_t)__half_as_ushort(l1) << 16);
        uint32_t ul1 = (uint32_t)__half_as_ushort(l2) | ((uint32_t)__half_as_ushort(l3) << 16);
        uint2 wl; wl.x = ul0; wl.y = ul1;
        *reinterpret_cast<uint2*>(P.Pl[l] + base) = wl;
    }
}

// ================= merged out-act pack with fused upsample cascade =================
struct PackOutParams {
    const float* map[4];
    __half* Ph[4];
    __half* Pl[4];
    int H[4];
    int npb[4];
    int blkBase[5];
};
__global__ void k_pack_out_all(const __grid_constant__ PackOutParams P){
    __shared__ float t[32][33];
    const int bid = blockIdx.x;
    int l = 0;
    if (bid >= P.blkBase[1]) l = 1;
    if (bid >= P.blkBase[2]) l = 2;
    if (bid >= P.blkBase[3]) l = 3;
    const int rel = bid - P.blkBase[l];
    const int npb = P.npb[l];
    const int bxp = rel % npb;
    const int c0  = (rel / npb) * 32;
    const int H = P.H[l], W = H;
    const int Hp = H + 2, Wp = W + 2, Np = 2 * Hp * Wp;
    const int p0 = bxp * 32;

    int px = p0 + threadIdx.x;
    int b = 0, hh = 0, ww = 0; bool inter = false;
    if (px < Np){
        b = px / (Hp * Wp); int r = px % (Hp * Wp); int hp = r / Wp, wp = r % Wp;
        if (hp >= 1 && hp <= H && wp >= 1 && wp <= W){ inter = true; hh = hp - 1; ww = wp - 1; }
    }
    #pragma unroll
    for (int dyy = 0; dyy < 32; dyy += 8){
        int ci = c0 + (int)threadIdx.y + dyy;
        float v = 0.f;
        if (inter){
            for (int k = l; k < 4; k++){
                int Wk = P.H[k];
                int sh = k - l;
                v += P.map[k][((size_t)(b * 256 + ci) * Wk + (hh >> sh)) * Wk + (ww >> sh)];
            }
        }
        t[threadIdx.y + dyy][threadIdx.x] = v;
    }
    __syncthreads();
    int ft = threadIdx.y * 32 + threadIdx.x;
    int pl = ft >> 3, sub = ft & 7;
    int px2 = p0 + pl;
    if (px2 < Np){
        size_t chStride = (size_t)2 * Hp * Wp * 32;
        int gsw = (sub >> 1) ^ ((px2 >> 1) & 3);
        size_t base = (size_t)(c0 >> 5) * chStride + (size_t)px2 * 32 + (gsw << 3) + (sub & 1) * 4;
        float v0 = t[sub*4+0][pl], v1 = t[sub*4+1][pl], v2 = t[sub*4+2][pl], v3 = t[sub*4+3][pl];
        __half h0 = __float2half_rn(v0), h1 = __float2half_rn(v1);
        __half h2 = __float2half_rn(v2), h3 = __float2half_rn(v3);
        uint32_t uh0 = (uint32_t)__half_as_ushort(h0) | ((uint32_t)__half_as_ushort(h1) << 16);
        uint32_t uh1 = (uint32_t)__half_as_ushort(h2) | ((uint32_t)__half_as_ushort(h3) << 16);
        uint2 wh; wh.x = uh0; wh.y = uh1;
        *reinterpret_cast<uint2*>(P.Ph[l] + base) = wh;
        __half l0 = __float2half_rn(v0 - __half2float(h0));
        __half l1 = __float2half_rn(v1 - __half2float(h1));
        __half l2 = __float2half_rn(v2 - __half2float(h2));
        __half l3 = __float2half_rn(v3 - __half2float(h3));
        uint32_t ul0 = (uint32_t)__half_as_ushort(l0) | ((uint32_t)__half_as_ushort(l1) << 16);
        uint32_t ul1 = (uint32_t)__half_as_ushort(l2) | ((uint32_t)__half_as_ushort(l3) << 16);
        uint2 wl; wl.x = ul0; wl.y = ul1;
        *reinterpret_cast<uint2*>(P.Pl[l] + base) = wl;
    }
}

// ================= merged multi-level fp16 2-pass implicit-conv GEMM =================
struct GemmParams {
    const __half* A;
    const __half* BhB;
    const __half* BlB;
    float*        out[4];
    const float*  bias[4];
    long aOff[4];
    long bOff[4];
    int  H[4];
    int  lgW[4];
    int  zc[4];
    int  tpz[4];
    int  blkBase[5];
    int  CH;
};

__global__ __launch_bounds__(256)
void k_gemm(const __grid_constant__ GemmParams P)
{
    extern __shared__ char dsm[];
    __shared__ __align__(8) unsigned long long mb[6];

    const int bid = blockIdx.x;
    int l = 0;
    if (bid >= P.blkBase[1]) l = 1;
    if (bid >= P.blkBase[2]) l = 2;
    if (bid >= P.blkBase[3]) l = 3;
    const int rel = bid - P.blkBase[l];
    const int zc = P.zc[l], tapsPerZ = P.tpz[l];
    const int zi = rel % zc;
    const int tt = rel / zc;
    const int m0 = (tt & 1) * 128;
    const int nt = tt >> 1;
    const int H = P.H[l], W = H, lgW = P.lgW[l];
    const __half* A  = P.A   + P.aOff[l];
    const __half* Bh = P.BhB + P.bOff[l];
    const __half* Bl = P.BlB + P.bOff[l];
    float* out = P.out[l];
    const float* bias = P.bias[l];
    const int useAtomic = (zc > 1);
    const int tapBeg = zi * tapsPerZ;
    const int CH = P.CH;

    const uint32_t smemBase = smem_u32(dsm);
    uint32_t A_OFF[4], B_OFF[2];
    #pragma unroll
    for (int s = 0; s < 4; s++) A_OFF[s] = smemBase + s * 8192u;
    B_OFF[0] = smemBase + 32768u;
    B_OFF[1] = smemBase + 32768u + 66560u;
    const uint32_t MBA = smem_u32(&mb[0]);
    const uint32_t MBB = smem_u32(&mb[4]);

    const int tid = threadIdx.x, wid = tid >> 5, lane = tid & 31;
    const int R = 256 >> lgW;
    const int Hp = H + 2, Wp = W + 2;
    const int tilesPerB = H / R;
    const int b  = nt / tilesPerB;
    const int h0 = (nt % tilesPerB) * R;
    const int q0 = (b * Hp + h0) * Wp;
    const uint32_t Bbytes = (uint32_t)(R + 2) * Wp * 64u;
    const size_t chStride = (size_t)2 * Hp * Wp * 32;

    if (tid == 0){
        #pragma unroll
        for (int i = 0; i < 6; i++) mbar_init(MBA + i * 8, 1);
    }
    __syncthreads();

    const int nA = CH * tapsPerZ;

    auto issueA = [&](int ia){
        int c = ia / tapsPerZ, tap = ia % tapsPerZ;
        const __half* src = A + ((((size_t)c * 9 + (tapBeg + tap)) * 256 + m0) << 5);
        int s = ia & 3;
        mbar_expect(MBA + s * 8, 8192u);
        bulk_cp(A_OFF[s], src, 8192u, MBA + s * 8);
    };
    auto issueB = [&](int c){
        int s = c & 1;
        mbar_expect(MBB + s * 8, 2u * Bbytes);
        bulk_cp(B_OFF[s],          Bh + (size_t)c * chStride + ((size_t)q0 << 5), Bbytes, MBB + s * 8);
        bulk_cp(B_OFF[s] + 33280u, Bl + (size_t)c * chStride + ((size_t)q0 << 5), Bbytes, MBB + s * 8);
    };

    const int lr  = lane & 7;
    const int lm8 = ((lane >> 3) & 1) * 8;
    const int lk  = lane >> 4;
    const int wm  = wid & 1;
    const int wn  = wid >> 1;
    const int rowA = wm * 64 + lm8 + lr;
    const int xorA = (lr >> 1) & 3;
    int rB[4], wB[4];
    #pragma unroll
    for (int g = 0; g < 4; g++){
        int n = wn * 64 + g * 16 + lm8 + lr;
        rB[g] = n >> lgW;
        wB[g] = n & (W - 1);
    }

    float acc[4][8][4];
    #pragma unroll
    for (int i = 0; i < 4; i++)
        #pragma unroll
        for (int j = 0; j < 8; j++)
            #pragma unroll
            for (int k = 0; k < 4; k++) acc[i][j][k] = 0.f;

    if (tid == 0){
        issueB(0);
        issueA(0);
        if (nA > 1) issueA(1);
        if (nA > 2) issueA(2);
    }

    for (int it = 0; it < nA; ++it){
        int c = it / tapsPerZ, tap = it % tapsPerZ;
        if (tid == 0){
            if (it + 3 < nA) issueA(it + 3);
            if (tap == 0 && c + 1 < CH) issueB(c + 1);
        }
        mbar_wait(MBA + (it & 3) * 8, (it >> 2) & 1);
        if (tap == 0) mbar_wait(MBB + (c & 1) * 8, (c >> 1) & 1);

        const uint32_t Ab = A_OFF[it & 3];
        const uint32_t Bb = B_OFF[c & 1];
        const int tIdx = tapBeg + tap;
        const int dy = tIdx / 3, dx = tIdx - dy * 3;

        uint32_t sAdr[4]; int xorB[4];
        #pragma unroll
        for (int g = 0; g < 4; g++){
            int s = (rB[g] + dy) * Wp + wB[g] + dx;
            sAdr[g] = Bb + (uint32_t)s * 64u;
            xorB[g] = ((q0 + s) >> 1) & 3;
        }

        #pragma unroll
        for (int ks = 0; ks < 2; ks++){
            const int gA = (2 * ks + lk) ^ xorA;
            uint32_t a[4][4];
            #pragma unroll
            for (int ma = 0; ma < 4; ma++)
                ldmx4(a[ma], Ab + (uint32_t)(rowA + ma * 16) * 64u + ((uint32_t)gA << 4));
            #pragma unroll
            for (int pass = 0; pass < 2; pass++){
                uint32_t bb[4][4];
                #pragma unroll
                for (int g = 0; g < 4; g++){
                    int gB = (2 * ks + lk) ^ xorB[g];
                    ldmx4(bb[g], sAdr[g] + (uint32_t)pass * 33280u + ((uint32_t)gB << 4));
                }
                #pragma unroll
                for (int ma = 0; ma < 4; ma++)
                    #pragma unroll
                    for (int na = 0; na < 8; na++)
                        mma16816(acc[ma][na], a[ma], bb[na >> 1][na & 1], bb[na >> 1][2 + (na & 1)]);
            }
        }
        __syncthreads();
    }

    #pragma unroll
    for (int ma = 0; ma < 4; ma++){
        int co0 = m0 + wm * 64 + ma * 16 + (lane >> 2);
        int co1 = co0 + 8;
        float bv0 = useAtomic ? 0.f : bias[co0];
        float bv1 = useAtomic ? 0.f : bias[co1];
        #pragma unroll
        for (int na = 0; na < 8; na++){
            int n = wn * 64 + na * 8 + (lane & 3) * 2;
            int r = h0 + (n >> lgW);
            int w = n & (W - 1);
            size_t i0 = ((size_t)(b * 256 + co0) * H + r) * W + w;
            size_t i1 = ((size_t)(b * 256 + co1) * H + r) * W + w;
            if (useAtomic){
                atomicAdd(&out[i0],     acc[ma][na][0]);
                atomicAdd(&out[i0 + 1], acc[ma][na][1]);
                atomicAdd(&out[i1],     acc[ma][na][2]);
                atomicAdd(&out[i1 + 1], acc[ma][na][3]);
            } else {
                float2 v0; v0.x = acc[ma][na][0] + bv0; v0.y = acc[ma][na][1] + bv0;
                float2 v1; v1.x = acc[ma][na][2] + bv1; v1.y = acc[ma][na][3] + bv1;
                *reinterpret_cast<float2*>(&out[i0]) = v0;
                *reinterpret_cast<float2*>(&out[i1]) = v1;
            }
        }
    }
}

// ---------------- host orchestration (8 launches total) ----------------
extern "C" void kernel_launch(void* const* d_in, const int* in_sizes, int n_in,
                              void* d_out, int out_size)
{
    const float *x[4]={0,0,0,0}, *rx[4]={0,0,0,0};
    const float *wm[4]={0,0,0,0}, *bm[4]={0,0,0,0}, *wo[4]={0,0,0,0}, *bo[4]={0,0,0,0};
    int wmi = 0, woi = 0, bi = 0;
    for (int i = 0; i < n_in; i++){
        int s = in_sizes[i];
        int lvl = -1;
        if      (s == 2*256*128*128) lvl = 0;
        else if (s == 2*256*64*64)   lvl = 1;
        else if (s == 2*256*32*32)   lvl = 2;
        else if (s == 2*256*16*16)   lvl = 3;
        if (lvl >= 0){
            if (!x[lvl]) x[lvl] = (const float*)d_in[i];
            else         rx[lvl] = (const float*)d_in[i];
        }
        else if (s == 1845504) wm[wmi++] = (const float*)d_in[i];
        else if (s ==  589824) wo[woi++] = (const float*)d_in[i];
        else if (s ==     256){
            if ((bi & 1) == 0) bm[bi >> 1] = (const float*)d_in[i];
            else               bo[bi >> 1] = (const float*)d_in[i];
            bi++;
        }
    }

    float *corrB, *mapB;
    __half *wmh, *woh, *amh, *aml, *aoh, *aol;
    cudaGetSymbolAddress((void**)&corrB, g_corr);
    cudaGetSymbolAddress((void**)&mapB,  g_map);
    cudaGetSymbolAddress((void**)&wmh, g_wm_h);
    cudaGetSymbolAddress((void**)&woh, g_wo_h);
    cudaGetSymbolAddress((void**)&amh, g_am_h); cudaGetSymbolAddress((void**)&aml, g_am_l);
    cudaGetSymbolAddress((void**)&aoh, g_ao_h); cudaGetSymbolAddress((void**)&aol, g_ao_l);

    cudaFuncSetAttribute(k_gemm, cudaFuncAttributeMaxDynamicSharedMemorySize, 165888);

    const int  Hl[4]      = {128, 64, 32, 16};
    const int  lgWl[4]    = {7, 6, 5, 4};
    const int  HWl[4]     = {16384, 4096, 1024, 256};
    const long corrOff[4] = {0, 9469952, 11837440, 12429312};
    const long mapOff[4]  = {0, 8388608, 10485760, 11010048};
    const long amOff[4]   = {0, 28121600, 35369984, 37293568};
    const long aoOff[4]   = {0, 8652800, 10883072, 11474944};
    const long wmOff[4]   = {0, 1916928, 3833856, 5750784};
    const long woOff[4]   = {0, 589824, 1179648, 1769472};
    const int  zl[4]      = {1, 3, 9, 9};
    const int  tpzl[4]    = {9, 3, 1, 1};
    float* outp = (float*)d_out;

    int gemmBase[5]; gemmBase[0] = 0;
    for (int l = 0; l < 4; l++)
        gemmBase[l + 1] = gemmBase[l] + (2 * HWl[l] / 256) * 2 * zl[l];  // {0,256,448,592,628}

    // ---- launch 0: init map buffers (levels 1-3, atomic) ----
    {
        InitParams P;
        long tot = 0;
        for (int r = 0; r < 3; r++){
            int l = r + 1;
            P.out[r] = mapB + mapOff[l]; P.bias[r] = bm[l]; P.HW[r] = HWl[l];
            P.base[r] = tot; tot += 2L * 256 * HWl[l];
        }
        P.base[3] = tot;
        k_init_all<<<(int)((tot + 255) / 256), 256>>>(P);
    }
    // ---- launch 1: init out buffers (levels 1-3, atomic) ----
    {
        InitParams P;
        long tot = 0;
        for (int r = 0; r < 3; r++){
            int l = r + 1;
            P.out[r] = outp + mapOff[l]; P.bias[r] = bo[l]; P.HW[r] = HWl[l];
            P.base[r] = tot; tot += 2L * 256 * HWl[l];
        }
        P.base[3] = tot;
        k_init_all<<<(int)((tot + 255) / 256), 256>>>(P);
    }
    // ---- launch 2: pack all weights ----
    {
        PackWParams P;
        long tot = 0;
        for (int l = 0; l < 4; l++){
            P.src[l] = wm[l]; P.dst[l] = wmh + wmOff[l]; P.Cin[l] = 801; P.Cpad[l] = 832;
            P.base[l] = tot; tot += 256L * 832;
        }
        for (int l = 0; l < 4; l++){
            P.src[4+l] = wo[l]; P.dst[4+l] = woh + woOff[l]; P.Cin[4+l] = 256; P.Cpad[4+l] = 256;
            P.base[4+l] = tot; tot += 256L * 256;
        }
        P.base[8] = tot;
        k_pack_w_all<<<(int)((tot + 255) / 256), 256>>>(P);
    }
    // ---- launch 3: all correlation volumes ----
    {
        CorrParams P;
        int base = 0;
        for (int l = 0; l < 4; l++){
            P.x[l] = x[l]; P.rx[l] = rx[l]; P.out[l] = corrB + corrOff[l];
            P.H[l] = Hl[l];
            P.grp[l] = (Hl[l] >= 32) ? 8 : 4;
            P.GX[l] = Hl[l] / (P.grp[l] * 4);
            P.blkBase[l] = base;
            base += P.GX[l] * Hl[l] * 2;
        }
        P.blkBase[4] = base;
        k_corr_all<<<base, 136>>>(P);
    }
    // ---- launch 4: pack map activations ----
    int npbl[4];
    for (int l = 0; l < 4; l++){
        int Np = 2 * (Hl[l] + 2) * (Hl[l] + 2);
        npbl[l] = (Np + 31) / 32;
    }
    {
        PackMapParams P;
        int base = 0;
        for (int l = 0; l < 4; l++){
            P.x[l] = x[l]; P.rx[l] = rx[l]; P.corr[l] = corrB + corrOff[l];
            P.Ph[l] = amh + amOff[l]; P.Pl[l] = aml + amOff[l];
            P.H[l] = Hl[l]; P.npb[l] = npbl[l];
            P.blkBase[l] = base;
            base += npbl[l] * 26;
        }
        P.blkBase[4] = base;
        k_pack_map_all<<<base, dim3(32, 8)>>>(P);
    }
    // ---- launch 5: merged map GEMM ----
    {
        GemmParams P;
        P.A = wmh; P.BhB = amh; P.BlB = aml;
        for (int l = 0; l < 4; l++){
            P.out[l] = mapB + mapOff[l]; P.bias[l] = bm[l];
            P.aOff[l] = wmOff[l]; P.bOff[l] = amOff[l];
            P.H[l] = Hl[l]; P.lgW[l] = lgWl[l]; P.zc[l] = zl[l]; P.tpz[l] = tpzl[l];
        }
        for (int i = 0; i < 5; i++) P.blkBase[i] = gemmBase[i];
        P.CH = 26;
        k_gemm<<<gemmBase[4], 256, 165888>>>(P);
    }
    // ---- launch 6: pack out activations with fused upsample cascade ----
    {
        PackOutParams P;
        int base = 0;
        for (int l = 0; l < 4; l++){
            P.map[l] = mapB + mapOff[l];
            P.Ph[l] = aoh + aoOff[l]; P.Pl[l] = aol + aoOff[l];
            P.H[l] = Hl[l]; P.npb[l] = npbl[l];
            P.blkBase[l] = base;
            base += npbl[l] * 8;
        }
        P.blkBase[4] = base;
        k_pack_out_all<<<base, dim3(32, 8)>>>(P);
    }
    // ---- launch 7: merged out GEMM -> d_out ----
    {
        GemmParams P;
        P.A = woh; P.BhB = aoh; P.BlB = aol;
        for (int l = 0; l < 4; l++){
            P.out[l] = outp + mapOff[l]; P.bias[l] = bo[l];
            P.aOff[l] = woOff[l]; P.bOff[l] = aoOff[l];
            P.H[l] = Hl[l]; P.lgW[l] = lgWl[l]; P.zc[l] = zl[l]; P.tpz[l] = tpzl[l];
        }
        for (int i = 0; i < 5; i++) P.blkBase[i] = gemmBase[i];
        P.CH = 8;
        k_gemm<<<gemmBase[4], 256, 165888>>>(P);
    }
}

// round 10
// speedup vs baseline: 1.1690x; 1.1690x over previous
#include <cuda_runtime.h>
#include <cuda_fp16.h>
#include <cstdint>
#include <cstddef>

#define PADC 8

// ---------------- static device buffers ----------------
__device__ __align__(256) float g_corr[12577280];
__device__ __align__(256) float g_map [11141120];
__device__ __align__(256) __half g_wm_h[7667712];   // [lvl][chunk26][tap9][co256][ci32] swizzled
__device__ __align__(256) __half g_wo_h[2359296];   // [lvl][chunk8][tap9][co256][ci32]
__device__ __align__(256) __half g_am_h[37832704];  // [lvl][chunk][b][Hp][Wp][32] swizzled
__device__ __align__(256) __half g_am_l[37832704];
__device__ __align__(256) __half g_ao_h[11640832];
__device__ __align__(256) __half g_ao_l[11640832];

// ---------------- PTX helpers (compute_103 baseline-safe) ----------------
__device__ __forceinline__ uint32_t smem_u32(const void* p){
    uint32_t a;
    asm("{ .reg .u64 t; cvta.to.shared.u64 t, %1; cvt.u32.u64 %0, t; }" : "=r"(a) : "l"(p));
    return a;
}
__device__ __forceinline__ void mbar_init(uint32_t a, uint32_t cnt){
    asm volatile("mbarrier.init.shared.b64 [%0], %1;" :: "r"(a), "r"(cnt) : "memory");
}
__device__ __forceinline__ void mbar_expect(uint32_t a, uint32_t bytes){
    asm volatile("mbarrier.arrive.expect_tx.shared.b64 _, [%0], %1;" :: "r"(a), "r"(bytes) : "memory");
}
__device__ __forceinline__ void mbar_wait(uint32_t a, int parity){
    asm volatile(
        "{\n\t.reg .pred P;\n\t"
        "WL_%=:\n\t"
        "mbarrier.try_wait.parity.acquire.cta.shared::cta.b64 P, [%0], %1, 0x989680;\n\t"
        "@P bra WD_%=;\n\t"
        "bra WL_%=;\n\t"
        "WD_%=:\n\t}"
        :: "r"(a), "r"(parity) : "memory");
}
__device__ __forceinline__ void bulk_cp(uint32_t dst, const void* src, uint32_t bytes, uint32_t mbar){
    asm volatile(
        "cp.async.bulk.shared::cluster.global.mbarrier::complete_tx::bytes [%0], [%1], %2, [%3];"
        :: "r"(dst), "l"(src), "r"(bytes), "r"(mbar) : "memory");
}
__device__ __forceinline__ void ldmx4(uint32_t* r, uint32_t addr){
    asm volatile("ldmatrix.sync.aligned.m8n8.x4.shared.b16 {%0,%1,%2,%3}, [%4];"
                 : "=r"(r[0]), "=r"(r[1]), "=r"(r[2]), "=r"(r[3]) : "r"(addr));
}
__device__ __forceinline__ void mma16816(float* c, const uint32_t* a, uint32_t b0, uint32_t b1){
    asm volatile(
        "mma.sync.aligned.m16n8k16.row.col.f32.f16.f16.f32 "
        "{%0,%1,%2,%3}, {%4,%5,%6,%7}, {%8,%9}, {%0,%1,%2,%3};"
        : "+f"(c[0]), "+f"(c[1]), "+f"(c[2]), "+f"(c[3])
        : "r"(a[0]), "r"(a[1]), "r"(a[2]), "r"(a[3]), "r"(b0), "r"(b1));
}

// ================= merged init bias (3 regions) =================
struct InitParams {
    float* out[3];
    const float* bias[3];
    int HW[3];
    long base[4];
};
__global__ void k_init_all(const __grid_constant__ InitParams P){
    long i = (long)blockIdx.x * blockDim.x + threadIdx.x;
    if (i >= P.base[3]) return;
    int r = 0;
    if (i >= P.base[1]) r = 1;
    if (i >= P.base[2]) r = 2;
    long loc = i - P.base[r];
    P.out[r][loc] = P.bias[r][(loc / P.HW[r]) & 255];
}

// ================= merged weight pack (8 tensors) =================
struct PackWParams {
    const float* src[8];
    __half* dst[8];
    int Cin[8];
    int Cpad[8];
    long base[9];
};
__global__ void k_pack_w_all(const __grid_constant__ PackWParams P){
    long i = (long)blockIdx.x * 256 + threadIdx.x;
    if (i >= P.base[8]) return;
    int t = 0;
    #pragma unroll
    for (int k = 1; k < 8; k++) if (i >= P.base[k]) t = k;
    long loc = i - P.base[t];
    int Cpad = P.Cpad[t], Cin = P.Cin[t];
    int co = (int)(loc / Cpad), ci = (int)(loc % Cpad);
    int c = ci >> 5, cl = ci & 31;
    int gsw = (cl >> 3) ^ ((co >> 1) & 3);
    const float* w = P.src[t];
    __half* oh = P.dst[t];
    #pragma unroll
    for (int tap = 0; tap < 9; tap++){
        float v = (ci < Cin) ? w[(size_t)(co * Cin + ci) * 9 + tap] : 0.f;
        size_t o = (((size_t)c * 9 + tap) * 256 + co) * 32 + (gsw << 3) + (cl & 7);
        oh[o] = __float2half_rn(v);
    }
}

// ================= merged correlation (4 levels), dj-split for occupancy =================
// Thread = (pixel group g of 4, dy, half). half0: dj 0-8 (acc 36 regs), half1: dj 9-16.
struct CorrParams {
    const float* x[4];
    const float* rx[4];
    float* out[4];
    int H[4];
    int GX[4];
    int blkBase[5];
};
__global__ void k_corr_all(const __grid_constant__ CorrParams P){
    const int bid = blockIdx.x;
    int l = 0;
    if (bid >= P.blkBase[1]) l = 1;
    if (bid >= P.blkBase[2]) l = 2;
    if (bid >= P.blkBase[3]) l = 3;
    const int rel = bid - P.blkBase[l];
    const int H = P.H[l], W = H;
    const int GX = P.GX[l];              // W / 16
    const int gx = rel % GX;
    const int t2 = rel / GX;
    const int h = t2 % H;
    const int b = t2 / H;

    const int g = threadIdx.x & 3;
    const int q = threadIdx.x >> 2;
    if (q >= 34) return;
    const int half = (q >= 17);
    const int dy = half ? (q - 17) : q;
    const int wbase = gx * 16 + g * 4;

    const float* x   = P.x[l];
    const float* ref = P.rx[l];
    float* corr      = P.out[l];

    float acc[9][4];
    #pragma unroll
    for (int j = 0; j < 9; j++){ acc[j][0]=0.f; acc[j][1]=0.f; acc[j][2]=0.f; acc[j][3]=0.f; }

    const int r = h + dy - PADC;
    const int HW = H * W;
    const int start = wbase - PADC + (half ? 8 : 0);   // 12-float window [start, start+12)

    if (r >= 0 && r < H){
        const float* xb = x   + ((b * 256) * H + h) * W + wbase;
        const float* rb = ref + ((b * 256) * H + r) * W;
        const bool inter = (start >= 0) && (start + 12 <= W);
        if (!half){
            for (int c = 0; c < 256; c++){
                const float4 xv = *reinterpret_cast<const float4*>(xb + c * HW);
                const float* rr = rb + c * HW;
                float rv[12];
                if (inter){
                    #pragma unroll
                    for (int t = 0; t < 3; t++){
                        float4 v = *reinterpret_cast<const float4*>(rr + start + t * 4);
                        rv[t*4+0]=v.x; rv[t*4+1]=v.y; rv[t*4+2]=v.z; rv[t*4+3]=v.w;
                    }
                } else {
                    #pragma unroll
                    for (int t = 0; t < 12; t++){
                        int qq = start + t;
                        rv[t] = (qq >= 0 && qq < W) ? rr[qq] : 0.f;
                    }
                }
                #pragma unroll
                for (int j = 0; j < 9; j++){
                    acc[j][0] += xv.x * rv[j];
                    acc[j][1] += xv.y * rv[j+1];
                    acc[j][2] += xv.z * rv[j+2];
                    acc[j][3] += xv.w * rv[j+3];
                }
            }
        } else {
            for (int c = 0; c < 256; c++){
                const float4 xv = *reinterpret_cast<const float4*>(xb + c * HW);
                const float* rr = rb + c * HW;
                float rv[12];
                if (inter){
                    #pragma unroll
                    for (int t = 0; t < 3; t++){
                        float4 v = *reinterpret_cast<const float4*>(rr + start + t * 4);
                        rv[t*4+0]=v.x; rv[t*4+1]=v.y; rv[t*4+2]=v.z; rv[t*4+3]=v.w;
                    }
                } else {
                    #pragma unroll
                    for (int t = 0; t < 12; t++){
                        int qq = start + t;
                        rv[t] = (qq >= 0 && qq < W) ? rr[qq] : 0.f;
                    }
                }
                // dj = 9 + j: ref idx (dj + p) - 8 = start + 1 + j + p  (start = wbase)
                #pragma unroll
                for (int j = 0; j < 8; j++){
                    acc[j][0] += xv.x * rv[1+j];
                    acc[j][1] += xv.y * rv[2+j];
                    acc[j][2] += xv.z * rv[3+j];
                    acc[j][3] += xv.w * rv[4+j];
                }
            }
        }
    }

    if (!half){
        #pragma unroll
        for (int j = 0; j < 9; j++){
            int d = dy * 17 + j;
            float4 o; o.x=acc[j][0]; o.y=acc[j][1]; o.z=acc[j][2]; o.w=acc[j][3];
            *reinterpret_cast<float4*>(corr + ((b * 289 + d) * H + h) * W + wbase) = o;
        }
    } else {
        #pragma unroll
        for (int j = 0; j < 8; j++){
            int d = dy * 17 + 9 + j;
            float4 o; o.x=acc[j][0]; o.y=acc[j][1]; o.z=acc[j][2]; o.w=acc[j][3];
            *reinterpret_cast<float4*>(corr + ((b * 289 + d) * H + h) * W + wbase) = o;
        }
    }
}

// ================= merged map-act pack (4 levels, Cpad=832) =================
struct PackMapParams {
    const float* x[4];
    const float* rx[4];
    const float* corr[4];
    __half* Ph[4];
    __half* Pl[4];
    int H[4];
    int npb[4];
    int blkBase[5];
};
__global__ void k_pack_map_all(const __grid_constant__ PackMapParams P){
    __shared__ float t[32][33];
    const int bid = blockIdx.x;
    int l = 0;
    if (bid >= P.blkBase[1]) l = 1;
    if (bid >= P.blkBase[2]) l = 2;
    if (bid >= P.blkBase[3]) l = 3;
    const int rel = bid - P.blkBase[l];
    const int npb = P.npb[l];
    const int bxp = rel % npb;
    const int c0  = (rel / npb) * 32;
    const int H = P.H[l], W = H;
    const int Hp = H + 2, Wp = W + 2, HW = H * W, Np = 2 * Hp * Wp;
    const int p0 = bxp * 32;

    int px = p0 + threadIdx.x;
    int b = 0, pix = 0; bool inter = false;
    if (px < Np){
        b = px / (Hp * Wp); int r = px % (Hp * Wp); int hp = r / Wp, wp = r % Wp;
        if (hp >= 1 && hp <= H && wp >= 1 && wp <= W){ inter = true; pix = (hp - 1) * W + (wp - 1); }
    }
    const float* X  = P.x[l];
    const float* RX = P.rx[l];
    const float* CR = P.corr[l];
    #pragma unroll
    for (int dyy = 0; dyy < 32; dyy += 8){
        int ci = c0 + (int)threadIdx.y + dyy;
        float v = 0.f;
        if (inter){
            if (ci < 256)       v = X [(size_t)(b * 256 + ci) * HW + pix];
            else if (ci < 512)  v = RX[(size_t)(b * 256 + ci - 256) * HW + pix];
            else if (ci < 801)  v = CR[(size_t)(b * 289 + ci - 512) * HW + pix];
        }
        t[threadIdx.y + dyy][threadIdx.x] = v;
    }
    __syncthreads();
    int ft = threadIdx.y * 32 + threadIdx.x;
    int pl = ft >> 3, sub = ft & 7;
    int px2 = p0 + pl;
    if (px2 < Np){
        size_t chStride = (size_t)2 * Hp * Wp * 32;
        int gsw = (sub >> 1) ^ ((px2 >> 1) & 3);
        size_t base = (size_t)(c0 >> 5) * chStride + (size_t)px2 * 32 + (gsw << 3) + (sub & 1) * 4;
        float v0 = t[sub*4+0][pl], v1 = t[sub*4+1][pl], v2 = t[sub*4+2][pl], v3 = t[sub*4+3][pl];
        __half h0 = __float2half_rn(v0), h1 = __float2half_rn(v1);
        __half h2 = __float2half_rn(v2), h3 = __float2half_rn(v3);
        uint32_t uh0 = (uint32_t)__half_as_ushort(h0) | ((uint32_t)__half_as_ushort(h1) << 16);
        uint32_t uh1 = (uint32_t)__half_as_ushort(h2) | ((uint32_t)__half_as_ushort(h3) << 16);
        uint2 wh; wh.x = uh0; wh.y = uh1;
        *reinterpret_cast<uint2*>(P.Ph[l] + base) = wh;
        __half l0 = __float2half_rn(v0 - __half2float(h0));
        __half l1 = __float2half_rn(v1 - __half2float(h1));
        __half l2 = __float2half_rn(v2 - __half2float(h2));
        __half l3 = __float2half_rn(v3 - __half2float(h3));
        uint32_t ul0 = (uint32_t)__half_as_ushort(l0) | ((uint32_t)__half_as_ushort(l1) << 16);
        uint32_t ul1 = (uint32_t)__half_as_ushort(l2) | ((uint32_t)__half_as_ushort(l3) << 16);
        uint2 wl; wl.x = ul0; wl.y = ul1;
        *reinterpret_cast<uint2*>(P.Pl[l] + base) = wl;
    }
}

// ================= merged out-act pack with fused upsample cascade =================
struct PackOutParams {
    const float* map[4];
    __half* Ph[4];
    __half* Pl[4];
    int H[4];
    int npb[4];
    int blkBase[5];
};
__global__ void k_pack_out_all(const __grid_constant__ PackOutParams P){
    __shared__ float t[32][33];
    const int bid = blockIdx.x;
    int l = 0;
    if (bid >= P.blkBase[1]) l = 1;
    if (bid >= P.blkBase[2]) l = 2;
    if (bid >= P.blkBase[3]) l = 3;
    const int rel = bid - P.blkBase[l];
    const int npb = P.npb[l];
    const int bxp = rel % npb;
    const int c0  = (rel / npb) * 32;
    const int H = P.H[l], W = H;
    const int Hp = H + 2, Wp = W + 2, Np = 2 * Hp * Wp;
    const int p0 = bxp * 32;

    int px = p0 + threadIdx.x;
    int b = 0, hh = 0, ww = 0; bool inter = false;
    if (px < Np){
        b = px / (Hp * Wp); int r = px % (Hp * Wp); int hp = r / Wp, wp = r % Wp;
        if (hp >= 1 && hp <= H && wp >= 1 && wp <= W){ inter = true; hh = hp - 1; ww = wp - 1; }
    }
    #pragma unroll
    for (int dyy = 0; dyy < 32; dyy += 8){
        int ci = c0 + (int)threadIdx.y + dyy;
        float v = 0.f;
        if (inter){
            for (int k = l; k < 4; k++){
                int Wk = P.H[k];
                int sh = k - l;
                v += P.map[k][((size_t)(b * 256 + ci) * Wk + (hh >> sh)) * Wk + (ww >> sh)];
            }
        }
        t[threadIdx.y + dyy][threadIdx.x] = v;
    }
    __syncthreads();
    int ft = threadIdx.y * 32 + threadIdx.x;
    int pl = ft >> 3, sub = ft & 7;
    int px2 = p0 + pl;
    if (px2 < Np){
        size_t chStride = (size_t)2 * Hp * Wp * 32;
        int gsw = (sub >> 1) ^ ((px2 >> 1) & 3);
        size_t base = (size_t)(c0 >> 5) * chStride + (size_t)px2 * 32 + (gsw << 3) + (sub & 1) * 4;
        float v0 = t[sub*4+0][pl], v1 = t[sub*4+1][pl], v2 = t[sub*4+2][pl], v3 = t[sub*4+3][pl];
        __half h0 = __float2half_rn(v0), h1 = __float2half_rn(v1);
        __half h2 = __float2half_rn(v2), h3 = __float2half_rn(v3);
        uint32_t uh0 = (uint32_t)__half_as_ushort(h0) | ((uint32_t)__half_as_ushort(h1) << 16);
        uint32_t uh1 = (uint32_t)__half_as_ushort(h2) | ((uint32_t)__half_as_ushort(h3) << 16);
        uint2 wh; wh.x = uh0; wh.y = uh1;
        *reinterpret_cast<uint2*>(P.Ph[l] + base) = wh;
        __half l0 = __float2half_rn(v0 - __half2float(h0));
        __half l1 = __float2half_rn(v1 - __half2float(h1));
        __half l2 = __float2half_rn(v2 - __half2float(h2));
        __half l3 = __float2half_rn(v3 - __half2float(h3));
        uint32_t ul0 = (uint32_t)__half_as_ushort(l0) | ((uint32_t)__half_as_ushort(l1) << 16);
        uint32_t ul1 = (uint32_t)__half_as_ushort(l2) | ((uint32_t)__half_as_ushort(l3) << 16);
        uint2 wl; wl.x = ul0; wl.y = ul1;
        *reinterpret_cast<uint2*>(P.Pl[l] + base) = wl;
    }
}

// ================= merged multi-level fp16 2-pass implicit-conv GEMM =================
struct GemmParams {
    const __half* A;
    const __half* BhB;
    const __half* BlB;
    float*        out[4];
    const float*  bias[4];
    long aOff[4];
    long bOff[4];
    int  H[4];
    int  lgW[4];
    int  zc[4];
    int  tpz[4];
    int  blkBase[5];
    int  CH;
};

__global__ __launch_bounds__(256)
void k_gemm(const __grid_constant__ GemmParams P)
{
    extern __shared__ char dsm[];
    __shared__ __align__(8) unsigned long long mb[6];

    const int bid = blockIdx.x;
    int l = 0;
    if (bid >= P.blkBase[1]) l = 1;
    if (bid >= P.blkBase[2]) l = 2;
    if (bid >= P.blkBase[3]) l = 3;
    const int rel = bid - P.blkBase[l];
    const int zc = P.zc[l], tapsPerZ = P.tpz[l];
    const int zi = rel % zc;
    const int tt = rel / zc;
    const int m0 = (tt & 1) * 128;
    const int nt = tt >> 1;
    const int H = P.H[l], W = H, lgW = P.lgW[l];
    const __half* A  = P.A   + P.aOff[l];
    const __half* Bh = P.BhB + P.bOff[l];
    const __half* Bl = P.BlB + P.bOff[l];
    float* out = P.out[l];
    const float* bias = P.bias[l];
    const int useAtomic = (zc > 1);
    const int tapBeg = zi * tapsPerZ;
    const int CH = P.CH;

    const uint32_t smemBase = smem_u32(dsm);
    uint32_t A_OFF[4], B_OFF[2];
    #pragma unroll
    for (int s = 0; s < 4; s++) A_OFF[s] = smemBase + s * 8192u;
    B_OFF[0] = smemBase + 32768u;
    B_OFF[1] = smemBase + 32768u + 66560u;
    const uint32_t MBA = smem_u32(&mb[0]);
    const uint32_t MBB = smem_u32(&mb[4]);

    const int tid = threadIdx.x, wid = tid >> 5, lane = tid & 31;
    const int R = 256 >> lgW;
    const int Hp = H + 2, Wp = W + 2;
    const int tilesPerB = H / R;
    const int b  = nt / tilesPerB;
    const int h0 = (nt % tilesPerB) * R;
    const int q0 = (b * Hp + h0) * Wp;
    const uint32_t Bbytes = (uint32_t)(R + 2) * Wp * 64u;
    const size_t chStride = (size_t)2 * Hp * Wp * 32;

    if (tid == 0){
        #pragma unroll
        for (int i = 0; i < 6; i++) mbar_init(MBA + i * 8, 1);
    }
    __syncthreads();

    const int nA = CH * tapsPerZ;

    auto issueA = [&](int ia){
        int c = ia / tapsPerZ, tap = ia % tapsPerZ;
        const __half* src = A + ((((size_t)c * 9 + (tapBeg + tap)) * 256 + m0) << 5);
        int s = ia & 3;
        mbar_expect(MBA + s * 8, 8192u);
        bulk_cp(A_OFF[s], src, 8192u, MBA + s * 8);
    };
    auto issueB = [&](int c){
        int s = c & 1;
        mbar_expect(MBB + s * 8, 2u * Bbytes);
        bulk_cp(B_OFF[s],          Bh + (size_t)c * chStride + ((size_t)q0 << 5), Bbytes, MBB + s * 8);
        bulk_cp(B_OFF[s] + 33280u, Bl + (size_t)c * chStride + ((size_t)q0 << 5), Bbytes, MBB + s * 8);
    };

    const int lr  = lane & 7;
    const int lm8 = ((lane >> 3) & 1) * 8;
    const int lk  = lane >> 4;
    const int wm  = wid & 1;
    const int wn  = wid >> 1;
    const int rowA = wm * 64 + lm8 + lr;
    const int xorA = (lr >> 1) & 3;
    int rB[4], wB[4];
    #pragma unroll
    for (int g = 0; g < 4; g++){
        int n = wn * 64 + g * 16 + lm8 + lr;
        rB[g] = n >> lgW;
        wB[g] = n & (W - 1);
    }

    float acc[4][8][4];
    #pragma unroll
    for (int i = 0; i < 4; i++)
        #pragma unroll
        for (int j = 0; j < 8; j++)
            #pragma unroll
            for (int k = 0; k < 4; k++) acc[i][j][k] = 0.f;

    if (tid == 0){
        issueB(0);
        issueA(0);
        if (nA > 1) issueA(1);
        if (nA > 2) issueA(2);
    }

    for (int it = 0; it < nA; ++it){
        int c = it / tapsPerZ, tap = it % tapsPerZ;
        if (tid == 0){
            if (it + 3 < nA) issueA(it + 3);
            if (tap == 0 && c + 1 < CH) issueB(c + 1);
        }
        mbar_wait(MBA + (it & 3) * 8, (it >> 2) & 1);
        if (tap == 0) mbar_wait(MBB + (c & 1) * 8, (c >> 1) & 1);

        const uint32_t Ab = A_OFF[it & 3];
        const uint32_t Bb = B_OFF[c & 1];
        const int tIdx = tapBeg + tap;
        const int dy = tIdx / 3, dx = tIdx - dy * 3;

        uint32_t sAdr[4]; int xorB[4];
        #pragma unroll
        for (int g = 0; g < 4; g++){
            int s = (rB[g] + dy) * Wp + wB[g] + dx;
            sAdr[g] = Bb + (uint32_t)s * 64u;
            xorB[g] = ((q0 + s) >> 1) & 3;
        }

        #pragma unroll
        for (int ks = 0; ks < 2; ks++){
            const int gA = (2 * ks + lk) ^ xorA;
            uint32_t a[4][4];
            #pragma unroll
            for (int ma = 0; ma < 4; ma++)
                ldmx4(a[ma], Ab + (uint32_t)(rowA + ma * 16) * 64u + ((uint32_t)gA << 4));
            #pragma unroll
            for (int pass = 0; pass < 2; pass++){
                uint32_t bb[4][4];
                #pragma unroll
                for (int g = 0; g < 4; g++){
                    int gB = (2 * ks + lk) ^ xorB[g];
                    ldmx4(bb[g], sAdr[g] + (uint32_t)pass * 33280u + ((uint32_t)gB << 4));
                }
                #pragma unroll
                for (int ma = 0; ma < 4; ma++)
                    #pragma unroll
                    for (int na = 0; na < 8; na++)
                        mma16816(acc[ma][na], a[ma], bb[na >> 1][na & 1], bb[na >> 1][2 + (na & 1)]);
            }
        }
        __syncthreads();
    }

    #pragma unroll
    for (int ma = 0; ma < 4; ma++){
        int co0 = m0 + wm * 64 + ma * 16 + (lane >> 2);
        int co1 = co0 + 8;
        float bv0 = useAtomic ? 0.f : bias[co0];
        float bv1 = useAtomic ? 0.f : bias[co1];
        #pragma unroll
        for (int na = 0; na < 8; na++){
            int n = wn * 64 + na * 8 + (lane & 3) * 2;
            int r = h0 + (n >> lgW);
            int w = n & (W - 1);
            size_t i0 = ((size_t)(b * 256 + co0) * H + r) * W + w;
            size_t i1 = ((size_t)(b * 256 + co1) * H + r) * W + w;
            if (useAtomic){
                atomicAdd(&out[i0],     acc[ma][na][0]);
                atomicAdd(&out[i0 + 1], acc[ma][na][1]);
                atomicAdd(&out[i1],     acc[ma][na][2]);
                atomicAdd(&out[i1 + 1], acc[ma][na][3]);
            } else {
                float2 v0; v0.x = acc[ma][na][0] + bv0; v0.y = acc[ma][na][1] + bv0;
                float2 v1; v1.x = acc[ma][na][2] + bv1; v1.y = acc[ma][na][3] + bv1;
                *reinterpret_cast<float2*>(&out[i0]) = v0;
                *reinterpret_cast<float2*>(&out[i1]) = v1;
            }
        }
    }
}

// ---------------- host orchestration (8 launches total) ----------------
extern "C" void kernel_launch(void* const* d_in, const int* in_sizes, int n_in,
                              void* d_out, int out_size)
{
    const float *x[4]={0,0,0,0}, *rx[4]={0,0,0,0};
    const float *wm[4]={0,0,0,0}, *bm[4]={0,0,0,0}, *wo[4]={0,0,0,0}, *bo[4]={0,0,0,0};
    int wmi = 0, woi = 0, bi = 0;
    for (int i = 0; i < n_in; i++){
        int s = in_sizes[i];
        int lvl = -1;
        if      (s == 2*256*128*128) lvl = 0;
        else if (s == 2*256*64*64)   lvl = 1;
        else if (s == 2*256*32*32)   lvl = 2;
        else if (s == 2*256*16*16)   lvl = 3;
        if (lvl >= 0){
            if (!x[lvl]) x[lvl] = (const float*)d_in[i];
            else         rx[lvl] = (const float*)d_in[i];
        }
        else if (s == 1845504) wm[wmi++] = (const float*)d_in[i];
        else if (s ==  589824) wo[woi++] = (const float*)d_in[i];
        else if (s ==     256){
            if ((bi & 1) == 0) bm[bi >> 1] = (const float*)d_in[i];
            else               bo[bi >> 1] = (const float*)d_in[i];
            bi++;
        }
    }

    float *corrB, *mapB;
    __half *wmh, *woh, *amh, *aml, *aoh, *aol;
    cudaGetSymbolAddress((void**)&corrB, g_corr);
    cudaGetSymbolAddress((void**)&mapB,  g_map);
    cudaGetSymbolAddress((void**)&wmh, g_wm_h);
    cudaGetSymbolAddress((void**)&woh, g_wo_h);
    cudaGetSymbolAddress((void**)&amh, g_am_h); cudaGetSymbolAddress((void**)&aml, g_am_l);
    cudaGetSymbolAddress((void**)&aoh, g_ao_h); cudaGetSymbolAddress((void**)&aol, g_ao_l);

    cudaFuncSetAttribute(k_gemm, cudaFuncAttributeMaxDynamicSharedMemorySize, 165888);

    const int  Hl[4]      = {128, 64, 32, 16};
    const int  lgWl[4]    = {7, 6, 5, 4};
    const int  HWl[4]     = {16384, 4096, 1024, 256};
    const long corrOff[4] = {0, 9469952, 11837440, 12429312};
    const long mapOff[4]  = {0, 8388608, 10485760, 11010048};
    const long amOff[4]   = {0, 28121600, 35369984, 37293568};
    const long aoOff[4]   = {0, 8652800, 10883072, 11474944};
    const long wmOff[4]   = {0, 1916928, 3833856, 5750784};
    const long woOff[4]   = {0, 589824, 1179648, 1769472};
    const int  zl[4]      = {1, 3, 9, 9};
    const int  tpzl[4]    = {9, 3, 1, 1};
    float* outp = (float*)d_out;

    int gemmBase[5]; gemmBase[0] = 0;
    for (int l = 0; l < 4; l++)
        gemmBase[l + 1] = gemmBase[l] + (2 * HWl[l] / 256) * 2 * zl[l];  // {0,256,448,592,628}

    // ---- launch 0: init map buffers (levels 1-3, atomic) ----
    {
        InitParams P;
        long tot = 0;
        for (int r = 0; r < 3; r++){
            int l = r + 1;
            P.out[r] = mapB + mapOff[l]; P.bias[r] = bm[l]; P.HW[r] = HWl[l];
            P.base[r] = tot; tot += 2L * 256 * HWl[l];
        }
        P.base[3] = tot;
        k_init_all<<<(int)((tot + 255) / 256), 256>>>(P);
    }
    // ---- launch 1: init out buffers (levels 1-3, atomic) ----
    {
        InitParams P;
        long tot = 0;
        for (int r = 0; r < 3; r++){
            int l = r + 1;
            P.out[r] = outp + mapOff[l]; P.bias[r] = bo[l]; P.HW[r] = HWl[l];
            P.base[r] = tot; tot += 2L * 256 * HWl[l];
        }
        P.base[3] = tot;
        k_init_all<<<(int)((tot + 255) / 256), 256>>>(P);
    }
    // ---- launch 2: pack all weights ----
    {
        PackWParams P;
        long tot = 0;
        for (int l = 0; l < 4; l++){
            P.src[l] = wm[l]; P.dst[l] = wmh + wmOff[l]; P.Cin[l] = 801; P.Cpad[l] = 832;
            P.base[l] = tot; tot += 256L * 832;
        }
        for (int l = 0; l < 4; l++){
            P.src[4+l] = wo[l]; P.dst[4+l] = woh + woOff[l]; P.Cin[4+l] = 256; P.Cpad[4+l] = 256;
            P.base[4+l] = tot; tot += 256L * 256;
        }
        P.base[8] = tot;
        k_pack_w_all<<<(int)((tot + 255) / 256), 256>>>(P);
    }
    // ---- launch 3: all correlation volumes (dj-split, 136 thr/block) ----
    {
        CorrParams P;
        int base = 0;
        for (int l = 0; l < 4; l++){
            P.x[l] = x[l]; P.rx[l] = rx[l]; P.out[l] = corrB + corrOff[l];
            P.H[l] = Hl[l];
            P.GX[l] = Hl[l] / 16;
            P.blkBase[l] = base;
            base += P.GX[l] * Hl[l] * 2;
        }
        P.blkBase[4] = base;
        k_corr_all<<<base, 136>>>(P);
    }
    // ---- launch 4: pack map activations ----
    int npbl[4];
    for (int l = 0; l < 4; l++){
        int Np = 2 * (Hl[l] + 2) * (Hl[l] + 2);
        npbl[l] = (Np + 31) / 32;
    }
    {
        PackMapParams P;
        int base = 0;
        for (int l = 0; l < 4; l++){
            P.x[l] = x[l]; P.rx[l] = rx[l]; P.corr[l] = corrB + corrOff[l];
            P.Ph[l] = amh + amOff[l]; P.Pl[l] = aml + amOff[l];
            P.H[l] = Hl[l]; P.npb[l] = npbl[l];
            P.blkBase[l] = base;
            base += npbl[l] * 26;
        }
        P.blkBase[4] = base;
        k_pack_map_all<<<base, dim3(32, 8)>>>(P);
    }
    // ---- launch 5: merged map GEMM ----
    {
        GemmParams P;
        P.A = wmh; P.BhB = amh; P.BlB = aml;
        for (int l = 0; l < 4; l++){
            P.out[l] = mapB + mapOff[l]; P.bias[l] = bm[l];
            P.aOff[l] = wmOff[l]; P.bOff[l] = amOff[l];
            P.H[l] = Hl[l]; P.lgW[l] = lgWl[l]; P.zc[l] = zl[l]; P.tpz[l] = tpzl[l];
        }
        for (int i = 0; i < 5; i++) P.blkBase[i] = gemmBase[i];
        P.CH = 26;
        k_gemm<<<gemmBase[4], 256, 165888>>>(P);
    }
    // ---- launch 6: pack out activations with fused upsample cascade ----
    {
        PackOutParams P;
        int base = 0;
        for (int l = 0; l < 4; l++){
            P.map[l] = mapB + mapOff[l];
            P.Ph[l] = aoh + aoOff[l]; P.Pl[l] = aol + aoOff[l];
            P.H[l] = Hl[l]; P.npb[l] = npbl[l];
            P.blkBase[l] = base;
            base += npbl[l] * 8;
        }
        P.blkBase[4] = base;
        k_pack_out_all<<<base, dim3(32, 8)>>>(P);
    }
    // ---- launch 7: merged out GEMM -> d_out ----
    {
        GemmParams P;
        P.A = woh; P.BhB = aoh; P.BlB = aol;
        for (int l = 0; l < 4; l++){
            P.out[l] = outp + mapOff[l]; P.bias[l] = bo[l];
            P.aOff[l] = woOff[l]; P.bOff[l] = aoOff[l];
            P.H[l] = Hl[l]; P.lgW[l] = lgWl[l]; P.zc[l] = zl[l]; P.tpz[l] = tpzl[l];
        }
        for (int i = 0; i < 5; i++) P.blkBase[i] = gemmBase[i];
        P.CH = 8;
        k_gemm<<<gemmBase[4], 256, 165888>>>(P);
    }
}

// round 11
// speedup vs baseline: 1.4596x; 1.2486x over previous
#include <cuda_runtime.h>
#include <cuda_fp16.h>
#include <cstdint>
#include <cstddef>

#define PADC 8

// ---------------- static device buffers ----------------
__device__ __align__(256) float g_corr[12577280];
__device__ __align__(256) float g_map [11141120];
__device__ __align__(256) __half g_wm_h[7667712];   // [lvl][chunk26][tap9][co256][ci32] swizzled
__device__ __align__(256) __half g_wo_h[2359296];   // [lvl][chunk8][tap9][co256][ci32]
__device__ __align__(256) __half g_am_h[37832704];  // [lvl][chunk][b][Hp][Wp][32] swizzled
__device__ __align__(256) __half g_am_l[37832704];
__device__ __align__(256) __half g_ao_h[11640832];
__device__ __align__(256) __half g_ao_l[11640832];

// ---------------- PTX helpers (compute_103 baseline-safe) ----------------
__device__ __forceinline__ uint32_t smem_u32(const void* p){
    uint32_t a;
    asm("{ .reg .u64 t; cvta.to.shared.u64 t, %1; cvt.u32.u64 %0, t; }" : "=r"(a) : "l"(p));
    return a;
}
__device__ __forceinline__ void mbar_init(uint32_t a, uint32_t cnt){
    asm volatile("mbarrier.init.shared.b64 [%0], %1;" :: "r"(a), "r"(cnt) : "memory");
}
__device__ __forceinline__ void mbar_expect(uint32_t a, uint32_t bytes){
    asm volatile("mbarrier.arrive.expect_tx.shared.b64 _, [%0], %1;" :: "r"(a), "r"(bytes) : "memory");
}
__device__ __forceinline__ void mbar_wait(uint32_t a, int parity){
    asm volatile(
        "{\n\t.reg .pred P;\n\t"
        "WL_%=:\n\t"
        "mbarrier.try_wait.parity.acquire.cta.shared::cta.b64 P, [%0], %1, 0x989680;\n\t"
        "@P bra WD_%=;\n\t"
        "bra WL_%=;\n\t"
        "WD_%=:\n\t}"
        :: "r"(a), "r"(parity) : "memory");
}
__device__ __forceinline__ void bulk_cp(uint32_t dst, const void* src, uint32_t bytes, uint32_t mbar){
    asm volatile(
        "cp.async.bulk.shared::cluster.global.mbarrier::complete_tx::bytes [%0], [%1], %2, [%3];"
        :: "r"(dst), "l"(src), "r"(bytes), "r"(mbar) : "memory");
}
__device__ __forceinline__ void ldmx4(uint32_t* r, uint32_t addr){
    asm volatile("ldmatrix.sync.aligned.m8n8.x4.shared.b16 {%0,%1,%2,%3}, [%4];"
                 : "=r"(r[0]), "=r"(r[1]), "=r"(r[2]), "=r"(r[3]) : "r"(addr));
}
__device__ __forceinline__ void mma16816(float* c, const uint32_t* a, uint32_t b0, uint32_t b1){
    asm volatile(
        "mma.sync.aligned.m16n8k16.row.col.f32.f16.f16.f32 "
        "{%0,%1,%2,%3}, {%4,%5,%6,%7}, {%8,%9}, {%0,%1,%2,%3};"
        : "+f"(c[0]), "+f"(c[1]), "+f"(c[2]), "+f"(c[3])
        : "r"(a[0]), "r"(a[1]), "r"(a[2]), "r"(a[3]), "r"(b0), "r"(b1));
}

// ================= merged init bias (3 regions) =================
struct InitParams {
    float* out[3];
    const float* bias[3];
    int HW[3];
    long base[4];
};
__global__ void k_init_all(const __grid_constant__ InitParams P){
    long i = (long)blockIdx.x * blockDim.x + threadIdx.x;
    if (i >= P.base[3]) return;
    int r = 0;
    if (i >= P.base[1]) r = 1;
    if (i >= P.base[2]) r = 2;
    long loc = i - P.base[r];
    P.out[r][loc] = P.bias[r][(loc / P.HW[r]) & 255];
}

// ================= merged weight pack (8 tensors) =================
struct PackWParams {
    const float* src[8];
    __half* dst[8];
    int Cin[8];
    int Cpad[8];
    long base[9];
};
__global__ void k_pack_w_all(const __grid_constant__ PackWParams P){
    long i = (long)blockIdx.x * 256 + threadIdx.x;
    if (i >= P.base[8]) return;
    int t = 0;
    #pragma unroll
    for (int k = 1; k < 8; k++) if (i >= P.base[k]) t = k;
    long loc = i - P.base[t];
    int Cpad = P.Cpad[t], Cin = P.Cin[t];
    int co = (int)(loc / Cpad), ci = (int)(loc % Cpad);
    int c = ci >> 5, cl = ci & 31;
    int gsw = (cl >> 3) ^ ((co >> 1) & 3);
    const float* w = P.src[t];
    __half* oh = P.dst[t];
    #pragma unroll
    for (int tap = 0; tap < 9; tap++){
        float v = (ci < Cin) ? w[(size_t)(co * Cin + ci) * 9 + tap] : 0.f;
        size_t o = (((size_t)c * 9 + tap) * 256 + co) * 32 + (gsw << 3) + (cl & 7);
        oh[o] = __float2half_rn(v);
    }
}

// ================= MMA correlation: corr[w,dj] = band of X^T R =================
// Block = (level, b, h0 group of RPB rows). 8 warps: warp = (hl, w-tile of 16).
// A = x (chunks 0-7 of packed NHWC), resident in smem. B = rx (chunks 8-15),
// double-buffered per (dy, chunk) stage. Output fp32 corr with zero-fill.
struct CorrMMAParams {
    const __half* Xh[4];
    const __half* Xl[4];
    float* out[4];
    int H[4];
    long chS[4];
    int blkBase[5];
};
__global__ __launch_bounds__(256)
void k_corr_mma(const __grid_constant__ CorrMMAParams P)
{
    extern __shared__ char dsm[];
    __shared__ __align__(8) unsigned long long mb[3];

    const int bid = blockIdx.x;
    int l = 0;
    if (bid >= P.blkBase[1]) l = 1;
    if (bid >= P.blkBase[2]) l = 2;
    if (bid >= P.blkBase[3]) l = 3;
    const int rel = bid - P.blkBase[l];
    const int H = P.H[l], W = H, Hp = H + 2, Wp = W + 2;
    const int WT = W >> 4;
    const int RPB = 8 / WT;
    const int HB = H / RPB;
    const int b  = rel / HB;
    const int h0 = (rel % HB) * RPB;
    const long chS = P.chS[l];
    const __half* Xh = P.Xh[l];
    const __half* Xl = P.Xl[l];
    float* corr = P.out[l];

    const uint32_t sb = smem_u32(dsm);
    // A slots: (q*2 + hilo) * 9216, q=0..7 -> 147456 B
    const uint32_t BB = sb + 147456u;
    const uint32_t MBA = smem_u32(&mb[0]);
    const uint32_t MBB = smem_u32(&mb[1]);   // two mbars, stride 8

    const int tid = threadIdx.x, wid = tid >> 5, lane = tid & 31;
    const int wt = wid % WT, hl = wid / WT;
    const int w0 = wt * 16;
    const int lr = lane & 7, lm8 = ((lane >> 3) & 1) * 8, lk = lane >> 4;

    if (tid == 0){
        mbar_init(MBA, 1);
        mbar_init(MBB, 1);
        mbar_init(MBB + 8, 1);
    }
    __syncthreads();

    const long pA0 = (long)(b * Hp + h0 + 1) * Wp + 1;
    const uint32_t Abytes = (uint32_t)(((RPB - 1) * Wp + W) * 64);

    if (tid == 0){
        mbar_expect(MBA, 16u * Abytes);
        #pragma unroll
        for (int q = 0; q < 8; q++){
            bulk_cp(sb + (q * 2 + 0) * 9216u, Xh + (size_t)q * chS + pA0 * 32, Abytes, MBA);
            bulk_cp(sb + (q * 2 + 1) * 9216u, Xl + (size_t)q * chS + pA0 * 32, Abytes, MBA);
        }
    }

    auto issueB = [&](int s){
        int dy = s >> 3, q = s & 7;
        int r0 = h0 + dy - 8;
        int rc0 = (r0 < -1) ? -1 : r0;
        int rc1 = r0 + RPB - 1; if (rc1 > H) rc1 = H;
        if (rc1 < rc0){ rc0 = h0; rc1 = h0; }
        long pB0 = (long)(b * Hp + rc0 + 1) * Wp - 7;
        uint32_t Bb = (uint32_t)(((rc1 - rc0) * Wp + W + 16) * 64);
        int buf = s & 1;
        mbar_expect(MBB + buf * 8, 2u * Bb);
        bulk_cp(BB + buf * 20480u,           Xh + (size_t)(8 + q) * chS + pB0 * 32, Bb, MBB + buf * 8);
        bulk_cp(BB + buf * 20480u + 10240u,  Xl + (size_t)(8 + q) * chS + pB0 * 32, Bb, MBB + buf * 8);
    };

    if (tid == 0) issueB(0);
    mbar_wait(MBA, 0);

    const int offA_px = hl * Wp + w0 + lm8 + lr;
    const int xorA = (int)(((pA0 + offA_px) >> 1) & 3);
    const uint32_t aOff = (uint32_t)offA_px * 64u;

    float acc[4][4];
    const int nStages = 17 * 8;

    for (int s = 0; s < nStages; ++s){
        const int dy = s >> 3, q = s & 7;
        if (tid == 0 && s + 1 < nStages) issueB(s + 1);
        mbar_wait(MBB + (s & 1) * 8, (s >> 1) & 1);

        if (q == 0){
            #pragma unroll
            for (int f = 0; f < 4; f++)
                #pragma unroll
                for (int e = 0; e < 4; e++) acc[f][e] = 0.f;
        }

        int r0 = h0 + dy - 8;
        int rc0 = (r0 < -1) ? -1 : r0;
        int rc1 = r0 + RPB - 1; if (rc1 > H) rc1 = H;
        if (rc1 < rc0){ rc0 = h0; rc1 = h0; }
        const int r = h0 + hl + dy - 8;
        const bool valid = (r >= rc0 && r <= rc1);

        if (valid){
            const long pB0 = (long)(b * Hp + rc0 + 1) * Wp - 7;
            const int rowBase = (r - rc0) * Wp;
            const int offB0 = rowBase + w0 + lm8 + lr;
            const int offB1 = offB0 + 16;
            const int xb0 = (int)(((pB0 + offB0) >> 1) & 3);
            const int xb1 = (int)(((pB0 + offB1) >> 1) & 3);
            const uint32_t Bh0 = BB + (s & 1) * 20480u;
            const uint32_t Bl0 = Bh0 + 10240u;
            const uint32_t Ah0 = sb + (q * 2 + 0) * 9216u;
            const uint32_t Al0 = sb + (q * 2 + 1) * 9216u;

            #pragma unroll
            for (int ks = 0; ks < 2; ks++){
                const int g = 2 * ks + lk;
                uint32_t ah[4], al[4], bh[2][4], bl[2][4];
                ldmx4(ah, Ah0 + aOff + ((uint32_t)(g ^ xorA) << 4));
                ldmx4(al, Al0 + aOff + ((uint32_t)(g ^ xorA) << 4));
                ldmx4(bh[0], Bh0 + (uint32_t)offB0 * 64u + ((uint32_t)(g ^ xb0) << 4));
                ldmx4(bh[1], Bh0 + (uint32_t)offB1 * 64u + ((uint32_t)(g ^ xb1) << 4));
                ldmx4(bl[0], Bl0 + (uint32_t)offB0 * 64u + ((uint32_t)(g ^ xb0) << 4));
                ldmx4(bl[1], Bl0 + (uint32_t)offB1 * 64u + ((uint32_t)(g ^ xb1) << 4));
                #pragma unroll
                for (int nf = 0; nf < 2; nf++)
                    #pragma unroll
                    for (int sub = 0; sub < 2; sub++){
                        const int f = nf * 2 + sub;
                        mma16816(acc[f], ah, bh[nf][sub], bh[nf][2 + sub]);
                        mma16816(acc[f], al, bh[nf][sub], bh[nf][2 + sub]);
                        mma16816(acc[f], ah, bl[nf][sub], bl[nf][2 + sub]);
                    }
            }
        }

        if (q == 7){
            const int h = h0 + hl;
            #pragma unroll
            for (int f = 0; f < 4; f++){
                const int nf = f >> 1, sub = f & 1;
                const int nb = nf * 16 + sub * 8 + (lane & 3) * 2;
                #pragma unroll
                for (int e = 0; e < 2; e++){
                    const int n = nb + e;
                    #pragma unroll
                    for (int mh = 0; mh < 2; mh++){
                        const int m = (lane >> 2) + mh * 8;
                        const int w = w0 + m;
                        const int dj = n - m;
                        const int u = w0 - 8 + n;
                        if (dj >= 0 && dj <= 16){
                            float o = (valid && u >= 0 && u < W) ? acc[f][mh * 2 + e] : 0.f;
                            corr[(((long)b * 289 + dy * 17 + dj) * H + h) * W + w] = o;
                        }
                    }
                }
            }
        }
        __syncthreads();
    }
}

// ================= merged map-act pack (chunk-range parameterized) =================
struct PackMapParams {
    const float* x[4];
    const float* rx[4];
    const float* corr[4];
    __half* Ph[4];
    __half* Pl[4];
    int H[4];
    int npb[4];
    int blkBase[5];
    int cBeg;
};
__global__ void k_pack_map_all(const __grid_constant__ PackMapParams P){
    __shared__ float t[32][33];
    const int bid = blockIdx.x;
    int l = 0;
    if (bid >= P.blkBase[1]) l = 1;
    if (bid >= P.blkBase[2]) l = 2;
    if (bid >= P.blkBase[3]) l = 3;
    const int rel = bid - P.blkBase[l];
    const int npb = P.npb[l];
    const int bxp = rel % npb;
    const int c0  = (P.cBeg + rel / npb) * 32;
    const int H = P.H[l], W = H;
    const int Hp = H + 2, Wp = W + 2, HW = H * W, Np = 2 * Hp * Wp;
    const int p0 = bxp * 32;

    int px = p0 + threadIdx.x;
    int b = 0, pix = 0; bool inter = false;
    if (px < Np){
        b = px / (Hp * Wp); int r = px % (Hp * Wp); int hp = r / Wp, wp = r % Wp;
        if (hp >= 1 && hp <= H && wp >= 1 && wp <= W){ inter = true; pix = (hp - 1) * W + (wp - 1); }
    }
    const float* X  = P.x[l];
    const float* RX = P.rx[l];
    const float* CR = P.corr[l];
    #pragma unroll
    for (int dyy = 0; dyy < 32; dyy += 8){
        int ci = c0 + (int)threadIdx.y + dyy;
        float v = 0.f;
        if (inter){
            if (ci < 256)       v = X [(size_t)(b * 256 + ci) * HW + pix];
            else if (ci < 512)  v = RX[(size_t)(b * 256 + ci - 256) * HW + pix];
            else if (ci < 801)  v = CR[(size_t)(b * 289 + ci - 512) * HW + pix];
        }
        t[threadIdx.y + dyy][threadIdx.x] = v;
    }
    __syncthreads();
    int ft = threadIdx.y * 32 + threadIdx.x;
    int pl = ft >> 3, sub = ft & 7;
    int px2 = p0 + pl;
    if (px2 < Np){
        size_t chStride = (size_t)2 * Hp * Wp * 32;
        int gsw = (sub >> 1) ^ ((px2 >> 1) & 3);
        size_t base = (size_t)(c0 >> 5) * chStride + (size_t)px2 * 32 + (gsw << 3) + (sub & 1) * 4;
        float v0 = t[sub*4+0][pl], v1 = t[sub*4+1][pl], v2 = t[sub*4+2][pl], v3 = t[sub*4+3][pl];
        __half h0 = __float2half_rn(v0), h1 = __float2half_rn(v1);
        __half h2 = __float2half_rn(v2), h3 = __float2half_rn(v3);
        uint32_t uh0 = (uint32_t)__half_as_ushort(h0) | ((uint32_t)__half_as_ushort(h1) << 16);
        uint32_t uh1 = (uint32_t)__half_as_ushort(h2) | ((uint32_t)__half_as_ushort(h3) << 16);
        uint2 wh; wh.x = uh0; wh.y = uh1;
        *reinterpret_cast<uint2*>(P.Ph[l] + base) = wh;
        __half l0 = __float2half_rn(v0 - __half2float(h0));
        __half l1 = __float2half_rn(v1 - __half2float(h1));
        __half l2 = __float2half_rn(v2 - __half2float(h2));
        __half l3 = __float2half_rn(v3 - __half2float(h3));
        uint32_t ul0 = (uint32_t)__half_as_ushort(l0) | ((uint32_t)__half_as_ushort(l1) << 16);
        uint32_t ul1 = (uint32_t)__half_as_ushort(l2) | ((uint32_t)__half_as_ushort(l3) << 16);
        uint2 wl; wl.x = ul0; wl.y = ul1;
        *reinterpret_cast<uint2*>(P.Pl[l] + base) = wl;
    }
}

// ================= merged out-act pack with fused upsample cascade =================
struct PackOutParams {
    const float* map[4];
    __half* Ph[4];
    __half* Pl[4];
    int H[4];
    int npb[4];
    int blkBase[5];
};
__global__ void k_pack_out_all(const __grid_constant__ PackOutParams P){
    __shared__ float t[32][33];
    const int bid = blockIdx.x;
    int l = 0;
    if (bid >= P.blkBase[1]) l = 1;
    if (bid >= P.blkBase[2]) l = 2;
    if (bid >= P.blkBase[3]) l = 3;
    const int rel = bid - P.blkBase[l];
    const int npb = P.npb[l];
    const int bxp = rel % npb;
    const int c0  = (rel / npb) * 32;
    const int H = P.H[l], W = H;
    const int Hp = H + 2, Wp = W + 2, Np = 2 * Hp * Wp;
    const int p0 = bxp * 32;

    int px = p0 + threadIdx.x;
    int b = 0, hh = 0, ww = 0; bool inter = false;
    if (px < Np){
        b = px / (Hp * Wp); int r = px % (Hp * Wp); int hp = r / Wp, wp = r % Wp;
        if (hp >= 1 && hp <= H && wp >= 1 && wp <= W){ inter = true; hh = hp - 1; ww = wp - 1; }
    }
    #pragma unroll
    for (int dyy = 0; dyy < 32; dyy += 8){
        int ci = c0 + (int)threadIdx.y + dyy;
        float v = 0.f;
        if (inter){
            for (int k = l; k < 4; k++){
                int Wk = P.H[k];
                int sh = k - l;
                v += P.map[k][((size_t)(b * 256 + ci) * Wk + (hh >> sh)) * Wk + (ww >> sh)];
            }
        }
        t[threadIdx.y + dyy][threadIdx.x] = v;
    }
    __syncthreads();
    int ft = threadIdx.y * 32 + threadIdx.x;
    int pl = ft >> 3, sub = ft & 7;
    int px2 = p0 + pl;
    if (px2 < Np){
        size_t chStride = (size_t)2 * Hp * Wp * 32;
        int gsw = (sub >> 1) ^ ((px2 >> 1) & 3);
        size_t base = (size_t)(c0 >> 5) * chStride + (size_t)px2 * 32 + (gsw << 3) + (sub & 1) * 4;
        float v0 = t[sub*4+0][pl], v1 = t[sub*4+1][pl], v2 = t[sub*4+2][pl], v3 = t[sub*4+3][pl];
        __half h0 = __float2half_rn(v0), h1 = __float2half_rn(v1);
        __half h2 = __float2half_rn(v2), h3 = __float2half_rn(v3);
        uint32_t uh0 = (uint32_t)__half_as_ushort(h0) | ((uint32_t)__half_as_ushort(h1) << 16);
        uint32_t uh1 = (uint32_t)__half_as_ushort(h2) | ((uint32_t)__half_as_ushort(h3) << 16);
        uint2 wh; wh.x = uh0; wh.y = uh1;
        *reinterpret_cast<uint2*>(P.Ph[l] + base) = wh;
        __half l0 = __float2half_rn(v0 - __half2float(h0));
        __half l1 = __float2half_rn(v1 - __half2float(h1));
        __half l2 = __float2half_rn(v2 - __half2float(h2));
        __half l3 = __float2half_rn(v3 - __half2float(h3));
        uint32_t ul0 = (uint32_t)__half_as_ushort(l0) | ((uint32_t)__half_as_ushort(l1) << 16);
        uint32_t ul1 = (uint32_t)__half_as_ushort(l2) | ((uint32_t)__half_as_ushort(l3) << 16);
        uint2 wl; wl.x = ul0; wl.y = ul1;
        *reinterpret_cast<uint2*>(P.Pl[l] + base) = wl;
    }
}

// ================= merged multi-level fp16 2-pass implicit-conv GEMM =================
struct GemmParams {
    const __half* A;
    const __half* BhB;
    const __half* BlB;
    float*        out[4];
    const float*  bias[4];
    long aOff[4];
    long bOff[4];
    int  H[4];
    int  lgW[4];
    int  zc[4];
    int  tpz[4];
    int  blkBase[5];
    int  CH;
};

__global__ __launch_bounds__(256)
void k_gemm(const __grid_constant__ GemmParams P)
{
    extern __shared__ char dsm[];
    __shared__ __align__(8) unsigned long long mb[6];

    const int bid = blockIdx.x;
    int l = 0;
    if (bid >= P.blkBase[1]) l = 1;
    if (bid >= P.blkBase[2]) l = 2;
    if (bid >= P.blkBase[3]) l = 3;
    const int rel = bid - P.blkBase[l];
    const int zc = P.zc[l], tapsPerZ = P.tpz[l];
    const int zi = rel % zc;
    const int tt = rel / zc;
    const int m0 = (tt & 1) * 128;
    const int nt = tt >> 1;
    const int H = P.H[l], W = H, lgW = P.lgW[l];
    const __half* A  = P.A   + P.aOff[l];
    const __half* Bh = P.BhB + P.bOff[l];
    const __half* Bl = P.BlB + P.bOff[l];
    float* out = P.out[l];
    const float* bias = P.bias[l];
    const int useAtomic = (zc > 1);
    const int tapBeg = zi * tapsPerZ;
    const int CH = P.CH;

    const uint32_t smemBase = smem_u32(dsm);
    uint32_t A_OFF[4], B_OFF[2];
    #pragma unroll
    for (int s = 0; s < 4; s++) A_OFF[s] = smemBase + s * 8192u;
    B_OFF[0] = smemBase + 32768u;
    B_OFF[1] = smemBase + 32768u + 66560u;
    const uint32_t MBA = smem_u32(&mb[0]);
    const uint32_t MBB = smem_u32(&mb[4]);

    const int tid = threadIdx.x, wid = tid >> 5, lane = tid & 31;
    const int R = 256 >> lgW;
    const int Hp = H + 2, Wp = W + 2;
    const int tilesPerB = H / R;
    const int b  = nt / tilesPerB;
    const int h0 = (nt % tilesPerB) * R;
    const int q0 = (b * Hp + h0) * Wp;
    const uint32_t Bbytes = (uint32_t)(R + 2) * Wp * 64u;
    const size_t chStride = (size_t)2 * Hp * Wp * 32;

    if (tid == 0){
        #pragma unroll
        for (int i = 0; i < 6; i++) mbar_init(MBA + i * 8, 1);
    }
    __syncthreads();

    const int nA = CH * tapsPerZ;

    auto issueA = [&](int ia){
        int c = ia / tapsPerZ, tap = ia % tapsPerZ;
        const __half* src = A + ((((size_t)c * 9 + (tapBeg + tap)) * 256 + m0) << 5);
        int s = ia & 3;
        mbar_expect(MBA + s * 8, 8192u);
        bulk_cp(A_OFF[s], src, 8192u, MBA + s * 8);
    };
    auto issueB = [&](int c){
        int s = c & 1;
        mbar_expect(MBB + s * 8, 2u * Bbytes);
        bulk_cp(B_OFF[s],          Bh + (size_t)c * chStride + ((size_t)q0 << 5), Bbytes, MBB + s * 8);
        bulk_cp(B_OFF[s] + 33280u, Bl + (size_t)c * chStride + ((size_t)q0 << 5), Bbytes, MBB + s * 8);
    };

    const int lr  = lane & 7;
    const int lm8 = ((lane >> 3) & 1) * 8;
    const int lk  = lane >> 4;
    const int wm  = wid & 1;
    const int wn  = wid >> 1;
    const int rowA = wm * 64 + lm8 + lr;
    const int xorA = (lr >> 1) & 3;
    int rB[4], wB[4];
    #pragma unroll
    for (int g = 0; g < 4; g++){
        int n = wn * 64 + g * 16 + lm8 + lr;
        rB[g] = n >> lgW;
        wB[g] = n & (W - 1);
    }

    float acc[4][8][4];
    #pragma unroll
    for (int i = 0; i < 4; i++)
        #pragma unroll
        for (int j = 0; j < 8; j++)
            #pragma unroll
            for (int k = 0; k < 4; k++) acc[i][j][k] = 0.f;

    if (tid == 0){
        issueB(0);
        issueA(0);
        if (nA > 1) issueA(1);
        if (nA > 2) issueA(2);
    }

    for (int it = 0; it < nA; ++it){
        int c = it / tapsPerZ, tap = it % tapsPerZ;
        if (tid == 0){
            if (it + 3 < nA) issueA(it + 3);
            if (tap == 0 && c + 1 < CH) issueB(c + 1);
        }
        mbar_wait(MBA + (it & 3) * 8, (it >> 2) & 1);
        if (tap == 0) mbar_wait(MBB + (c & 1) * 8, (c >> 1) & 1);

        const uint32_t Ab = A_OFF[it & 3];
        const uint32_t Bb = B_OFF[c & 1];
        const int tIdx = tapBeg + tap;
        const int dy = tIdx / 3, dx = tIdx - dy * 3;

        uint32_t sAdr[4]; int xorB[4];
        #pragma unroll
        for (int g = 0; g < 4; g++){
            int s = (rB[g] + dy) * Wp + wB[g] + dx;
            sAdr[g] = Bb + (uint32_t)s * 64u;
            xorB[g] = ((q0 + s) >> 1) & 3;
        }

        #pragma unroll
        for (int ks = 0; ks < 2; ks++){
            const int gA = (2 * ks + lk) ^ xorA;
            uint32_t a[4][4];
            #pragma unroll
            for (int ma = 0; ma < 4; ma++)
                ldmx4(a[ma], Ab + (uint32_t)(rowA + ma * 16) * 64u + ((uint32_t)gA << 4));
            #pragma unroll
            for (int pass = 0; pass < 2; pass++){
                uint32_t bb[4][4];
                #pragma unroll
                for (int g = 0; g < 4; g++){
                    int gB = (2 * ks + lk) ^ xorB[g];
                    ldmx4(bb[g], sAdr[g] + (uint32_t)pass * 33280u + ((uint32_t)gB << 4));
                }
                #pragma unroll
                for (int ma = 0; ma < 4; ma++)
                    #pragma unroll
                    for (int na = 0; na < 8; na++)
                        mma16816(acc[ma][na], a[ma], bb[na >> 1][na & 1], bb[na >> 1][2 + (na & 1)]);
            }
        }
        __syncthreads();
    }

    #pragma unroll
    for (int ma = 0; ma < 4; ma++){
        int co0 = m0 + wm * 64 + ma * 16 + (lane >> 2);
        int co1 = co0 + 8;
        float bv0 = useAtomic ? 0.f : bias[co0];
        float bv1 = useAtomic ? 0.f : bias[co1];
        #pragma unroll
        for (int na = 0; na < 8; na++){
            int n = wn * 64 + na * 8 + (lane & 3) * 2;
            int r = h0 + (n >> lgW);
            int w = n & (W - 1);
            size_t i0 = ((size_t)(b * 256 + co0) * H + r) * W + w;
            size_t i1 = ((size_t)(b * 256 + co1) * H + r) * W + w;
            if (useAtomic){
                atomicAdd(&out[i0],     acc[ma][na][0]);
                atomicAdd(&out[i0 + 1], acc[ma][na][1]);
                atomicAdd(&out[i1],     acc[ma][na][2]);
                atomicAdd(&out[i1 + 1], acc[ma][na][3]);
            } else {
                float2 v0; v0.x = acc[ma][na][0] + bv0; v0.y = acc[ma][na][1] + bv0;
                float2 v1; v1.x = acc[ma][na][2] + bv1; v1.y = acc[ma][na][3] + bv1;
                *reinterpret_cast<float2*>(&out[i0]) = v0;
                *reinterpret_cast<float2*>(&out[i1]) = v1;
            }
        }
    }
}

// ---------------- host orchestration (9 launches total) ----------------
extern "C" void kernel_launch(void* const* d_in, const int* in_sizes, int n_in,
                              void* d_out, int out_size)
{
    const float *x[4]={0,0,0,0}, *rx[4]={0,0,0,0};
    const float *wm[4]={0,0,0,0}, *bm[4]={0,0,0,0}, *wo[4]={0,0,0,0}, *bo[4]={0,0,0,0};
    int wmi = 0, woi = 0, bi = 0;
    for (int i = 0; i < n_in; i++){
        int s = in_sizes[i];
        int lvl = -1;
        if      (s == 2*256*128*128) lvl = 0;
        else if (s == 2*256*64*64)   lvl = 1;
        else if (s == 2*256*32*32)   lvl = 2;
        else if (s == 2*256*16*16)   lvl = 3;
        if (lvl >= 0){
            if (!x[lvl]) x[lvl] = (const float*)d_in[i];
            else         rx[lvl] = (const float*)d_in[i];
        }
        else if (s == 1845504) wm[wmi++] = (const float*)d_in[i];
        else if (s ==  589824) wo[woi++] = (const float*)d_in[i];
        else if (s ==     256){
            if ((bi & 1) == 0) bm[bi >> 1] = (const float*)d_in[i];
            else               bo[bi >> 1] = (const float*)d_in[i];
            bi++;
        }
    }

    float *corrB, *mapB;
    __half *wmh, *woh, *amh, *aml, *aoh, *aol;
    cudaGetSymbolAddress((void**)&corrB, g_corr);
    cudaGetSymbolAddress((void**)&mapB,  g_map);
    cudaGetSymbolAddress((void**)&wmh, g_wm_h);
    cudaGetSymbolAddress((void**)&woh, g_wo_h);
    cudaGetSymbolAddress((void**)&amh, g_am_h); cudaGetSymbolAddress((void**)&aml, g_am_l);
    cudaGetSymbolAddress((void**)&aoh, g_ao_h); cudaGetSymbolAddress((void**)&aol, g_ao_l);

    cudaFuncSetAttribute(k_gemm, cudaFuncAttributeMaxDynamicSharedMemorySize, 165888);
    cudaFuncSetAttribute(k_corr_mma, cudaFuncAttributeMaxDynamicSharedMemorySize, 188416);

    const int  Hl[4]      = {128, 64, 32, 16};
    const int  lgWl[4]    = {7, 6, 5, 4};
    const int  HWl[4]     = {16384, 4096, 1024, 256};
    const long corrOff[4] = {0, 9469952, 11837440, 12429312};
    const long mapOff[4]  = {0, 8388608, 10485760, 11010048};
    const long amOff[4]   = {0, 28121600, 35369984, 37293568};
    const long aoOff[4]   = {0, 8652800, 10883072, 11474944};
    const long wmOff[4]   = {0, 1916928, 3833856, 5750784};
    const long woOff[4]   = {0, 589824, 1179648, 1769472};
    const int  zl[4]      = {1, 3, 9, 9};
    const int  tpzl[4]    = {9, 3, 1, 1};
    float* outp = (float*)d_out;

    int gemmBase[5]; gemmBase[0] = 0;
    for (int l = 0; l < 4; l++)
        gemmBase[l + 1] = gemmBase[l] + (2 * HWl[l] / 256) * 2 * zl[l];  // {0,256,448,592,628}

    int npbl[4];
    for (int l = 0; l < 4; l++){
        int Np = 2 * (Hl[l] + 2) * (Hl[l] + 2);
        npbl[l] = (Np + 31) / 32;
    }

    // ---- launch 0: init map buffers (levels 1-3, atomic) ----
    {
        InitParams P;
        long tot = 0;
        for (int r = 0; r < 3; r++){
            int l = r + 1;
            P.out[r] = mapB + mapOff[l]; P.bias[r] = bm[l]; P.HW[r] = HWl[l];
            P.base[r] = tot; tot += 2L * 256 * HWl[l];
        }
        P.base[3] = tot;
        k_init_all<<<(int)((tot + 255) / 256), 256>>>(P);
    }
    // ---- launch 1: init out buffers (levels 1-3, atomic) ----
    {
        InitParams P;
        long tot = 0;
        for (int r = 0; r < 3; r++){
            int l = r + 1;
            P.out[r] = outp + mapOff[l]; P.bias[r] = bo[l]; P.HW[r] = HWl[l];
            P.base[r] = tot; tot += 2L * 256 * HWl[l];
        }
        P.base[3] = tot;
        k_init_all<<<(int)((tot + 255) / 256), 256>>>(P);
    }
    // ---- launch 2: pack all weights ----
    {
        PackWParams P;
        long tot = 0;
        for (int l = 0; l < 4; l++){
            P.src[l] = wm[l]; P.dst[l] = wmh + wmOff[l]; P.Cin[l] = 801; P.Cpad[l] = 832;
            P.base[l] = tot; tot += 256L * 832;
        }
        for (int l = 0; l < 4; l++){
            P.src[4+l] = wo[l]; P.dst[4+l] = woh + woOff[l]; P.Cin[4+l] = 256; P.Cpad[4+l] = 256;
            P.base[4+l] = tot; tot += 256L * 256;
        }
        P.base[8] = tot;
        k_pack_w_all<<<(int)((tot + 255) / 256), 256>>>(P);
    }
    // ---- launch 3: pack x/rx activation chunks (0-15) ----
    {
        PackMapParams P;
        int base = 0;
        for (int l = 0; l < 4; l++){
            P.x[l] = x[l]; P.rx[l] = rx[l]; P.corr[l] = corrB + corrOff[l];
            P.Ph[l] = amh + amOff[l]; P.Pl[l] = aml + amOff[l];
            P.H[l] = Hl[l]; P.npb[l] = npbl[l];
            P.blkBase[l] = base;
            base += npbl[l] * 16;
        }
        P.blkBase[4] = base;
        P.cBeg = 0;
        k_pack_map_all<<<base, dim3(32, 8)>>>(P);
    }
    // ---- launch 4: MMA correlation ----
    {
        CorrMMAParams P;
        int base = 0;
        for (int l = 0; l < 4; l++){
            P.Xh[l] = amh + amOff[l];
            P.Xl[l] = aml + amOff[l];
            P.out[l] = corrB + corrOff[l];
            P.H[l] = Hl[l];
            P.chS[l] = 2L * (Hl[l] + 2) * (Hl[l] + 2) * 32;
            P.blkBase[l] = base;
            int RPB = 128 / Hl[l];
            base += 2 * Hl[l] / RPB;
        }
        P.blkBase[4] = base;   // 340
        k_corr_mma<<<base, 256, 188416>>>(P);
    }
    // ---- launch 5: pack corr activation chunks (16-25) ----
    {
        PackMapParams P;
        int base = 0;
        for (int l = 0; l < 4; l++){
            P.x[l] = x[l]; P.rx[l] = rx[l]; P.corr[l] = corrB + corrOff[l];
            P.Ph[l] = amh + amOff[l]; P.Pl[l] = aml + amOff[l];
            P.H[l] = Hl[l]; P.npb[l] = npbl[l];
            P.blkBase[l] = base;
            base += npbl[l] * 10;
        }
        P.blkBase[4] = base;
        P.cBeg = 16;
        k_pack_map_all<<<base, dim3(32, 8)>>>(P);
    }
    // ---- launch 6: merged map GEMM ----
    {
        GemmParams P;
        P.A = wmh; P.BhB = amh; P.BlB = aml;
        for (int l = 0; l < 4; l++){
            P.out[l] = mapB + mapOff[l]; P.bias[l] = bm[l];
            P.aOff[l] = wmOff[l]; P.bOff[l] = amOff[l];
            P.H[l] = Hl[l]; P.lgW[l] = lgWl[l]; P.zc[l] = zl[l]; P.tpz[l] = tpzl[l];
        }
        for (int i = 0; i < 5; i++) P.blkBase[i] = gemmBase[i];
        P.CH = 26;
        k_gemm<<<gemmBase[4], 256, 165888>>>(P);
    }
    // ---- launch 7: pack out activations with fused upsample cascade ----
    {
        PackOutParams P;
        int base = 0;
        for (int l = 0; l < 4; l++){
            P.map[l] = mapB + mapOff[l];
            P.Ph[l] = aoh + aoOff[l]; P.Pl[l] = aol + aoOff[l];
            P.H[l] = Hl[l]; P.npb[l] = npbl[l];
            P.blkBase[l] = base;
            base += npbl[l] * 8;
        }
        P.blkBase[4] = base;
        k_pack_out_all<<<base, dim3(32, 8)>>>(P);
    }
    // ---- launch 8: merged out GEMM -> d_out ----
    {
        GemmParams P;
        P.A = woh; P.BhB = aoh; P.BlB = aol;
        for (int l = 0; l < 4; l++){
            P.out[l] = outp + mapOff[l]; P.bias[l] = bo[l];
            P.aOff[l] = woOff[l]; P.bOff[l] = aoOff[l];
            P.H[l] = Hl[l]; P.lgW[l] = lgWl[l]; P.zc[l] = zl[l]; P.tpz[l] = tpzl[l];
        }
        for (int i = 0; i < 5; i++) P.blkBase[i] = gemmBase[i];
        P.CH = 8;
        k_gemm<<<gemmBase[4], 256, 165888>>>(P);
    }
}

// round 12
// speedup vs baseline: 1.7449x; 1.1955x over previous
#include <cuda_runtime.h>
#include <cuda_fp16.h>
#include <cstdint>
#include <cstddef>

#define PADC 8

// ---------------- static device buffers ----------------
__device__ __align__(256) float g_corr[12577280];
__device__ __align__(256) float g_map [11141120];
__device__ __align__(256) __half g_wm_h[7667712];   // [lvl][chunk26][tap9][co256][ci32] swizzled
__device__ __align__(256) __half g_wo_h[2359296];   // [lvl][chunk8][tap9][co256][ci32]
__device__ __align__(256) __half g_am_h[37832704];  // [lvl][chunk][b][Hp][Wp][32] swizzled
__device__ __align__(256) __half g_am_l[37832704];
__device__ __align__(256) __half g_ao_h[11640832];
__device__ __align__(256) __half g_ao_l[11640832];

// ---------------- PTX helpers (compute_103 baseline-safe) ----------------
__device__ __forceinline__ uint32_t smem_u32(const void* p){
    uint32_t a;
    asm("{ .reg .u64 t; cvta.to.shared.u64 t, %1; cvt.u32.u64 %0, t; }" : "=r"(a) : "l"(p));
    return a;
}
__device__ __forceinline__ void mbar_init(uint32_t a, uint32_t cnt){
    asm volatile("mbarrier.init.shared.b64 [%0], %1;" :: "r"(a), "r"(cnt) : "memory");
}
__device__ __forceinline__ void mbar_expect(uint32_t a, uint32_t bytes){
    asm volatile("mbarrier.arrive.expect_tx.shared.b64 _, [%0], %1;" :: "r"(a), "r"(bytes) : "memory");
}
__device__ __forceinline__ void mbar_wait(uint32_t a, int parity){
    asm volatile(
        "{\n\t.reg .pred P;\n\t"
        "WL_%=:\n\t"
        "mbarrier.try_wait.parity.acquire.cta.shared::cta.b64 P, [%0], %1, 0x989680;\n\t"
        "@P bra WD_%=;\n\t"
        "bra WL_%=;\n\t"
        "WD_%=:\n\t}"
        :: "r"(a), "r"(parity) : "memory");
}
__device__ __forceinline__ void bulk_cp(uint32_t dst, const void* src, uint32_t bytes, uint32_t mbar){
    asm volatile(
        "cp.async.bulk.shared::cluster.global.mbarrier::complete_tx::bytes [%0], [%1], %2, [%3];"
        :: "r"(dst), "l"(src), "r"(bytes), "r"(mbar) : "memory");
}
__device__ __forceinline__ void ldmx4(uint32_t* r, uint32_t addr){
    asm volatile("ldmatrix.sync.aligned.m8n8.x4.shared.b16 {%0,%1,%2,%3}, [%4];"
                 : "=r"(r[0]), "=r"(r[1]), "=r"(r[2]), "=r"(r[3]) : "r"(addr));
}
__device__ __forceinline__ void mma16816(float* c, const uint32_t* a, uint32_t b0, uint32_t b1){
    asm volatile(
        "mma.sync.aligned.m16n8k16.row.col.f32.f16.f16.f32 "
        "{%0,%1,%2,%3}, {%4,%5,%6,%7}, {%8,%9}, {%0,%1,%2,%3};"
        : "+f"(c[0]), "+f"(c[1]), "+f"(c[2]), "+f"(c[3])
        : "r"(a[0]), "r"(a[1]), "r"(a[2]), "r"(a[3]), "r"(b0), "r"(b1));
}

// ================= merged init bias (6 regions) =================
struct InitParams {
    float* out[6];
    const float* bias[6];
    int HW[6];
    long base[7];
};
__global__ void k_init_all(const __grid_constant__ InitParams P){
    long i = (long)blockIdx.x * blockDim.x + threadIdx.x;
    if (i >= P.base[6]) return;
    int r = 0;
    #pragma unroll
    for (int k = 1; k < 6; k++) if (i >= P.base[k]) r = k;
    long loc = i - P.base[r];
    P.out[r][loc] = P.bias[r][(loc / P.HW[r]) & 255];
}

// ================= merged weight pack (8 tensors) =================
struct PackWParams {
    const float* src[8];
    __half* dst[8];
    int Cin[8];
    int Cpad[8];
    long base[9];
};
__global__ void k_pack_w_all(const __grid_constant__ PackWParams P){
    long i = (long)blockIdx.x * 256 + threadIdx.x;
    if (i >= P.base[8]) return;
    int t = 0;
    #pragma unroll
    for (int k = 1; k < 8; k++) if (i >= P.base[k]) t = k;
    long loc = i - P.base[t];
    int Cpad = P.Cpad[t], Cin = P.Cin[t];
    int co = (int)(loc / Cpad), ci = (int)(loc % Cpad);
    int c = ci >> 5, cl = ci & 31;
    int gsw = (cl >> 3) ^ ((co >> 1) & 3);
    const float* w = P.src[t];
    __half* oh = P.dst[t];
    #pragma unroll
    for (int tap = 0; tap < 9; tap++){
        float v = (ci < Cin) ? w[(size_t)(co * Cin + ci) * 9 + tap] : 0.f;
        size_t o = (((size_t)c * 9 + tap) * 256 + co) * 32 + (gsw << 3) + (cl & 7);
        oh[o] = __float2half_rn(v);
    }
}

// ================= MMA correlation: corr[w,dj] = band of X^T R =================
struct CorrMMAParams {
    const __half* Xh[4];
    const __half* Xl[4];
    float* out[4];
    int H[4];
    long chS[4];
    int blkBase[5];
};
__global__ __launch_bounds__(256)
void k_corr_mma(const __grid_constant__ CorrMMAParams P)
{
    extern __shared__ char dsm[];
    __shared__ __align__(8) unsigned long long mb[3];

    const int bid = blockIdx.x;
    int l = 0;
    if (bid >= P.blkBase[1]) l = 1;
    if (bid >= P.blkBase[2]) l = 2;
    if (bid >= P.blkBase[3]) l = 3;
    const int rel = bid - P.blkBase[l];
    const int H = P.H[l], W = H, Hp = H + 2, Wp = W + 2;
    const int WT = W >> 4;
    const int RPB = 8 / WT;
    const int HB = H / RPB;
    const int b  = rel / HB;
    const int h0 = (rel % HB) * RPB;
    const long chS = P.chS[l];
    const __half* Xh = P.Xh[l];
    const __half* Xl = P.Xl[l];
    float* corr = P.out[l];

    const uint32_t sb = smem_u32(dsm);
    const uint32_t BB = sb + 147456u;
    const uint32_t MBA = smem_u32(&mb[0]);
    const uint32_t MBB = smem_u32(&mb[1]);

    const int tid = threadIdx.x, wid = tid >> 5, lane = tid & 31;
    const int wt = wid % WT, hl = wid / WT;
    const int w0 = wt * 16;
    const int lr = lane & 7, lm8 = ((lane >> 3) & 1) * 8, lk = lane >> 4;

    if (tid == 0){
        mbar_init(MBA, 1);
        mbar_init(MBB, 1);
        mbar_init(MBB + 8, 1);
    }
    __syncthreads();

    const long pA0 = (long)(b * Hp + h0 + 1) * Wp + 1;
    const uint32_t Abytes = (uint32_t)(((RPB - 1) * Wp + W) * 64);

    if (tid == 0){
        mbar_expect(MBA, 16u * Abytes);
        #pragma unroll
        for (int q = 0; q < 8; q++){
            bulk_cp(sb + (q * 2 + 0) * 9216u, Xh + (size_t)q * chS + pA0 * 32, Abytes, MBA);
            bulk_cp(sb + (q * 2 + 1) * 9216u, Xl + (size_t)q * chS + pA0 * 32, Abytes, MBA);
        }
    }

    auto issueB = [&](int s){
        int dy = s >> 3, q = s & 7;
        int r0 = h0 + dy - 8;
        int rc0 = (r0 < -1) ? -1 : r0;
        int rc1 = r0 + RPB - 1; if (rc1 > H) rc1 = H;
        if (rc1 < rc0){ rc0 = h0; rc1 = h0; }
        long pB0 = (long)(b * Hp + rc0 + 1) * Wp - 7;
        uint32_t Bb = (uint32_t)(((rc1 - rc0) * Wp + W + 16) * 64);
        int buf = s & 1;
        mbar_expect(MBB + buf * 8, 2u * Bb);
        bulk_cp(BB + buf * 20480u,           Xh + (size_t)(8 + q) * chS + pB0 * 32, Bb, MBB + buf * 8);
        bulk_cp(BB + buf * 20480u + 10240u,  Xl + (size_t)(8 + q) * chS + pB0 * 32, Bb, MBB + buf * 8);
    };

    if (tid == 0) issueB(0);
    mbar_wait(MBA, 0);

    const int offA_px = hl * Wp + w0 + lm8 + lr;
    const int xorA = (int)(((pA0 + offA_px) >> 1) & 3);
    const uint32_t aOff = (uint32_t)offA_px * 64u;

    float acc[4][4];
    const int nStages = 17 * 8;

    for (int s = 0; s < nStages; ++s){
        const int dy = s >> 3, q = s & 7;
        if (tid == 0 && s + 1 < nStages) issueB(s + 1);
        mbar_wait(MBB + (s & 1) * 8, (s >> 1) & 1);

        if (q == 0){
            #pragma unroll
            for (int f = 0; f < 4; f++)
                #pragma unroll
                for (int e = 0; e < 4; e++) acc[f][e] = 0.f;
        }

        int r0 = h0 + dy - 8;
        int rc0 = (r0 < -1) ? -1 : r0;
        int rc1 = r0 + RPB - 1; if (rc1 > H) rc1 = H;
        if (rc1 < rc0){ rc0 = h0; rc1 = h0; }
        const int r = h0 + hl + dy - 8;
        const bool valid = (r >= rc0 && r <= rc1);

        if (valid){
            const long pB0 = (long)(b * Hp + rc0 + 1) * Wp - 7;
            const int rowBase = (r - rc0) * Wp;
            const int offB0 = rowBase + w0 + lm8 + lr;
            const int offB1 = offB0 + 16;
            const int xb0 = (int)(((pB0 + offB0) >> 1) & 3);
            const int xb1 = (int)(((pB0 + offB1) >> 1) & 3);
            const uint32_t Bh0 = BB + (s & 1) * 20480u;
            const uint32_t Bl0 = Bh0 + 10240u;
            const uint32_t Ah0 = sb + (q * 2 + 0) * 9216u;
            const uint32_t Al0 = sb + (q * 2 + 1) * 9216u;

            #pragma unroll
            for (int ks = 0; ks < 2; ks++){
                const int g = 2 * ks + lk;
                uint32_t ah[4], al[4], bh[2][4], bl[2][4];
                ldmx4(ah, Ah0 + aOff + ((uint32_t)(g ^ xorA) << 4));
                ldmx4(al, Al0 + aOff + ((uint32_t)(g ^ xorA) << 4));
                ldmx4(bh[0], Bh0 + (uint32_t)offB0 * 64u + ((uint32_t)(g ^ xb0) << 4));
                ldmx4(bh[1], Bh0 + (uint32_t)offB1 * 64u + ((uint32_t)(g ^ xb1) << 4));
                ldmx4(bl[0], Bl0 + (uint32_t)offB0 * 64u + ((uint32_t)(g ^ xb0) << 4));
                ldmx4(bl[1], Bl0 + (uint32_t)offB1 * 64u + ((uint32_t)(g ^ xb1) << 4));
                #pragma unroll
                for (int nf = 0; nf < 2; nf++)
                    #pragma unroll
                    for (int sub = 0; sub < 2; sub++){
                        const int f = nf * 2 + sub;
                        mma16816(acc[f], ah, bh[nf][sub], bh[nf][2 + sub]);
                        mma16816(acc[f], al, bh[nf][sub], bh[nf][2 + sub]);
                        mma16816(acc[f], ah, bl[nf][sub], bl[nf][2 + sub]);
                    }
            }
        }

        if (q == 7){
            const int h = h0 + hl;
            #pragma unroll
            for (int f = 0; f < 4; f++){
                const int nf = f >> 1, sub = f & 1;
                const int nb = nf * 16 + sub * 8 + (lane & 3) * 2;
                #pragma unroll
                for (int e = 0; e < 2; e++){
                    const int n = nb + e;
                    #pragma unroll
                    for (int mh = 0; mh < 2; mh++){
                        const int m = (lane >> 2) + mh * 8;
                        const int w = w0 + m;
                        const int dj = n - m;
                        const int u = w0 - 8 + n;
                        if (dj >= 0 && dj <= 16){
                            float o = (valid && u >= 0 && u < W) ? acc[f][mh * 2 + e] : 0.f;
                            corr[(((long)b * 289 + dy * 17 + dj) * H + h) * W + w] = o;
                        }
                    }
                }
            }
        }
        __syncthreads();
    }
}

// ================= merged map-act pack (chunk-range parameterized) =================
struct PackMapParams {
    const float* x[4];
    const float* rx[4];
    const float* corr[4];
    __half* Ph[4];
    __half* Pl[4];
    int H[4];
    int npb[4];
    int blkBase[5];
    int cBeg;
};
__global__ void k_pack_map_all(const __grid_constant__ PackMapParams P){
    __shared__ float t[32][33];
    const int bid = blockIdx.x;
    int l = 0;
    if (bid >= P.blkBase[1]) l = 1;
    if (bid >= P.blkBase[2]) l = 2;
    if (bid >= P.blkBase[3]) l = 3;
    const int rel = bid - P.blkBase[l];
    const int npb = P.npb[l];
    const int bxp = rel % npb;
    const int c0  = (P.cBeg + rel / npb) * 32;
    const int H = P.H[l], W = H;
    const int Hp = H + 2, Wp = W + 2, HW = H * W, Np = 2 * Hp * Wp;
    const int p0 = bxp * 32;

    int px = p0 + threadIdx.x;
    int b = 0, pix = 0; bool inter = false;
    if (px < Np){
        b = px / (Hp * Wp); int r = px % (Hp * Wp); int hp = r / Wp, wp = r % Wp;
        if (hp >= 1 && hp <= H && wp >= 1 && wp <= W){ inter = true; pix = (hp - 1) * W + (wp - 1); }
    }
    const float* X  = P.x[l];
    const float* RX = P.rx[l];
    const float* CR = P.corr[l];
    #pragma unroll
    for (int dyy = 0; dyy < 32; dyy += 8){
        int ci = c0 + (int)threadIdx.y + dyy;
        float v = 0.f;
        if (inter){
            if (ci < 256)       v = X [(size_t)(b * 256 + ci) * HW + pix];
            else if (ci < 512)  v = RX[(size_t)(b * 256 + ci - 256) * HW + pix];
            else if (ci < 801)  v = CR[(size_t)(b * 289 + ci - 512) * HW + pix];
        }
        t[threadIdx.y + dyy][threadIdx.x] = v;
    }
    __syncthreads();
    int ft = threadIdx.y * 32 + threadIdx.x;
    int pl = ft >> 3, sub = ft & 7;
    int px2 = p0 + pl;
    if (px2 < Np){
        size_t chStride = (size_t)2 * Hp * Wp * 32;
        int gsw = (sub >> 1) ^ ((px2 >> 1) & 3);
        size_t base = (size_t)(c0 >> 5) * chStride + (size_t)px2 * 32 + (gsw << 3) + (sub & 1) * 4;
        float v0 = t[sub*4+0][pl], v1 = t[sub*4+1][pl], v2 = t[sub*4+2][pl], v3 = t[sub*4+3][pl];
        __half h0 = __float2half_rn(v0), h1 = __float2half_rn(v1);
        __half h2 = __float2half_rn(v2), h3 = __float2half_rn(v3);
        uint32_t uh0 = (uint32_t)__half_as_ushort(h0) | ((uint32_t)__half_as_ushort(h1) << 16);
        uint32_t uh1 = (uint32_t)__half_as_ushort(h2) | ((uint32_t)__half_as_ushort(h3) << 16);
        uint2 wh; wh.x = uh0; wh.y = uh1;
        *reinterpret_cast<uint2*>(P.Ph[l] + base) = wh;
        __half l0 = __float2half_rn(v0 - __half2float(h0));
        __half l1 = __float2half_rn(v1 - __half2float(h1));
        __half l2 = __float2half_rn(v2 - __half2float(h2));
        __half l3 = __float2half_rn(v3 - __half2float(h3));
        uint32_t ul0 = (uint32_t)__half_as_ushort(l0) | ((uint32_t)__half_as_ushort(l1) << 16);
        uint32_t ul1 = (uint32_t)__half_as_ushort(l2) | ((uint32_t)__half_as_ushort(l3) << 16);
        uint2 wl; wl.x = ul0; wl.y = ul1;
        *reinterpret_cast<uint2*>(P.Pl[l] + base) = wl;
    }
}

// ================= merged out-act pack with fused upsample cascade =================
struct PackOutParams {
    const float* map[4];
    __half* Ph[4];
    __half* Pl[4];
    int H[4];
    int npb[4];
    int blkBase[5];
};
__global__ void k_pack_out_all(const __grid_constant__ PackOutParams P){
    __shared__ float t[32][33];
    const int bid = blockIdx.x;
    int l = 0;
    if (bid >= P.blkBase[1]) l = 1;
    if (bid >= P.blkBase[2]) l = 2;
    if (bid >= P.blkBase[3]) l = 3;
    const int rel = bid - P.blkBase[l];
    const int npb = P.npb[l];
    const int bxp = rel % npb;
    const int c0  = (rel / npb) * 32;
    const int H = P.H[l], W = H;
    const int Hp = H + 2, Wp = W + 2, Np = 2 * Hp * Wp;
    const int p0 = bxp * 32;

    int px = p0 + threadIdx.x;
    int b = 0, hh = 0, ww = 0; bool inter = false;
    if (px < Np){
        b = px / (Hp * Wp); int r = px % (Hp * Wp); int hp = r / Wp, wp = r % Wp;
        if (hp >= 1 && hp <= H && wp >= 1 && wp <= W){ inter = true; hh = hp - 1; ww = wp - 1; }
    }
    #pragma unroll
    for (int dyy = 0; dyy < 32; dyy += 8){
        int ci = c0 + (int)threadIdx.y + dyy;
        float v = 0.f;
        if (inter){
            for (int k = l; k < 4; k++){
                int Wk = P.H[k];
                int sh = k - l;
                v += P.map[k][((size_t)(b * 256 + ci) * Wk + (hh >> sh)) * Wk + (ww >> sh)];
            }
        }
        t[threadIdx.y + dyy][threadIdx.x] = v;
    }
    __syncthreads();
    int ft = threadIdx.y * 32 + threadIdx.x;
    int pl = ft >> 3, sub = ft & 7;
    int px2 = p0 + pl;
    if (px2 < Np){
        size_t chStride = (size_t)2 * Hp * Wp * 32;
        int gsw = (sub >> 1) ^ ((px2 >> 1) & 3);
        size_t base = (size_t)(c0 >> 5) * chStride + (size_t)px2 * 32 + (gsw << 3) + (sub & 1) * 4;
        float v0 = t[sub*4+0][pl], v1 = t[sub*4+1][pl], v2 = t[sub*4+2][pl], v3 = t[sub*4+3][pl];
        __half h0 = __float2half_rn(v0), h1 = __float2half_rn(v1);
        __half h2 = __float2half_rn(v2), h3 = __float2half_rn(v3);
        uint32_t uh0 = (uint32_t)__half_as_ushort(h0) | ((uint32_t)__half_as_ushort(h1) << 16);
        uint32_t uh1 = (uint32_t)__half_as_ushort(h2) | ((uint32_t)__half_as_ushort(h3) << 16);
        uint2 wh; wh.x = uh0; wh.y = uh1;
        *reinterpret_cast<uint2*>(P.Ph[l] + base) = wh;
        __half l0 = __float2half_rn(v0 - __half2float(h0));
        __half l1 = __float2half_rn(v1 - __half2float(h1));
        __half l2 = __float2half_rn(v2 - __half2float(h2));
        __half l3 = __float2half_rn(v3 - __half2float(h3));
        uint32_t ul0 = (uint32_t)__half_as_ushort(l0) | ((uint32_t)__half_as_ushort(l1) << 16);
        uint32_t ul1 = (uint32_t)__half_as_ushort(l2) | ((uint32_t)__half_as_ushort(l3) << 16);
        uint2 wl; wl.x = ul0; wl.y = ul1;
        *reinterpret_cast<uint2*>(P.Pl[l] + base) = wl;
    }
}

// ================= merged multi-level fp16 implicit-conv GEMM =================
// Chunks >= loBeg get the activation-lo pass; chunks < loBeg are single-pass.
struct GemmParams {
    const __half* A;
    const __half* BhB;
    const __half* BlB;
    float*        out[4];
    const float*  bias[4];
    long aOff[4];
    long bOff[4];
    int  H[4];
    int  lgW[4];
    int  zc[4];
    int  tpz[4];
    int  blkBase[5];
    int  CH;
    int  loBeg;
};

__global__ __launch_bounds__(256)
void k_gemm(const __grid_constant__ GemmParams P)
{
    extern __shared__ char dsm[];
    __shared__ __align__(8) unsigned long long mb[6];

    const int bid = blockIdx.x;
    int l = 0;
    if (bid >= P.blkBase[1]) l = 1;
    if (bid >= P.blkBase[2]) l = 2;
    if (bid >= P.blkBase[3]) l = 3;
    const int rel = bid - P.blkBase[l];
    const int zc = P.zc[l], tapsPerZ = P.tpz[l];
    const int zi = rel % zc;
    const int tt = rel / zc;
    const int m0 = (tt & 1) * 128;
    const int nt = tt >> 1;
    const int H = P.H[l], W = H, lgW = P.lgW[l];
    const __half* A  = P.A   + P.aOff[l];
    const __half* Bh = P.BhB + P.bOff[l];
    const __half* Bl = P.BlB + P.bOff[l];
    float* out = P.out[l];
    const float* bias = P.bias[l];
    const int useAtomic = (zc > 1);
    const int tapBeg = zi * tapsPerZ;
    const int CH = P.CH;
    const int loBeg = P.loBeg;

    const uint32_t smemBase = smem_u32(dsm);
    uint32_t A_OFF[4], B_OFF[2];
    #pragma unroll
    for (int s = 0; s < 4; s++) A_OFF[s] = smemBase + s * 8192u;
    B_OFF[0] = smemBase + 32768u;
    B_OFF[1] = smemBase + 32768u + 66560u;
    const uint32_t MBA = smem_u32(&mb[0]);
    const uint32_t MBB = smem_u32(&mb[4]);

    const int tid = threadIdx.x, wid = tid >> 5, lane = tid & 31;
    const int R = 256 >> lgW;
    const int Hp = H + 2, Wp = W + 2;
    const int tilesPerB = H / R;
    const int b  = nt / tilesPerB;
    const int h0 = (nt % tilesPerB) * R;
    const int q0 = (b * Hp + h0) * Wp;
    const uint32_t Bbytes = (uint32_t)(R + 2) * Wp * 64u;
    const size_t chStride = (size_t)2 * Hp * Wp * 32;

    if (tid == 0){
        #pragma unroll
        for (int i = 0; i < 6; i++) mbar_init(MBA + i * 8, 1);
    }
    __syncthreads();

    const int nA = CH * tapsPerZ;

    auto issueA = [&](int ia){
        int c = ia / tapsPerZ, tap = ia % tapsPerZ;
        const __half* src = A + ((((size_t)c * 9 + (tapBeg + tap)) * 256 + m0) << 5);
        int s = ia & 3;
        mbar_expect(MBA + s * 8, 8192u);
        bulk_cp(A_OFF[s], src, 8192u, MBA + s * 8);
    };
    auto issueB = [&](int c){
        int s = c & 1;
        bool lo = (c >= loBeg);
        mbar_expect(MBB + s * 8, lo ? 2u * Bbytes : Bbytes);
        bulk_cp(B_OFF[s], Bh + (size_t)c * chStride + ((size_t)q0 << 5), Bbytes, MBB + s * 8);
        if (lo)
            bulk_cp(B_OFF[s] + 33280u, Bl + (size_t)c * chStride + ((size_t)q0 << 5), Bbytes, MBB + s * 8);
    };

    const int lr  = lane & 7;
    const int lm8 = ((lane >> 3) & 1) * 8;
    const int lk  = lane >> 4;
    const int wm  = wid & 1;
    const int wn  = wid >> 1;
    const int rowA = wm * 64 + lm8 + lr;
    const int xorA = (lr >> 1) & 3;
    int rB[4], wB[4];
    #pragma unroll
    for (int g = 0; g < 4; g++){
        int n = wn * 64 + g * 16 + lm8 + lr;
        rB[g] = n >> lgW;
        wB[g] = n & (W - 1);
    }

    float acc[4][8][4];
    #pragma unroll
    for (int i = 0; i < 4; i++)
        #pragma unroll
        for (int j = 0; j < 8; j++)
            #pragma unroll
            for (int k = 0; k < 4; k++) acc[i][j][k] = 0.f;

    if (tid == 0){
        issueB(0);
        issueA(0);
        if (nA > 1) issueA(1);
        if (nA > 2) issueA(2);
    }

    for (int it = 0; it < nA; ++it){
        int c = it / tapsPerZ, tap = it % tapsPerZ;
        if (tid == 0){
            if (it + 3 < nA) issueA(it + 3);
            if (tap == 0 && c + 1 < CH) issueB(c + 1);
        }
        mbar_wait(MBA + (it & 3) * 8, (it >> 2) & 1);
        if (tap == 0) mbar_wait(MBB + (c & 1) * 8, (c >> 1) & 1);

        const uint32_t Ab = A_OFF[it & 3];
        const uint32_t Bb = B_OFF[c & 1];
        const int tIdx = tapBeg + tap;
        const int dy = tIdx / 3, dx = tIdx - dy * 3;
        const int nPass = (c >= loBeg) ? 2 : 1;

        uint32_t sAdr[4]; int xorB[4];
        #pragma unroll
        for (int g = 0; g < 4; g++){
            int s = (rB[g] + dy) * Wp + wB[g] + dx;
            sAdr[g] = Bb + (uint32_t)s * 64u;
            xorB[g] = ((q0 + s) >> 1) & 3;
        }

        #pragma unroll
        for (int ks = 0; ks < 2; ks++){
            const int gA = (2 * ks + lk) ^ xorA;
            uint32_t a[4][4];
            #pragma unroll
            for (int ma = 0; ma < 4; ma++)
                ldmx4(a[ma], Ab + (uint32_t)(rowA + ma * 16) * 64u + ((uint32_t)gA << 4));
            for (int pass = 0; pass < nPass; pass++){
                uint32_t bb[4][4];
                #pragma unroll
                for (int g = 0; g < 4; g++){
                    int gB = (2 * ks + lk) ^ xorB[g];
                    ldmx4(bb[g], sAdr[g] + (uint32_t)pass * 33280u + ((uint32_t)gB << 4));
                }
                #pragma unroll
                for (int ma = 0; ma < 4; ma++)
                    #pragma unroll
                    for (int na = 0; na < 8; na++)
                        mma16816(acc[ma][na], a[ma], bb[na >> 1][na & 1], bb[na >> 1][2 + (na & 1)]);
            }
        }
        __syncthreads();
    }

    #pragma unroll
    for (int ma = 0; ma < 4; ma++){
        int co0 = m0 + wm * 64 + ma * 16 + (lane >> 2);
        int co1 = co0 + 8;
        float bv0 = useAtomic ? 0.f : bias[co0];
        float bv1 = useAtomic ? 0.f : bias[co1];
        #pragma unroll
        for (int na = 0; na < 8; na++){
            int n = wn * 64 + na * 8 + (lane & 3) * 2;
            int r = h0 + (n >> lgW);
            int w = n & (W - 1);
            size_t i0 = ((size_t)(b * 256 + co0) * H + r) * W + w;
            size_t i1 = ((size_t)(b * 256 + co1) * H + r) * W + w;
            if (useAtomic){
                atomicAdd(&out[i0],     acc[ma][na][0]);
                atomicAdd(&out[i0 + 1], acc[ma][na][1]);
                atomicAdd(&out[i1],     acc[ma][na][2]);
                atomicAdd(&out[i1 + 1], acc[ma][na][3]);
            } else {
                float2 v0; v0.x = acc[ma][na][0] + bv0; v0.y = acc[ma][na][1] + bv0;
                float2 v1; v1.x = acc[ma][na][2] + bv1; v1.y = acc[ma][na][3] + bv1;
                *reinterpret_cast<float2*>(&out[i0]) = v0;
                *reinterpret_cast<float2*>(&out[i1]) = v1;
            }
        }
    }
}

// ---------------- host orchestration (8 launches total) ----------------
extern "C" void kernel_launch(void* const* d_in, const int* in_sizes, int n_in,
                              void* d_out, int out_size)
{
    const float *x[4]={0,0,0,0}, *rx[4]={0,0,0,0};
    const float *wm[4]={0,0,0,0}, *bm[4]={0,0,0,0}, *wo[4]={0,0,0,0}, *bo[4]={0,0,0,0};
    int wmi = 0, woi = 0, bi = 0;
    for (int i = 0; i < n_in; i++){
        int s = in_sizes[i];
        int lvl = -1;
        if      (s == 2*256*128*128) lvl = 0;
        else if (s == 2*256*64*64)   lvl = 1;
        else if (s == 2*256*32*32)   lvl = 2;
        else if (s == 2*256*16*16)   lvl = 3;
        if (lvl >= 0){
            if (!x[lvl]) x[lvl] = (const float*)d_in[i];
            else         rx[lvl] = (const float*)d_in[i];
        }
        else if (s == 1845504) wm[wmi++] = (const float*)d_in[i];
        else if (s ==  589824) wo[woi++] = (const float*)d_in[i];
        else if (s ==     256){
            if ((bi & 1) == 0) bm[bi >> 1] = (const float*)d_in[i];
            else               bo[bi >> 1] = (const float*)d_in[i];
            bi++;
        }
    }

    float *corrB, *mapB;
    __half *wmh, *woh, *amh, *aml, *aoh, *aol;
    cudaGetSymbolAddress((void**)&corrB, g_corr);
    cudaGetSymbolAddress((void**)&mapB,  g_map);
    cudaGetSymbolAddress((void**)&wmh, g_wm_h);
    cudaGetSymbolAddress((void**)&woh, g_wo_h);
    cudaGetSymbolAddress((void**)&amh, g_am_h); cudaGetSymbolAddress((void**)&aml, g_am_l);
    cudaGetSymbolAddress((void**)&aoh, g_ao_h); cudaGetSymbolAddress((void**)&aol, g_ao_l);

    cudaFuncSetAttribute(k_gemm, cudaFuncAttributeMaxDynamicSharedMemorySize, 165888);
    cudaFuncSetAttribute(k_corr_mma, cudaFuncAttributeMaxDynamicSharedMemorySize, 188416);

    const int  Hl[4]      = {128, 64, 32, 16};
    const int  lgWl[4]    = {7, 6, 5, 4};
    const int  HWl[4]     = {16384, 4096, 1024, 256};
    const long corrOff[4] = {0, 9469952, 11837440, 12429312};
    const long mapOff[4]  = {0, 8388608, 10485760, 11010048};
    const long amOff[4]   = {0, 28121600, 35369984, 37293568};
    const long aoOff[4]   = {0, 8652800, 10883072, 11474944};
    const long wmOff[4]   = {0, 1916928, 3833856, 5750784};
    const long woOff[4]   = {0, 589824, 1179648, 1769472};
    const int  zl[4]      = {1, 3, 9, 9};
    const int  tpzl[4]    = {9, 3, 1, 1};
    float* outp = (float*)d_out;

    int gemmBase[5]; gemmBase[0] = 0;
    for (int l = 0; l < 4; l++)
        gemmBase[l + 1] = gemmBase[l] + (2 * HWl[l] / 256) * 2 * zl[l];  // {0,256,448,592,628}

    int npbl[4];
    for (int l = 0; l < 4; l++){
        int Np = 2 * (Hl[l] + 2) * (Hl[l] + 2);
        npbl[l] = (Np + 31) / 32;
    }

    // ---- launch 0: init all atomic output buffers (map+out, levels 1-3) ----
    {
        InitParams P;
        long tot = 0;
        for (int r = 0; r < 3; r++){
            int l = r + 1;
            P.out[r] = mapB + mapOff[l]; P.bias[r] = bm[l]; P.HW[r] = HWl[l];
            P.base[r] = tot; tot += 2L * 256 * HWl[l];
        }
        for (int r = 0; r < 3; r++){
            int l = r + 1;
            P.out[3 + r] = outp + mapOff[l]; P.bias[3 + r] = bo[l]; P.HW[3 + r] = HWl[l];
            P.base[3 + r] = tot; tot += 2L * 256 * HWl[l];
        }
        P.base[6] = tot;
        k_init_all<<<(int)((tot + 255) / 256), 256>>>(P);
    }
    // ---- launch 1: pack all weights ----
    {
        PackWParams P;
        long tot = 0;
        for (int l = 0; l < 4; l++){
            P.src[l] = wm[l]; P.dst[l] = wmh + wmOff[l]; P.Cin[l] = 801; P.Cpad[l] = 832;
            P.base[l] = tot; tot += 256L * 832;
        }
        for (int l = 0; l < 4; l++){
            P.src[4+l] = wo[l]; P.dst[4+l] = woh + woOff[l]; P.Cin[4+l] = 256; P.Cpad[4+l] = 256;
            P.base[4+l] = tot; tot += 256L * 256;
        }
        P.base[8] = tot;
        k_pack_w_all<<<(int)((tot + 255) / 256), 256>>>(P);
    }
    // ---- launch 2: pack x/rx activation chunks (0-15) ----
    {
        PackMapParams P;
        int base = 0;
        for (int l = 0; l < 4; l++){
            P.x[l] = x[l]; P.rx[l] = rx[l]; P.corr[l] = corrB + corrOff[l];
            P.Ph[l] = amh + amOff[l]; P.Pl[l] = aml + amOff[l];
            P.H[l] = Hl[l]; P.npb[l] = npbl[l];
            P.blkBase[l] = base;
            base += npbl[l] * 16;
        }
        P.blkBase[4] = base;
        P.cBeg = 0;
        k_pack_map_all<<<base, dim3(32, 8)>>>(P);
    }
    // ---- launch 3: MMA correlation ----
    {
        CorrMMAParams P;
        int base = 0;
        for (int l = 0; l < 4; l++){
            P.Xh[l] = amh + amOff[l];
            P.Xl[l] = aml + amOff[l];
            P.out[l] = corrB + corrOff[l];
            P.H[l] = Hl[l];
            P.chS[l] = 2L * (Hl[l] + 2) * (Hl[l] + 2) * 32;
            P.blkBase[l] = base;
            int RPB = 128 / Hl[l];
            base += 2 * Hl[l] / RPB;
        }
        P.blkBase[4] = base;
        k_corr_mma<<<base, 256, 188416>>>(P);
    }
    // ---- launch 4: pack corr activation chunks (16-25) ----
    {
        PackMapParams P;
        int base = 0;
        for (int l = 0; l < 4; l++){
            P.x[l] = x[l]; P.rx[l] = rx[l]; P.corr[l] = corrB + corrOff[l];
            P.Ph[l] = amh + amOff[l]; P.Pl[l] = aml + amOff[l];
            P.H[l] = Hl[l]; P.npb[l] = npbl[l];
            P.blkBase[l] = base;
            base += npbl[l] * 10;
        }
        P.blkBase[4] = base;
        P.cBeg = 16;
        k_pack_map_all<<<base, dim3(32, 8)>>>(P);
    }
    // ---- launch 5: merged map GEMM (single-pass x/rx chunks, 2-pass corr chunks) ----
    {
        GemmParams P;
        P.A = wmh; P.BhB = amh; P.BlB = aml;
        for (int l = 0; l < 4; l++){
            P.out[l] = mapB + mapOff[l]; P.bias[l] = bm[l];
            P.aOff[l] = wmOff[l]; P.bOff[l] = amOff[l];
            P.H[l] = Hl[l]; P.lgW[l] = lgWl[l]; P.zc[l] = zl[l]; P.tpz[l] = tpzl[l];
        }
        for (int i = 0; i < 5; i++) P.blkBase[i] = gemmBase[i];
        P.CH = 26;
        P.loBeg = 16;
        k_gemm<<<gemmBase[4], 256, 165888>>>(P);
    }
    // ---- launch 6: pack out activations with fused upsample cascade ----
    {
        PackOutParams P;
        int base = 0;
        for (int l = 0; l < 4; l++){
            P.map[l] = mapB + mapOff[l];
            P.Ph[l] = aoh + aoOff[l]; P.Pl[l] = aol + aoOff[l];
            P.H[l] = Hl[l]; P.npb[l] = npbl[l];
            P.blkBase[l] = base;
            base += npbl[l] * 8;
        }
        P.blkBase[4] = base;
        k_pack_out_all<<<base, dim3(32, 8)>>>(P);
    }
    // ---- launch 7: merged out GEMM -> d_out (2-pass everywhere) ----
    {
        GemmParams P;
        P.A = woh; P.BhB = aoh; P.BlB = aol;
        for (int l = 0; l < 4; l++){
            P.out[l] = outp + mapOff[l]; P.bias[l] = bo[l];
            P.aOff[l] = woOff[l]; P.bOff[l] = aoOff[l];
            P.H[l] = Hl[l]; P.lgW[l] = lgWl[l]; P.zc[l] = zl[l]; P.tpz[l] = tpzl[l];
        }
        for (int i = 0; i < 5; i++) P.blkBase[i] = gemmBase[i];
        P.CH = 8;
        P.loBeg = 0;
        k_gemm<<<gemmBase[4], 256, 165888>>>(P);
    }
}

// round 13
// speedup vs baseline: 1.8777x; 1.0761x over previous
#include <cuda_runtime.h>
#include <cuda_fp16.h>
#include <cstdint>
#include <cstddef>

#define PADC 8

// ---------------- static device buffers ----------------
__device__ __align__(256) float g_corr[12577280];
__device__ __align__(256) float g_map [11141120];
__device__ __align__(256) __half g_wm_h[7667712];   // [lvl][chunk26][tap9][co256][ci32] swizzled
__device__ __align__(256) __half g_wo_h[2359296];   // [lvl][chunk8][tap9][co256][ci32]
__device__ __align__(256) __half g_am_h[37832704];  // [lvl][chunk][b][Hp][Wp][32] swizzled
__device__ __align__(256) __half g_am_l[37832704];
__device__ __align__(256) __half g_ao_h[11640832];
__device__ __align__(256) __half g_ao_l[11640832];

// ---------------- PTX helpers (compute_103 baseline-safe) ----------------
__device__ __forceinline__ uint32_t smem_u32(const void* p){
    uint32_t a;
    asm("{ .reg .u64 t; cvta.to.shared.u64 t, %1; cvt.u32.u64 %0, t; }" : "=r"(a) : "l"(p));
    return a;
}
__device__ __forceinline__ void mbar_init(uint32_t a, uint32_t cnt){
    asm volatile("mbarrier.init.shared.b64 [%0], %1;" :: "r"(a), "r"(cnt) : "memory");
}
__device__ __forceinline__ void mbar_expect(uint32_t a, uint32_t bytes){
    asm volatile("mbarrier.arrive.expect_tx.shared.b64 _, [%0], %1;" :: "r"(a), "r"(bytes) : "memory");
}
__device__ __forceinline__ void mbar_wait(uint32_t a, int parity){
    asm volatile(
        "{\n\t.reg .pred P;\n\t"
        "WL_%=:\n\t"
        "mbarrier.try_wait.parity.acquire.cta.shared::cta.b64 P, [%0], %1, 0x989680;\n\t"
        "@P bra WD_%=;\n\t"
        "bra WL_%=;\n\t"
        "WD_%=:\n\t}"
        :: "r"(a), "r"(parity) : "memory");
}
__device__ __forceinline__ void bulk_cp(uint32_t dst, const void* src, uint32_t bytes, uint32_t mbar){
    asm volatile(
        "cp.async.bulk.shared::cluster.global.mbarrier::complete_tx::bytes [%0], [%1], %2, [%3];"
        :: "r"(dst), "l"(src), "r"(bytes), "r"(mbar) : "memory");
}
__device__ __forceinline__ void ldmx4(uint32_t* r, uint32_t addr){
    asm volatile("ldmatrix.sync.aligned.m8n8.x4.shared.b16 {%0,%1,%2,%3}, [%4];"
                 : "=r"(r[0]), "=r"(r[1]), "=r"(r[2]), "=r"(r[3]) : "r"(addr));
}
__device__ __forceinline__ void mma16816(float* c, const uint32_t* a, uint32_t b0, uint32_t b1){
    asm volatile(
        "mma.sync.aligned.m16n8k16.row.col.f32.f16.f16.f32 "
        "{%0,%1,%2,%3}, {%4,%5,%6,%7}, {%8,%9}, {%0,%1,%2,%3};"
        : "+f"(c[0]), "+f"(c[1]), "+f"(c[2]), "+f"(c[3])
        : "r"(a[0]), "r"(a[1]), "r"(a[2]), "r"(a[3]), "r"(b0), "r"(b1));
}

// ================= merged init bias (6 regions) =================
struct InitParams {
    float* out[6];
    const float* bias[6];
    int HW[6];
    long base[7];
};
__global__ void k_init_all(const __grid_constant__ InitParams P){
    long i = (long)blockIdx.x * blockDim.x + threadIdx.x;
    if (i >= P.base[6]) return;
    int r = 0;
    #pragma unroll
    for (int k = 1; k < 6; k++) if (i >= P.base[k]) r = k;
    long loc = i - P.base[r];
    P.out[r][loc] = P.bias[r][(loc / P.HW[r]) & 255];
}

// ================= merged weight pack (8 tensors) =================
struct PackWParams {
    const float* src[8];
    __half* dst[8];
    int Cin[8];
    int Cpad[8];
    long base[9];
};
__global__ void k_pack_w_all(const __grid_constant__ PackWParams P){
    long i = (long)blockIdx.x * 256 + threadIdx.x;
    if (i >= P.base[8]) return;
    int t = 0;
    #pragma unroll
    for (int k = 1; k < 8; k++) if (i >= P.base[k]) t = k;
    long loc = i - P.base[t];
    int Cpad = P.Cpad[t], Cin = P.Cin[t];
    int co = (int)(loc / Cpad), ci = (int)(loc % Cpad);
    int c = ci >> 5, cl = ci & 31;
    int gsw = (cl >> 3) ^ ((co >> 1) & 3);
    const float* w = P.src[t];
    __half* oh = P.dst[t];
    #pragma unroll
    for (int tap = 0; tap < 9; tap++){
        float v = (ci < Cin) ? w[(size_t)(co * Cin + ci) * 9 + tap] : 0.f;
        size_t o = (((size_t)c * 9 + tap) * 256 + co) * 32 + (gsw << 3) + (cl & 7);
        oh[o] = __float2half_rn(v);
    }
}

// ================= MMA correlation: corr[w,dj] = band of X^T R =================
struct CorrMMAParams {
    const __half* Xh[4];
    const __half* Xl[4];
    float* out[4];
    int H[4];
    long chS[4];
    int blkBase[5];
};
__global__ __launch_bounds__(256)
void k_corr_mma(const __grid_constant__ CorrMMAParams P)
{
    extern __shared__ char dsm[];
    __shared__ __align__(8) unsigned long long mb[3];

    const int bid = blockIdx.x;
    int l = 0;
    if (bid >= P.blkBase[1]) l = 1;
    if (bid >= P.blkBase[2]) l = 2;
    if (bid >= P.blkBase[3]) l = 3;
    const int rel = bid - P.blkBase[l];
    const int H = P.H[l], W = H, Hp = H + 2, Wp = W + 2;
    const int WT = W >> 4;
    const int RPB = 8 / WT;
    const int HB = H / RPB;
    const int b  = rel / HB;
    const int h0 = (rel % HB) * RPB;
    const long chS = P.chS[l];
    const __half* Xh = P.Xh[l];
    const __half* Xl = P.Xl[l];
    float* corr = P.out[l];

    const uint32_t sb = smem_u32(dsm);
    const uint32_t BB = sb + 147456u;
    const uint32_t MBA = smem_u32(&mb[0]);
    const uint32_t MBB = smem_u32(&mb[1]);

    const int tid = threadIdx.x, wid = tid >> 5, lane = tid & 31;
    const int wt = wid % WT, hl = wid / WT;
    const int w0 = wt * 16;
    const int lr = lane & 7, lm8 = ((lane >> 3) & 1) * 8, lk = lane >> 4;

    if (tid == 0){
        mbar_init(MBA, 1);
        mbar_init(MBB, 1);
        mbar_init(MBB + 8, 1);
    }
    __syncthreads();

    const long pA0 = (long)(b * Hp + h0 + 1) * Wp + 1;
    const uint32_t Abytes = (uint32_t)(((RPB - 1) * Wp + W) * 64);

    if (tid == 0){
        mbar_expect(MBA, 16u * Abytes);
        #pragma unroll
        for (int q = 0; q < 8; q++){
            bulk_cp(sb + (q * 2 + 0) * 9216u, Xh + (size_t)q * chS + pA0 * 32, Abytes, MBA);
            bulk_cp(sb + (q * 2 + 1) * 9216u, Xl + (size_t)q * chS + pA0 * 32, Abytes, MBA);
        }
    }

    auto issueB = [&](int s){
        int dy = s >> 3, q = s & 7;
        int r0 = h0 + dy - 8;
        int rc0 = (r0 < -1) ? -1 : r0;
        int rc1 = r0 + RPB - 1; if (rc1 > H) rc1 = H;
        if (rc1 < rc0){ rc0 = h0; rc1 = h0; }
        long pB0 = (long)(b * Hp + rc0 + 1) * Wp - 7;
        uint32_t Bb = (uint32_t)(((rc1 - rc0) * Wp + W + 16) * 64);
        int buf = s & 1;
        mbar_expect(MBB + buf * 8, 2u * Bb);
        bulk_cp(BB + buf * 20480u,           Xh + (size_t)(8 + q) * chS + pB0 * 32, Bb, MBB + buf * 8);
        bulk_cp(BB + buf * 20480u + 10240u,  Xl + (size_t)(8 + q) * chS + pB0 * 32, Bb, MBB + buf * 8);
    };

    if (tid == 0) issueB(0);
    mbar_wait(MBA, 0);

    const int offA_px = hl * Wp + w0 + lm8 + lr;
    const int xorA = (int)(((pA0 + offA_px) >> 1) & 3);
    const uint32_t aOff = (uint32_t)offA_px * 64u;

    float acc[4][4];
    const int nStages = 17 * 8;

    for (int s = 0; s < nStages; ++s){
        const int dy = s >> 3, q = s & 7;
        if (tid == 0 && s + 1 < nStages) issueB(s + 1);
        mbar_wait(MBB + (s & 1) * 8, (s >> 1) & 1);

        if (q == 0){
            #pragma unroll
            for (int f = 0; f < 4; f++)
                #pragma unroll
                for (int e = 0; e < 4; e++) acc[f][e] = 0.f;
        }

        int r0 = h0 + dy - 8;
        int rc0 = (r0 < -1) ? -1 : r0;
        int rc1 = r0 + RPB - 1; if (rc1 > H) rc1 = H;
        if (rc1 < rc0){ rc0 = h0; rc1 = h0; }
        const int r = h0 + hl + dy - 8;
        const bool valid = (r >= rc0 && r <= rc1);

        if (valid){
            const long pB0 = (long)(b * Hp + rc0 + 1) * Wp - 7;
            const int rowBase = (r - rc0) * Wp;
            const int offB0 = rowBase + w0 + lm8 + lr;
            const int offB1 = offB0 + 16;
            const int xb0 = (int)(((pB0 + offB0) >> 1) & 3);
            const int xb1 = (int)(((pB0 + offB1) >> 1) & 3);
            const uint32_t Bh0 = BB + (s & 1) * 20480u;
            const uint32_t Bl0 = Bh0 + 10240u;
            const uint32_t Ah0 = sb + (q * 2 + 0) * 9216u;
            const uint32_t Al0 = sb + (q * 2 + 1) * 9216u;

            #pragma unroll
            for (int ks = 0; ks < 2; ks++){
                const int g = 2 * ks + lk;
                uint32_t ah[4], al[4], bh[2][4], bl[2][4];
                ldmx4(ah, Ah0 + aOff + ((uint32_t)(g ^ xorA) << 4));
                ldmx4(al, Al0 + aOff + ((uint32_t)(g ^ xorA) << 4));
                ldmx4(bh[0], Bh0 + (uint32_t)offB0 * 64u + ((uint32_t)(g ^ xb0) << 4));
                ldmx4(bh[1], Bh0 + (uint32_t)offB1 * 64u + ((uint32_t)(g ^ xb1) << 4));
                ldmx4(bl[0], Bl0 + (uint32_t)offB0 * 64u + ((uint32_t)(g ^ xb0) << 4));
                ldmx4(bl[1], Bl0 + (uint32_t)offB1 * 64u + ((uint32_t)(g ^ xb1) << 4));
                #pragma unroll
                for (int nf = 0; nf < 2; nf++)
                    #pragma unroll
                    for (int sub = 0; sub < 2; sub++){
                        const int f = nf * 2 + sub;
                        mma16816(acc[f], ah, bh[nf][sub], bh[nf][2 + sub]);
                        mma16816(acc[f], al, bh[nf][sub], bh[nf][2 + sub]);
                        mma16816(acc[f], ah, bl[nf][sub], bl[nf][2 + sub]);
                    }
            }
        }

        if (q == 7){
            const int h = h0 + hl;
            #pragma unroll
            for (int f = 0; f < 4; f++){
                const int nf = f >> 1, sub = f & 1;
                const int nb = nf * 16 + sub * 8 + (lane & 3) * 2;
                #pragma unroll
                for (int e = 0; e < 2; e++){
                    const int n = nb + e;
                    #pragma unroll
                    for (int mh = 0; mh < 2; mh++){
                        const int m = (lane >> 2) + mh * 8;
                        const int w = w0 + m;
                        const int dj = n - m;
                        const int u = w0 - 8 + n;
                        if (dj >= 0 && dj <= 16){
                            float o = (valid && u >= 0 && u < W) ? acc[f][mh * 2 + e] : 0.f;
                            corr[(((long)b * 289 + dy * 17 + dj) * H + h) * W + w] = o;
                        }
                    }
                }
            }
        }
        __syncthreads();
    }
}

// ================= merged map-act pack (chunk-range, optional lo plane) =================
struct PackMapParams {
    const float* x[4];
    const float* rx[4];
    const float* corr[4];
    __half* Ph[4];
    __half* Pl[4];
    int H[4];
    int npb[4];
    int blkBase[5];
    int cBeg;
    int writeLo;
};
__global__ void k_pack_map_all(const __grid_constant__ PackMapParams P){
    __shared__ float t[32][33];
    const int bid = blockIdx.x;
    int l = 0;
    if (bid >= P.blkBase[1]) l = 1;
    if (bid >= P.blkBase[2]) l = 2;
    if (bid >= P.blkBase[3]) l = 3;
    const int rel = bid - P.blkBase[l];
    const int npb = P.npb[l];
    const int bxp = rel % npb;
    const int c0  = (P.cBeg + rel / npb) * 32;
    const int H = P.H[l], W = H;
    const int Hp = H + 2, Wp = W + 2, HW = H * W, Np = 2 * Hp * Wp;
    const int p0 = bxp * 32;

    int px = p0 + threadIdx.x;
    int b = 0, pix = 0; bool inter = false;
    if (px < Np){
        b = px / (Hp * Wp); int r = px % (Hp * Wp); int hp = r / Wp, wp = r % Wp;
        if (hp >= 1 && hp <= H && wp >= 1 && wp <= W){ inter = true; pix = (hp - 1) * W + (wp - 1); }
    }
    const float* X  = P.x[l];
    const float* RX = P.rx[l];
    const float* CR = P.corr[l];
    #pragma unroll
    for (int dyy = 0; dyy < 32; dyy += 8){
        int ci = c0 + (int)threadIdx.y + dyy;
        float v = 0.f;
        if (inter){
            if (ci < 256)       v = X [(size_t)(b * 256 + ci) * HW + pix];
            else if (ci < 512)  v = RX[(size_t)(b * 256 + ci - 256) * HW + pix];
            else if (ci < 801)  v = CR[(size_t)(b * 289 + ci - 512) * HW + pix];
        }
        t[threadIdx.y + dyy][threadIdx.x] = v;
    }
    __syncthreads();
    int ft = threadIdx.y * 32 + threadIdx.x;
    int pl = ft >> 3, sub = ft & 7;
    int px2 = p0 + pl;
    if (px2 < Np){
        size_t chStride = (size_t)2 * Hp * Wp * 32;
        int gsw = (sub >> 1) ^ ((px2 >> 1) & 3);
        size_t base = (size_t)(c0 >> 5) * chStride + (size_t)px2 * 32 + (gsw << 3) + (sub & 1) * 4;
        float v0 = t[sub*4+0][pl], v1 = t[sub*4+1][pl], v2 = t[sub*4+2][pl], v3 = t[sub*4+3][pl];
        __half h0 = __float2half_rn(v0), h1 = __float2half_rn(v1);
        __half h2 = __float2half_rn(v2), h3 = __float2half_rn(v3);
        uint32_t uh0 = (uint32_t)__half_as_ushort(h0) | ((uint32_t)__half_as_ushort(h1) << 16);
        uint32_t uh1 = (uint32_t)__half_as_ushort(h2) | ((uint32_t)__half_as_ushort(h3) << 16);
        uint2 wh; wh.x = uh0; wh.y = uh1;
        *reinterpret_cast<uint2*>(P.Ph[l] + base) = wh;
        if (P.writeLo){
            __half l0 = __float2half_rn(v0 - __half2float(h0));
            __half l1 = __float2half_rn(v1 - __half2float(h1));
            __half l2 = __float2half_rn(v2 - __half2float(h2));
            __half l3 = __float2half_rn(v3 - __half2float(h3));
            uint32_t ul0 = (uint32_t)__half_as_ushort(l0) | ((uint32_t)__half_as_ushort(l1) << 16);
            uint32_t ul1 = (uint32_t)__half_as_ushort(l2) | ((uint32_t)__half_as_ushort(l3) << 16);
            uint2 wl; wl.x = ul0; wl.y = ul1;
            *reinterpret_cast<uint2*>(P.Pl[l] + base) = wl;
        }
    }
}

// ================= merged out-act pack with fused upsample cascade (hi only) =================
struct PackOutParams {
    const float* map[4];
    __half* Ph[4];
    int H[4];
    int npb[4];
    int blkBase[5];
};
__global__ void k_pack_out_all(const __grid_constant__ PackOutParams P){
    __shared__ float t[32][33];
    const int bid = blockIdx.x;
    int l = 0;
    if (bid >= P.blkBase[1]) l = 1;
    if (bid >= P.blkBase[2]) l = 2;
    if (bid >= P.blkBase[3]) l = 3;
    const int rel = bid - P.blkBase[l];
    const int npb = P.npb[l];
    const int bxp = rel % npb;
    const int c0  = (rel / npb) * 32;
    const int H = P.H[l], W = H;
    const int Hp = H + 2, Wp = W + 2, Np = 2 * Hp * Wp;
    const int p0 = bxp * 32;

    int px = p0 + threadIdx.x;
    int b = 0, hh = 0, ww = 0; bool inter = false;
    if (px < Np){
        b = px / (Hp * Wp); int r = px % (Hp * Wp); int hp = r / Wp, wp = r % Wp;
        if (hp >= 1 && hp <= H && wp >= 1 && wp <= W){ inter = true; hh = hp - 1; ww = wp - 1; }
    }
    #pragma unroll
    for (int dyy = 0; dyy < 32; dyy += 8){
        int ci = c0 + (int)threadIdx.y + dyy;
        float v = 0.f;
        if (inter){
            for (int k = l; k < 4; k++){
                int Wk = P.H[k];
                int sh = k - l;
                v += P.map[k][((size_t)(b * 256 + ci) * Wk + (hh >> sh)) * Wk + (ww >> sh)];
            }
        }
        t[threadIdx.y + dyy][threadIdx.x] = v;
    }
    __syncthreads();
    int ft = threadIdx.y * 32 + threadIdx.x;
    int pl = ft >> 3, sub = ft & 7;
    int px2 = p0 + pl;
    if (px2 < Np){
        size_t chStride = (size_t)2 * Hp * Wp * 32;
        int gsw = (sub >> 1) ^ ((px2 >> 1) & 3);
        size_t base = (size_t)(c0 >> 5) * chStride + (size_t)px2 * 32 + (gsw << 3) + (sub & 1) * 4;
        float v0 = t[sub*4+0][pl], v1 = t[sub*4+1][pl], v2 = t[sub*4+2][pl], v3 = t[sub*4+3][pl];
        __half h0 = __float2half_rn(v0), h1 = __float2half_rn(v1);
        __half h2 = __float2half_rn(v2), h3 = __float2half_rn(v3);
        uint32_t uh0 = (uint32_t)__half_as_ushort(h0) | ((uint32_t)__half_as_ushort(h1) << 16);
        uint32_t uh1 = (uint32_t)__half_as_ushort(h2) | ((uint32_t)__half_as_ushort(h3) << 16);
        uint2 wh; wh.x = uh0; wh.y = uh1;
        *reinterpret_cast<uint2*>(P.Ph[l] + base) = wh;
    }
}

// ================= merged multi-level fp16 implicit-conv GEMM =================
// Chunks >= loBeg get the activation-lo pass; chunks < loBeg are single-pass.
struct GemmParams {
    const __half* A;
    const __half* BhB;
    const __half* BlB;
    float*        out[4];
    const float*  bias[4];
    long aOff[4];
    long bOff[4];
    int  H[4];
    int  lgW[4];
    int  zc[4];
    int  tpz[4];
    int  blkBase[5];
    int  CH;
    int  loBeg;
};

__global__ __launch_bounds__(256)
void k_gemm(const __grid_constant__ GemmParams P)
{
    extern __shared__ char dsm[];
    __shared__ __align__(8) unsigned long long mb[6];

    const int bid = blockIdx.x;
    int l = 0;
    if (bid >= P.blkBase[1]) l = 1;
    if (bid >= P.blkBase[2]) l = 2;
    if (bid >= P.blkBase[3]) l = 3;
    const int rel = bid - P.blkBase[l];
    const int zc = P.zc[l], tapsPerZ = P.tpz[l];
    const int zi = rel % zc;
    const int tt = rel / zc;
    const int m0 = (tt & 1) * 128;
    const int nt = tt >> 1;
    const int H = P.H[l], W = H, lgW = P.lgW[l];
    const __half* A  = P.A   + P.aOff[l];
    const __half* Bh = P.BhB + P.bOff[l];
    const __half* Bl = P.BlB + P.bOff[l];
    float* out = P.out[l];
    const float* bias = P.bias[l];
    const int useAtomic = (zc > 1);
    const int tapBeg = zi * tapsPerZ;
    const int CH = P.CH;
    const int loBeg = P.loBeg;

    const uint32_t smemBase = smem_u32(dsm);
    uint32_t A_OFF[4], B_OFF[2];
    #pragma unroll
    for (int s = 0; s < 4; s++) A_OFF[s] = smemBase + s * 8192u;
    B_OFF[0] = smemBase + 32768u;
    B_OFF[1] = smemBase + 32768u + 66560u;
    const uint32_t MBA = smem_u32(&mb[0]);
    const uint32_t MBB = smem_u32(&mb[4]);

    const int tid = threadIdx.x, wid = tid >> 5, lane = tid & 31;
    const int R = 256 >> lgW;
    const int Hp = H + 2, Wp = W + 2;
    const int tilesPerB = H / R;
    const int b  = nt / tilesPerB;
    const int h0 = (nt % tilesPerB) * R;
    const int q0 = (b * Hp + h0) * Wp;
    const uint32_t Bbytes = (uint32_t)(R + 2) * Wp * 64u;
    const size_t chStride = (size_t)2 * Hp * Wp * 32;

    if (tid == 0){
        #pragma unroll
        for (int i = 0; i < 6; i++) mbar_init(MBA + i * 8, 1);
    }
    __syncthreads();

    const int nA = CH * tapsPerZ;

    auto issueA = [&](int ia){
        int c = ia / tapsPerZ, tap = ia % tapsPerZ;
        const __half* src = A + ((((size_t)c * 9 + (tapBeg + tap)) * 256 + m0) << 5);
        int s = ia & 3;
        mbar_expect(MBA + s * 8, 8192u);
        bulk_cp(A_OFF[s], src, 8192u, MBA + s * 8);
    };
    auto issueB = [&](int c){
        int s = c & 1;
        bool lo = (c >= loBeg);
        mbar_expect(MBB + s * 8, lo ? 2u * Bbytes : Bbytes);
        bulk_cp(B_OFF[s], Bh + (size_t)c * chStride + ((size_t)q0 << 5), Bbytes, MBB + s * 8);
        if (lo)
            bulk_cp(B_OFF[s] + 33280u, Bl + (size_t)c * chStride + ((size_t)q0 << 5), Bbytes, MBB + s * 8);
    };

    const int lr  = lane & 7;
    const int lm8 = ((lane >> 3) & 1) * 8;
    const int lk  = lane >> 4;
    const int wm  = wid & 1;
    const int wn  = wid >> 1;
    const int rowA = wm * 64 + lm8 + lr;
    const int xorA = (lr >> 1) & 3;
    int rB[4], wB[4];
    #pragma unroll
    for (int g = 0; g < 4; g++){
        int n = wn * 64 + g * 16 + lm8 + lr;
        rB[g] = n >> lgW;
        wB[g] = n & (W - 1);
    }

    float acc[4][8][4];
    #pragma unroll
    for (int i = 0; i < 4; i++)
        #pragma unroll
        for (int j = 0; j < 8; j++)
            #pragma unroll
            for (int k = 0; k < 4; k++) acc[i][j][k] = 0.f;

    if (tid == 0){
        issueB(0);
        issueA(0);
        if (nA > 1) issueA(1);
        if (nA > 2) issueA(2);
    }

    for (int it = 0; it < nA; ++it){
        int c = it / tapsPerZ, tap = it % tapsPerZ;
        if (tid == 0){
            if (it + 3 < nA) issueA(it + 3);
            if (tap == 0 && c + 1 < CH) issueB(c + 1);
        }
        mbar_wait(MBA + (it & 3) * 8, (it >> 2) & 1);
        if (tap == 0) mbar_wait(MBB + (c & 1) * 8, (c >> 1) & 1);

        const uint32_t Ab = A_OFF[it & 3];
        const uint32_t Bb = B_OFF[c & 1];
        const int tIdx = tapBeg + tap;
        const int dy = tIdx / 3, dx = tIdx - dy * 3;
        const int nPass = (c >= loBeg) ? 2 : 1;

        uint32_t sAdr[4]; int xorB[4];
        #pragma unroll
        for (int g = 0; g < 4; g++){
            int s = (rB[g] + dy) * Wp + wB[g] + dx;
            sAdr[g] = Bb + (uint32_t)s * 64u;
            xorB[g] = ((q0 + s) >> 1) & 3;
        }

        #pragma unroll
        for (int ks = 0; ks < 2; ks++){
            const int gA = (2 * ks + lk) ^ xorA;
            uint32_t a[4][4];
            #pragma unroll
            for (int ma = 0; ma < 4; ma++)
                ldmx4(a[ma], Ab + (uint32_t)(rowA + ma * 16) * 64u + ((uint32_t)gA << 4));
            for (int pass = 0; pass < nPass; pass++){
                uint32_t bb[4][4];
                #pragma unroll
                for (int g = 0; g < 4; g++){
                    int gB = (2 * ks + lk) ^ xorB[g];
                    ldmx4(bb[g], sAdr[g] + (uint32_t)pass * 33280u + ((uint32_t)gB << 4));
                }
                #pragma unroll
                for (int ma = 0; ma < 4; ma++)
                    #pragma unroll
                    for (int na = 0; na < 8; na++)
                        mma16816(acc[ma][na], a[ma], bb[na >> 1][na & 1], bb[na >> 1][2 + (na & 1)]);
            }
        }
        __syncthreads();
    }

    #pragma unroll
    for (int ma = 0; ma < 4; ma++){
        int co0 = m0 + wm * 64 + ma * 16 + (lane >> 2);
        int co1 = co0 + 8;
        float bv0 = useAtomic ? 0.f : bias[co0];
        float bv1 = useAtomic ? 0.f : bias[co1];
        #pragma unroll
        for (int na = 0; na < 8; na++){
            int n = wn * 64 + na * 8 + (lane & 3) * 2;
            int r = h0 + (n >> lgW);
            int w = n & (W - 1);
            size_t i0 = ((size_t)(b * 256 + co0) * H + r) * W + w;
            size_t i1 = ((size_t)(b * 256 + co1) * H + r) * W + w;
            if (useAtomic){
                atomicAdd(&out[i0],     acc[ma][na][0]);
                atomicAdd(&out[i0 + 1], acc[ma][na][1]);
                atomicAdd(&out[i1],     acc[ma][na][2]);
                atomicAdd(&out[i1 + 1], acc[ma][na][3]);
            } else {
                float2 v0; v0.x = acc[ma][na][0] + bv0; v0.y = acc[ma][na][1] + bv0;
                float2 v1; v1.x = acc[ma][na][2] + bv1; v1.y = acc[ma][na][3] + bv1;
                *reinterpret_cast<float2*>(&out[i0]) = v0;
                *reinterpret_cast<float2*>(&out[i1]) = v1;
            }
        }
    }
}

// ---------------- host orchestration (8 launches total) ----------------
extern "C" void kernel_launch(void* const* d_in, const int* in_sizes, int n_in,
                              void* d_out, int out_size)
{
    const float *x[4]={0,0,0,0}, *rx[4]={0,0,0,0};
    const float *wm[4]={0,0,0,0}, *bm[4]={0,0,0,0}, *wo[4]={0,0,0,0}, *bo[4]={0,0,0,0};
    int wmi = 0, woi = 0, bi = 0;
    for (int i = 0; i < n_in; i++){
        int s = in_sizes[i];
        int lvl = -1;
        if      (s == 2*256*128*128) lvl = 0;
        else if (s == 2*256*64*64)   lvl = 1;
        else if (s == 2*256*32*32)   lvl = 2;
        else if (s == 2*256*16*16)   lvl = 3;
        if (lvl >= 0){
            if (!x[lvl]) x[lvl] = (const float*)d_in[i];
            else         rx[lvl] = (const float*)d_in[i];
        }
        else if (s == 1845504) wm[wmi++] = (const float*)d_in[i];
        else if (s ==  589824) wo[woi++] = (const float*)d_in[i];
        else if (s ==     256){
            if ((bi & 1) == 0) bm[bi >> 1] = (const float*)d_in[i];
            else               bo[bi >> 1] = (const float*)d_in[i];
            bi++;
        }
    }

    float *corrB, *mapB;
    __half *wmh, *woh, *amh, *aml, *aoh, *aol;
    cudaGetSymbolAddress((void**)&corrB, g_corr);
    cudaGetSymbolAddress((void**)&mapB,  g_map);
    cudaGetSymbolAddress((void**)&wmh, g_wm_h);
    cudaGetSymbolAddress((void**)&woh, g_wo_h);
    cudaGetSymbolAddress((void**)&amh, g_am_h); cudaGetSymbolAddress((void**)&aml, g_am_l);
    cudaGetSymbolAddress((void**)&aoh, g_ao_h); cudaGetSymbolAddress((void**)&aol, g_ao_l);

    cudaFuncSetAttribute(k_gemm, cudaFuncAttributeMaxDynamicSharedMemorySize, 165888);
    cudaFuncSetAttribute(k_corr_mma, cudaFuncAttributeMaxDynamicSharedMemorySize, 188416);

    const int  Hl[4]      = {128, 64, 32, 16};
    const int  lgWl[4]    = {7, 6, 5, 4};
    const int  HWl[4]     = {16384, 4096, 1024, 256};
    const long corrOff[4] = {0, 9469952, 11837440, 12429312};
    const long mapOff[4]  = {0, 8388608, 10485760, 11010048};
    const long amOff[4]   = {0, 28121600, 35369984, 37293568};
    const long aoOff[4]   = {0, 8652800, 10883072, 11474944};
    const long wmOff[4]   = {0, 1916928, 3833856, 5750784};
    const long woOff[4]   = {0, 589824, 1179648, 1769472};
    const int  zl[4]      = {1, 3, 9, 9};
    const int  tpzl[4]    = {9, 3, 1, 1};
    float* outp = (float*)d_out;

    int gemmBase[5]; gemmBase[0] = 0;
    for (int l = 0; l < 4; l++)
        gemmBase[l + 1] = gemmBase[l] + (2 * HWl[l] / 256) * 2 * zl[l];  // {0,256,448,592,628}

    int npbl[4];
    for (int l = 0; l < 4; l++){
        int Np = 2 * (Hl[l] + 2) * (Hl[l] + 2);
        npbl[l] = (Np + 31) / 32;
    }

    // ---- launch 0: init all atomic output buffers (map+out, levels 1-3) ----
    {
        InitParams P;
        long tot = 0;
        for (int r = 0; r < 3; r++){
            int l = r + 1;
            P.out[r] = mapB + mapOff[l]; P.bias[r] = bm[l]; P.HW[r] = HWl[l];
            P.base[r] = tot; tot += 2L * 256 * HWl[l];
        }
        for (int r = 0; r < 3; r++){
            int l = r + 1;
            P.out[3 + r] = outp + mapOff[l]; P.bias[3 + r] = bo[l]; P.HW[3 + r] = HWl[l];
            P.base[3 + r] = tot; tot += 2L * 256 * HWl[l];
        }
        P.base[6] = tot;
        k_init_all<<<(int)((tot + 255) / 256), 256>>>(P);
    }
    // ---- launch 1: pack all weights ----
    {
        PackWParams P;
        long tot = 0;
        for (int l = 0; l < 4; l++){
            P.src[l] = wm[l]; P.dst[l] = wmh + wmOff[l]; P.Cin[l] = 801; P.Cpad[l] = 832;
            P.base[l] = tot; tot += 256L * 832;
        }
        for (int l = 0; l < 4; l++){
            P.src[4+l] = wo[l]; P.dst[4+l] = woh + woOff[l]; P.Cin[4+l] = 256; P.Cpad[4+l] = 256;
            P.base[4+l] = tot; tot += 256L * 256;
        }
        P.base[8] = tot;
        k_pack_w_all<<<(int)((tot + 255) / 256), 256>>>(P);
    }
    // ---- launch 2: pack x/rx activation chunks (0-15), hi+lo (lo feeds corr-MMA) ----
    {
        PackMapParams P;
        int base = 0;
        for (int l = 0; l < 4; l++){
            P.x[l] = x[l]; P.rx[l] = rx[l]; P.corr[l] = corrB + corrOff[l];
            P.Ph[l] = amh + amOff[l]; P.Pl[l] = aml + amOff[l];
            P.H[l] = Hl[l]; P.npb[l] = npbl[l];
            P.blkBase[l] = base;
            base += npbl[l] * 16;
        }
        P.blkBase[4] = base;
        P.cBeg = 0;
        P.writeLo = 1;   // corr-MMA consumes x/rx lo planes
        k_pack_map_all<<<base, dim3(32, 8)>>>(P);
    }
    // ---- launch 3: MMA correlation ----
    {
        CorrMMAParams P;
        int base = 0;
        for (int l = 0; l < 4; l++){
            P.Xh[l] = amh + amOff[l];
            P.Xl[l] = aml + amOff[l];
            P.out[l] = corrB + corrOff[l];
            P.H[l] = Hl[l];
            P.chS[l] = 2L * (Hl[l] + 2) * (Hl[l] + 2) * 32;
            P.blkBase[l] = base;
            int RPB = 128 / Hl[l];
            base += 2 * Hl[l] / RPB;
        }
        P.blkBase[4] = base;
        k_corr_mma<<<base, 256, 188416>>>(P);
    }
    // ---- launch 4: pack corr activation chunks (16-25), hi+lo ----
    {
        PackMapParams P;
        int base = 0;
        for (int l = 0; l < 4; l++){
            P.x[l] = x[l]; P.rx[l] = rx[l]; P.corr[l] = corrB + corrOff[l];
            P.Ph[l] = amh + amOff[l]; P.Pl[l] = aml + amOff[l];
            P.H[l] = Hl[l]; P.npb[l] = npbl[l];
            P.blkBase[l] = base;
            base += npbl[l] * 10;
        }
        P.blkBase[4] = base;
        P.cBeg = 16;
        P.writeLo = 1;
        k_pack_map_all<<<base, dim3(32, 8)>>>(P);
    }
    // ---- launch 5: merged map GEMM (single-pass x/rx chunks, 2-pass corr chunks) ----
    {
        GemmParams P;
        P.A = wmh; P.BhB = amh; P.BlB = aml;
        for (int l = 0; l < 4; l++){
            P.out[l] = mapB + mapOff[l]; P.bias[l] = bm[l];
            P.aOff[l] = wmOff[l]; P.bOff[l] = amOff[l];
            P.H[l] = Hl[l]; P.lgW[l] = lgWl[l]; P.zc[l] = zl[l]; P.tpz[l] = tpzl[l];
        }
        for (int i = 0; i < 5; i++) P.blkBase[i] = gemmBase[i];
        P.CH = 26;
        P.loBeg = 16;
        k_gemm<<<gemmBase[4], 256, 165888>>>(P);
    }
    // ---- launch 6: pack out activations (hi only) with fused upsample cascade ----
    {
        PackOutParams P;
        int base = 0;
        for (int l = 0; l < 4; l++){
            P.map[l] = mapB + mapOff[l];
            P.Ph[l] = aoh + aoOff[l];
            P.H[l] = Hl[l]; P.npb[l] = npbl[l];
            P.blkBase[l] = base;
            base += npbl[l] * 8;
        }
        P.blkBase[4] = base;
        k_pack_out_all<<<base, dim3(32, 8)>>>(P);
    }
    // ---- launch 7: merged out GEMM -> d_out (single-pass) ----
    {
        GemmParams P;
        P.A = woh; P.BhB = aoh; P.BlB = aol;
        for (int l = 0; l < 4; l++){
            P.out[l] = outp + mapOff[l]; P.bias[l] = bo[l];
            P.aOff[l] = woOff[l]; P.bOff[l] = aoOff[l];
            P.H[l] = Hl[l]; P.lgW[l] = lgWl[l]; P.zc[l] = zl[l]; P.tpz[l] = tpzl[l];
        }
        for (int i = 0; i < 5; i++) P.blkBase[i] = gemmBase[i];
        P.CH = 8;
        P.loBeg = 8;   // all chunks single-pass
        k_gemm<<<gemmBase[4], 256, 165888>>>(P);
    }
}

// round 14
// speedup vs baseline: 2.0672x; 1.1009x over previous
#include <cuda_runtime.h>
#include <cuda_fp16.h>
#include <cstdint>
#include <cstddef>

#define PADC 8

// ---------------- static device buffers ----------------
__device__ __align__(256) float g_corr[12577280];
__device__ __align__(256) float g_map [11141120];
__device__ __align__(256) __half g_wm_h[7667712];   // [lvl][chunk26][tap9][co256][ci32] swizzled
__device__ __align__(256) __half g_wo_h[2359296];   // [lvl][chunk8][tap9][co256][ci32]
__device__ __align__(256) __half g_am_h[37832704];  // [lvl][chunk][b][Hp][Wp][32] swizzled
__device__ __align__(256) __half g_am_l[37832704];
__device__ __align__(256) __half g_ao_h[11640832];
__device__ __align__(256) __half g_ao_l[11640832];

// ---------------- PTX helpers (compute_103 baseline-safe) ----------------
__device__ __forceinline__ uint32_t smem_u32(const void* p){
    uint32_t a;
    asm("{ .reg .u64 t; cvta.to.shared.u64 t, %1; cvt.u32.u64 %0, t; }" : "=r"(a) : "l"(p));
    return a;
}
__device__ __forceinline__ void mbar_init(uint32_t a, uint32_t cnt){
    asm volatile("mbarrier.init.shared.b64 [%0], %1;" :: "r"(a), "r"(cnt) : "memory");
}
__device__ __forceinline__ void mbar_expect(uint32_t a, uint32_t bytes){
    asm volatile("mbarrier.arrive.expect_tx.shared.b64 _, [%0], %1;" :: "r"(a), "r"(bytes) : "memory");
}
__device__ __forceinline__ void mbar_wait(uint32_t a, int parity){
    asm volatile(
        "{\n\t.reg .pred P;\n\t"
        "WL_%=:\n\t"
        "mbarrier.try_wait.parity.acquire.cta.shared::cta.b64 P, [%0], %1, 0x989680;\n\t"
        "@P bra WD_%=;\n\t"
        "bra WL_%=;\n\t"
        "WD_%=:\n\t}"
        :: "r"(a), "r"(parity) : "memory");
}
__device__ __forceinline__ void bulk_cp(uint32_t dst, const void* src, uint32_t bytes, uint32_t mbar){
    asm volatile(
        "cp.async.bulk.shared::cluster.global.mbarrier::complete_tx::bytes [%0], [%1], %2, [%3];"
        :: "r"(dst), "l"(src), "r"(bytes), "r"(mbar) : "memory");
}
__device__ __forceinline__ void ldmx4(uint32_t* r, uint32_t addr){
    asm volatile("ldmatrix.sync.aligned.m8n8.x4.shared.b16 {%0,%1,%2,%3}, [%4];"
                 : "=r"(r[0]), "=r"(r[1]), "=r"(r[2]), "=r"(r[3]) : "r"(addr));
}
__device__ __forceinline__ void mma16816(float* c, const uint32_t* a, uint32_t b0, uint32_t b1){
    asm volatile(
        "mma.sync.aligned.m16n8k16.row.col.f32.f16.f16.f32 "
        "{%0,%1,%2,%3}, {%4,%5,%6,%7}, {%8,%9}, {%0,%1,%2,%3};"
        : "+f"(c[0]), "+f"(c[1]), "+f"(c[2]), "+f"(c[3])
        : "r"(a[0]), "r"(a[1]), "r"(a[2]), "r"(a[3]), "r"(b0), "r"(b1));
}

// ================= merged init bias (6 regions) =================
struct InitParams {
    float* out[6];
    const float* bias[6];
    int HW[6];
    long base[7];
};
__global__ void k_init_all(const __grid_constant__ InitParams P){
    long i = (long)blockIdx.x * blockDim.x + threadIdx.x;
    if (i >= P.base[6]) return;
    int r = 0;
    #pragma unroll
    for (int k = 1; k < 6; k++) if (i >= P.base[k]) r = k;
    long loc = i - P.base[r];
    P.out[r][loc] = P.bias[r][(loc / P.HW[r]) & 255];
}

// ================= merged weight pack (8 tensors) =================
struct PackWParams {
    const float* src[8];
    __half* dst[8];
    int Cin[8];
    int Cpad[8];
    long base[9];
};
__global__ void k_pack_w_all(const __grid_constant__ PackWParams P){
    long i = (long)blockIdx.x * 256 + threadIdx.x;
    if (i >= P.base[8]) return;
    int t = 0;
    #pragma unroll
    for (int k = 1; k < 8; k++) if (i >= P.base[k]) t = k;
    long loc = i - P.base[t];
    int Cpad = P.Cpad[t], Cin = P.Cin[t];
    int co = (int)(loc / Cpad), ci = (int)(loc % Cpad);
    int c = ci >> 5, cl = ci & 31;
    int gsw = (cl >> 3) ^ ((co >> 1) & 3);
    const float* w = P.src[t];
    __half* oh = P.dst[t];
    #pragma unroll
    for (int tap = 0; tap < 9; tap++){
        float v = (ci < Cin) ? w[(size_t)(co * Cin + ci) * 9 + tap] : 0.f;
        size_t o = (((size_t)c * 9 + tap) * 256 + co) * 32 + (gsw << 3) + (cl & 7);
        oh[o] = __float2half_rn(v);
    }
}

// ================= MMA correlation: corr[w,dj] = band of X^T R =================
struct CorrMMAParams {
    const __half* Xh[4];
    const __half* Xl[4];
    float* out[4];
    int H[4];
    long chS[4];
    int blkBase[5];
};
__global__ __launch_bounds__(256)
void k_corr_mma(const __grid_constant__ CorrMMAParams P)
{
    extern __shared__ char dsm[];
    __shared__ __align__(8) unsigned long long mb[3];

    const int bid = blockIdx.x;
    int l = 0;
    if (bid >= P.blkBase[1]) l = 1;
    if (bid >= P.blkBase[2]) l = 2;
    if (bid >= P.blkBase[3]) l = 3;
    const int rel = bid - P.blkBase[l];
    const int H = P.H[l], W = H, Hp = H + 2, Wp = W + 2;
    const int WT = W >> 4;
    const int RPB = 8 / WT;
    const int HB = H / RPB;
    const int b  = rel / HB;
    const int h0 = (rel % HB) * RPB;
    const long chS = P.chS[l];
    const __half* Xh = P.Xh[l];
    const __half* Xl = P.Xl[l];
    float* corr = P.out[l];

    const uint32_t sb = smem_u32(dsm);
    const uint32_t BB = sb + 147456u;
    const uint32_t MBA = smem_u32(&mb[0]);
    const uint32_t MBB = smem_u32(&mb[1]);

    const int tid = threadIdx.x, wid = tid >> 5, lane = tid & 31;
    const int wt = wid % WT, hl = wid / WT;
    const int w0 = wt * 16;
    const int lr = lane & 7, lm8 = ((lane >> 3) & 1) * 8, lk = lane >> 4;

    if (tid == 0){
        mbar_init(MBA, 1);
        mbar_init(MBB, 1);
        mbar_init(MBB + 8, 1);
    }
    __syncthreads();

    const long pA0 = (long)(b * Hp + h0 + 1) * Wp + 1;
    const uint32_t Abytes = (uint32_t)(((RPB - 1) * Wp + W) * 64);

    if (tid == 0){
        mbar_expect(MBA, 16u * Abytes);
        #pragma unroll
        for (int q = 0; q < 8; q++){
            bulk_cp(sb + (q * 2 + 0) * 9216u, Xh + (size_t)q * chS + pA0 * 32, Abytes, MBA);
            bulk_cp(sb + (q * 2 + 1) * 9216u, Xl + (size_t)q * chS + pA0 * 32, Abytes, MBA);
        }
    }

    auto issueB = [&](int s){
        int dy = s >> 3, q = s & 7;
        int r0 = h0 + dy - 8;
        int rc0 = (r0 < -1) ? -1 : r0;
        int rc1 = r0 + RPB - 1; if (rc1 > H) rc1 = H;
        if (rc1 < rc0){ rc0 = h0; rc1 = h0; }
        long pB0 = (long)(b * Hp + rc0 + 1) * Wp - 7;
        uint32_t Bb = (uint32_t)(((rc1 - rc0) * Wp + W + 16) * 64);
        int buf = s & 1;
        mbar_expect(MBB + buf * 8, 2u * Bb);
        bulk_cp(BB + buf * 20480u,           Xh + (size_t)(8 + q) * chS + pB0 * 32, Bb, MBB + buf * 8);
        bulk_cp(BB + buf * 20480u + 10240u,  Xl + (size_t)(8 + q) * chS + pB0 * 32, Bb, MBB + buf * 8);
    };

    if (tid == 0) issueB(0);
    mbar_wait(MBA, 0);

    const int offA_px = hl * Wp + w0 + lm8 + lr;
    const int xorA = (int)(((pA0 + offA_px) >> 1) & 3);
    const uint32_t aOff = (uint32_t)offA_px * 64u;

    float acc[4][4];
    const int nStages = 17 * 8;

    for (int s = 0; s < nStages; ++s){
        const int dy = s >> 3, q = s & 7;
        if (tid == 0 && s + 1 < nStages) issueB(s + 1);
        mbar_wait(MBB + (s & 1) * 8, (s >> 1) & 1);

        if (q == 0){
            #pragma unroll
            for (int f = 0; f < 4; f++)
                #pragma unroll
                for (int e = 0; e < 4; e++) acc[f][e] = 0.f;
        }

        int r0 = h0 + dy - 8;
        int rc0 = (r0 < -1) ? -1 : r0;
        int rc1 = r0 + RPB - 1; if (rc1 > H) rc1 = H;
        if (rc1 < rc0){ rc0 = h0; rc1 = h0; }
        const int r = h0 + hl + dy - 8;
        const bool valid = (r >= rc0 && r <= rc1);

        if (valid){
            const long pB0 = (long)(b * Hp + rc0 + 1) * Wp - 7;
            const int rowBase = (r - rc0) * Wp;
            const int offB0 = rowBase + w0 + lm8 + lr;
            const int offB1 = offB0 + 16;
            const int xb0 = (int)(((pB0 + offB0) >> 1) & 3);
            const int xb1 = (int)(((pB0 + offB1) >> 1) & 3);
            const uint32_t Bh0 = BB + (s & 1) * 20480u;
            const uint32_t Bl0 = Bh0 + 10240u;
            const uint32_t Ah0 = sb + (q * 2 + 0) * 9216u;
            const uint32_t Al0 = sb + (q * 2 + 1) * 9216u;

            #pragma unroll
            for (int ks = 0; ks < 2; ks++){
                const int g = 2 * ks + lk;
                uint32_t ah[4], al[4], bh[2][4], bl[2][4];
                ldmx4(ah, Ah0 + aOff + ((uint32_t)(g ^ xorA) << 4));
                ldmx4(al, Al0 + aOff + ((uint32_t)(g ^ xorA) << 4));
                ldmx4(bh[0], Bh0 + (uint32_t)offB0 * 64u + ((uint32_t)(g ^ xb0) << 4));
                ldmx4(bh[1], Bh0 + (uint32_t)offB1 * 64u + ((uint32_t)(g ^ xb1) << 4));
                ldmx4(bl[0], Bl0 + (uint32_t)offB0 * 64u + ((uint32_t)(g ^ xb0) << 4));
                ldmx4(bl[1], Bl0 + (uint32_t)offB1 * 64u + ((uint32_t)(g ^ xb1) << 4));
                #pragma unroll
                for (int nf = 0; nf < 2; nf++)
                    #pragma unroll
                    for (int sub = 0; sub < 2; sub++){
                        const int f = nf * 2 + sub;
                        mma16816(acc[f], ah, bh[nf][sub], bh[nf][2 + sub]);
                        mma16816(acc[f], al, bh[nf][sub], bh[nf][2 + sub]);
                        mma16816(acc[f], ah, bl[nf][sub], bl[nf][2 + sub]);
                    }
            }
        }

        if (q == 7){
            const int h = h0 + hl;
            #pragma unroll
            for (int f = 0; f < 4; f++){
                const int nf = f >> 1, sub = f & 1;
                const int nb = nf * 16 + sub * 8 + (lane & 3) * 2;
                #pragma unroll
                for (int e = 0; e < 2; e++){
                    const int n = nb + e;
                    #pragma unroll
                    for (int mh = 0; mh < 2; mh++){
                        const int m = (lane >> 2) + mh * 8;
                        const int w = w0 + m;
                        const int dj = n - m;
                        const int u = w0 - 8 + n;
                        if (dj >= 0 && dj <= 16){
                            float o = (valid && u >= 0 && u < W) ? acc[f][mh * 2 + e] : 0.f;
                            corr[(((long)b * 289 + dy * 17 + dj) * H + h) * W + w] = o;
                        }
                    }
                }
            }
        }
        __syncthreads();
    }
}

// ================= merged map-act pack (chunk-range, optional lo plane) =================
struct PackMapParams {
    const float* x[4];
    const float* rx[4];
    const float* corr[4];
    __half* Ph[4];
    __half* Pl[4];
    int H[4];
    int npb[4];
    int blkBase[5];
    int cBeg;
    int writeLo;
};
__global__ void k_pack_map_all(const __grid_constant__ PackMapParams P){
    __shared__ float t[32][33];
    const int bid = blockIdx.x;
    int l = 0;
    if (bid >= P.blkBase[1]) l = 1;
    if (bid >= P.blkBase[2]) l = 2;
    if (bid >= P.blkBase[3]) l = 3;
    const int rel = bid - P.blkBase[l];
    const int npb = P.npb[l];
    const int bxp = rel % npb;
    const int c0  = (P.cBeg + rel / npb) * 32;
    const int H = P.H[l], W = H;
    const int Hp = H + 2, Wp = W + 2, HW = H * W, Np = 2 * Hp * Wp;
    const int p0 = bxp * 32;

    int px = p0 + threadIdx.x;
    int b = 0, pix = 0; bool inter = false;
    if (px < Np){
        b = px / (Hp * Wp); int r = px % (Hp * Wp); int hp = r / Wp, wp = r % Wp;
        if (hp >= 1 && hp <= H && wp >= 1 && wp <= W){ inter = true; pix = (hp - 1) * W + (wp - 1); }
    }
    const float* X  = P.x[l];
    const float* RX = P.rx[l];
    const float* CR = P.corr[l];
    #pragma unroll
    for (int dyy = 0; dyy < 32; dyy += 8){
        int ci = c0 + (int)threadIdx.y + dyy;
        float v = 0.f;
        if (inter){
            if (ci < 256)       v = X [(size_t)(b * 256 + ci) * HW + pix];
            else if (ci < 512)  v = RX[(size_t)(b * 256 + ci - 256) * HW + pix];
            else if (ci < 801)  v = CR[(size_t)(b * 289 + ci - 512) * HW + pix];
        }
        t[threadIdx.y + dyy][threadIdx.x] = v;
    }
    __syncthreads();
    int ft = threadIdx.y * 32 + threadIdx.x;
    int pl = ft >> 3, sub = ft & 7;
    int px2 = p0 + pl;
    if (px2 < Np){
        size_t chStride = (size_t)2 * Hp * Wp * 32;
        int gsw = (sub >> 1) ^ ((px2 >> 1) & 3);
        size_t base = (size_t)(c0 >> 5) * chStride + (size_t)px2 * 32 + (gsw << 3) + (sub & 1) * 4;
        float v0 = t[sub*4+0][pl], v1 = t[sub*4+1][pl], v2 = t[sub*4+2][pl], v3 = t[sub*4+3][pl];
        __half h0 = __float2half_rn(v0), h1 = __float2half_rn(v1);
        __half h2 = __float2half_rn(v2), h3 = __float2half_rn(v3);
        uint32_t uh0 = (uint32_t)__half_as_ushort(h0) | ((uint32_t)__half_as_ushort(h1) << 16);
        uint32_t uh1 = (uint32_t)__half_as_ushort(h2) | ((uint32_t)__half_as_ushort(h3) << 16);
        uint2 wh; wh.x = uh0; wh.y = uh1;
        *reinterpret_cast<uint2*>(P.Ph[l] + base) = wh;
        if (P.writeLo){
            __half l0 = __float2half_rn(v0 - __half2float(h0));
            __half l1 = __float2half_rn(v1 - __half2float(h1));
            __half l2 = __float2half_rn(v2 - __half2float(h2));
            __half l3 = __float2half_rn(v3 - __half2float(h3));
            uint32_t ul0 = (uint32_t)__half_as_ushort(l0) | ((uint32_t)__half_as_ushort(l1) << 16);
            uint32_t ul1 = (uint32_t)__half_as_ushort(l2) | ((uint32_t)__half_as_ushort(l3) << 16);
            uint2 wl; wl.x = ul0; wl.y = ul1;
            *reinterpret_cast<uint2*>(P.Pl[l] + base) = wl;
        }
    }
}

// ================= merged out-act pack with fused upsample cascade (hi only) =================
struct PackOutParams {
    const float* map[4];
    __half* Ph[4];
    int H[4];
    int npb[4];
    int blkBase[5];
};
__global__ void k_pack_out_all(const __grid_constant__ PackOutParams P){
    __shared__ float t[32][33];
    const int bid = blockIdx.x;
    int l = 0;
    if (bid >= P.blkBase[1]) l = 1;
    if (bid >= P.blkBase[2]) l = 2;
    if (bid >= P.blkBase[3]) l = 3;
    const int rel = bid - P.blkBase[l];
    const int npb = P.npb[l];
    const int bxp = rel % npb;
    const int c0  = (rel / npb) * 32;
    const int H = P.H[l], W = H;
    const int Hp = H + 2, Wp = W + 2, Np = 2 * Hp * Wp;
    const int p0 = bxp * 32;

    int px = p0 + threadIdx.x;
    int b = 0, hh = 0, ww = 0; bool inter = false;
    if (px < Np){
        b = px / (Hp * Wp); int r = px % (Hp * Wp); int hp = r / Wp, wp = r % Wp;
        if (hp >= 1 && hp <= H && wp >= 1 && wp <= W){ inter = true; hh = hp - 1; ww = wp - 1; }
    }
    #pragma unroll
    for (int dyy = 0; dyy < 32; dyy += 8){
        int ci = c0 + (int)threadIdx.y + dyy;
        float v = 0.f;
        if (inter){
            for (int k = l; k < 4; k++){
                int Wk = P.H[k];
                int sh = k - l;
                v += P.map[k][((size_t)(b * 256 + ci) * Wk + (hh >> sh)) * Wk + (ww >> sh)];
            }
        }
        t[threadIdx.y + dyy][threadIdx.x] = v;
    }
    __syncthreads();
    int ft = threadIdx.y * 32 + threadIdx.x;
    int pl = ft >> 3, sub = ft & 7;
    int px2 = p0 + pl;
    if (px2 < Np){
        size_t chStride = (size_t)2 * Hp * Wp * 32;
        int gsw = (sub >> 1) ^ ((px2 >> 1) & 3);
        size_t base = (size_t)(c0 >> 5) * chStride + (size_t)px2 * 32 + (gsw << 3) + (sub & 1) * 4;
        float v0 = t[sub*4+0][pl], v1 = t[sub*4+1][pl], v2 = t[sub*4+2][pl], v3 = t[sub*4+3][pl];
        __half h0 = __float2half_rn(v0), h1 = __float2half_rn(v1);
        __half h2 = __float2half_rn(v2), h3 = __float2half_rn(v3);
        uint32_t uh0 = (uint32_t)__half_as_ushort(h0) | ((uint32_t)__half_as_ushort(h1) << 16);
        uint32_t uh1 = (uint32_t)__half_as_ushort(h2) | ((uint32_t)__half_as_ushort(h3) << 16);
        uint2 wh; wh.x = uh0; wh.y = uh1;
        *reinterpret_cast<uint2*>(P.Ph[l] + base) = wh;
    }
}

// ================= merged multi-level fp16 implicit-conv GEMM =================
// Chunks >= loBeg get the activation-lo pass; chunks < loBeg are single-pass.
struct GemmParams {
    const __half* A;
    const __half* BhB;
    const __half* BlB;
    float*        out[4];
    const float*  bias[4];
    long aOff[4];
    long bOff[4];
    int  H[4];
    int  lgW[4];
    int  zc[4];
    int  tpz[4];
    int  blkBase[5];
    int  CH;
    int  loBeg;
};

__global__ __launch_bounds__(256)
void k_gemm(const __grid_constant__ GemmParams P)
{
    extern __shared__ char dsm[];
    __shared__ __align__(8) unsigned long long mb[6];

    const int bid = blockIdx.x;
    int l = 0;
    if (bid >= P.blkBase[1]) l = 1;
    if (bid >= P.blkBase[2]) l = 2;
    if (bid >= P.blkBase[3]) l = 3;
    const int rel = bid - P.blkBase[l];
    const int zc = P.zc[l], tapsPerZ = P.tpz[l];
    const int zi = rel % zc;
    const int tt = rel / zc;
    const int m0 = (tt & 1) * 128;
    const int nt = tt >> 1;
    const int H = P.H[l], W = H, lgW = P.lgW[l];
    const __half* A  = P.A   + P.aOff[l];
    const __half* Bh = P.BhB + P.bOff[l];
    const __half* Bl = P.BlB + P.bOff[l];
    float* out = P.out[l];
    const float* bias = P.bias[l];
    const int useAtomic = (zc > 1);
    const int tapBeg = zi * tapsPerZ;
    const int CH = P.CH;
    const int loBeg = P.loBeg;

    const uint32_t smemBase = smem_u32(dsm);
    uint32_t A_OFF[4], B_OFF[2];
    #pragma unroll
    for (int s = 0; s < 4; s++) A_OFF[s] = smemBase + s * 8192u;
    B_OFF[0] = smemBase + 32768u;
    B_OFF[1] = smemBase + 32768u + 66560u;
    const uint32_t MBA = smem_u32(&mb[0]);
    const uint32_t MBB = smem_u32(&mb[4]);

    const int tid = threadIdx.x, wid = tid >> 5, lane = tid & 31;
    const int R = 256 >> lgW;
    const int Hp = H + 2, Wp = W + 2;
    const int tilesPerB = H / R;
    const int b  = nt / tilesPerB;
    const int h0 = (nt % tilesPerB) * R;
    const int q0 = (b * Hp + h0) * Wp;
    const uint32_t Bbytes = (uint32_t)(R + 2) * Wp * 64u;
    const size_t chStride = (size_t)2 * Hp * Wp * 32;

    if (tid == 0){
        #pragma unroll
        for (int i = 0; i < 6; i++) mbar_init(MBA + i * 8, 1);
    }
    __syncthreads();

    const int nA = CH * tapsPerZ;

    auto issueA = [&](int ia){
        int c = ia / tapsPerZ, tap = ia % tapsPerZ;
        const __half* src = A + ((((size_t)c * 9 + (tapBeg + tap)) * 256 + m0) << 5);
        int s = ia & 3;
        mbar_expect(MBA + s * 8, 8192u);
        bulk_cp(A_OFF[s], src, 8192u, MBA + s * 8);
    };
    auto issueB = [&](int c){
        int s = c & 1;
        bool lo = (c >= loBeg);
        mbar_expect(MBB + s * 8, lo ? 2u * Bbytes : Bbytes);
        bulk_cp(B_OFF[s], Bh + (size_t)c * chStride + ((size_t)q0 << 5), Bbytes, MBB + s * 8);
        if (lo)
            bulk_cp(B_OFF[s] + 33280u, Bl + (size_t)c * chStride + ((size_t)q0 << 5), Bbytes, MBB + s * 8);
    };

    const int lr  = lane & 7;
    const int lm8 = ((lane >> 3) & 1) * 8;
    const int lk  = lane >> 4;
    const int wm  = wid & 1;
    const int wn  = wid >> 1;
    const int rowA = wm * 64 + lm8 + lr;
    const int xorA = (lr >> 1) & 3;
    int rB[4], wB[4];
    #pragma unroll
    for (int g = 0; g < 4; g++){
        int n = wn * 64 + g * 16 + lm8 + lr;
        rB[g] = n >> lgW;
        wB[g] = n & (W - 1);
    }

    float acc[4][8][4];
    #pragma unroll
    for (int i = 0; i < 4; i++)
        #pragma unroll
        for (int j = 0; j < 8; j++)
            #pragma unroll
            for (int k = 0; k < 4; k++) acc[i][j][k] = 0.f;

    if (tid == 0){
        issueB(0);
        issueA(0);
        if (nA > 1) issueA(1);
        if (nA > 2) issueA(2);
    }

    for (int it = 0; it < nA; ++it){
        int c = it / tapsPerZ, tap = it % tapsPerZ;
        if (tid == 0){
            if (it + 3 < nA) issueA(it + 3);
            if (tap == 0 && c + 1 < CH) issueB(c + 1);
        }
        mbar_wait(MBA + (it & 3) * 8, (it >> 2) & 1);
        if (tap == 0) mbar_wait(MBB + (c & 1) * 8, (c >> 1) & 1);

        const uint32_t Ab = A_OFF[it & 3];
        const uint32_t Bb = B_OFF[c & 1];
        const int tIdx = tapBeg + tap;
        const int dy = tIdx / 3, dx = tIdx - dy * 3;
        const int nPass = (c >= loBeg) ? 2 : 1;

        uint32_t sAdr[4]; int xorB[4];
        #pragma unroll
        for (int g = 0; g < 4; g++){
            int s = (rB[g] + dy) * Wp + wB[g] + dx;
            sAdr[g] = Bb + (uint32_t)s * 64u;
            xorB[g] = ((q0 + s) >> 1) & 3;
        }

        #pragma unroll
        for (int ks = 0; ks < 2; ks++){
            const int gA = (2 * ks + lk) ^ xorA;
            uint32_t a[4][4];
            #pragma unroll
            for (int ma = 0; ma < 4; ma++)
                ldmx4(a[ma], Ab + (uint32_t)(rowA + ma * 16) * 64u + ((uint32_t)gA << 4));
            for (int pass = 0; pass < nPass; pass++){
                uint32_t bb[4][4];
                #pragma unroll
                for (int g = 0; g < 4; g++){
                    int gB = (2 * ks + lk) ^ xorB[g];
                    ldmx4(bb[g], sAdr[g] + (uint32_t)pass * 33280u + ((uint32_t)gB << 4));
                }
                #pragma unroll
                for (int ma = 0; ma < 4; ma++)
                    #pragma unroll
                    for (int na = 0; na < 8; na++)
                        mma16816(acc[ma][na], a[ma], bb[na >> 1][na & 1], bb[na >> 1][2 + (na & 1)]);
            }
        }
        __syncthreads();
    }

    #pragma unroll
    for (int ma = 0; ma < 4; ma++){
        int co0 = m0 + wm * 64 + ma * 16 + (lane >> 2);
        int co1 = co0 + 8;
        float bv0 = useAtomic ? 0.f : bias[co0];
        float bv1 = useAtomic ? 0.f : bias[co1];
        #pragma unroll
        for (int na = 0; na < 8; na++){
            int n = wn * 64 + na * 8 + (lane & 3) * 2;
            int r = h0 + (n >> lgW);
            int w = n & (W - 1);
            size_t i0 = ((size_t)(b * 256 + co0) * H + r) * W + w;
            size_t i1 = ((size_t)(b * 256 + co1) * H + r) * W + w;
            if (useAtomic){
                atomicAdd(&out[i0],     acc[ma][na][0]);
                atomicAdd(&out[i0 + 1], acc[ma][na][1]);
                atomicAdd(&out[i1],     acc[ma][na][2]);
                atomicAdd(&out[i1 + 1], acc[ma][na][3]);
            } else {
                float2 v0; v0.x = acc[ma][na][0] + bv0; v0.y = acc[ma][na][1] + bv0;
                float2 v1; v1.x = acc[ma][na][2] + bv1; v1.y = acc[ma][na][3] + bv1;
                *reinterpret_cast<float2*>(&out[i0]) = v0;
                *reinterpret_cast<float2*>(&out[i1]) = v1;
            }
        }
    }
}

// ---------------- host orchestration (8 launches total) ----------------
extern "C" void kernel_launch(void* const* d_in, const int* in_sizes, int n_in,
                              void* d_out, int out_size)
{
    const float *x[4]={0,0,0,0}, *rx[4]={0,0,0,0};
    const float *wm[4]={0,0,0,0}, *bm[4]={0,0,0,0}, *wo[4]={0,0,0,0}, *bo[4]={0,0,0,0};
    int wmi = 0, woi = 0, bi = 0;
    for (int i = 0; i < n_in; i++){
        int s = in_sizes[i];
        int lvl = -1;
        if      (s == 2*256*128*128) lvl = 0;
        else if (s == 2*256*64*64)   lvl = 1;
        else if (s == 2*256*32*32)   lvl = 2;
        else if (s == 2*256*16*16)   lvl = 3;
        if (lvl >= 0){
            if (!x[lvl]) x[lvl] = (const float*)d_in[i];
            else         rx[lvl] = (const float*)d_in[i];
        }
        else if (s == 1845504) wm[wmi++] = (const float*)d_in[i];
        else if (s ==  589824) wo[woi++] = (const float*)d_in[i];
        else if (s ==     256){
            if ((bi & 1) == 0) bm[bi >> 1] = (const float*)d_in[i];
            else               bo[bi >> 1] = (const float*)d_in[i];
            bi++;
        }
    }

    float *corrB, *mapB;
    __half *wmh, *woh, *amh, *aml, *aoh, *aol;
    cudaGetSymbolAddress((void**)&corrB, g_corr);
    cudaGetSymbolAddress((void**)&mapB,  g_map);
    cudaGetSymbolAddress((void**)&wmh, g_wm_h);
    cudaGetSymbolAddress((void**)&woh, g_wo_h);
    cudaGetSymbolAddress((void**)&amh, g_am_h); cudaGetSymbolAddress((void**)&aml, g_am_l);
    cudaGetSymbolAddress((void**)&aoh, g_ao_h); cudaGetSymbolAddress((void**)&aol, g_ao_l);

    cudaFuncSetAttribute(k_gemm, cudaFuncAttributeMaxDynamicSharedMemorySize, 165888);
    cudaFuncSetAttribute(k_corr_mma, cudaFuncAttributeMaxDynamicSharedMemorySize, 188416);

    const int  Hl[4]      = {128, 64, 32, 16};
    const int  lgWl[4]    = {7, 6, 5, 4};
    const int  HWl[4]     = {16384, 4096, 1024, 256};
    const long corrOff[4] = {0, 9469952, 11837440, 12429312};
    const long mapOff[4]  = {0, 8388608, 10485760, 11010048};
    const long amOff[4]   = {0, 28121600, 35369984, 37293568};
    const long aoOff[4]   = {0, 8652800, 10883072, 11474944};
    const long wmOff[4]   = {0, 1916928, 3833856, 5750784};
    const long woOff[4]   = {0, 589824, 1179648, 1769472};
    const int  zl[4]      = {1, 3, 9, 9};
    const int  tpzl[4]    = {9, 3, 1, 1};
    float* outp = (float*)d_out;

    int gemmBase[5]; gemmBase[0] = 0;
    for (int l = 0; l < 4; l++)
        gemmBase[l + 1] = gemmBase[l] + (2 * HWl[l] / 256) * 2 * zl[l];  // {0,256,448,592,628}

    int npbl[4];
    for (int l = 0; l < 4; l++){
        int Np = 2 * (Hl[l] + 2) * (Hl[l] + 2);
        npbl[l] = (Np + 31) / 32;
    }

    // ---- launch 0: init all atomic output buffers (map+out, levels 1-3) ----
    {
        InitParams P;
        long tot = 0;
        for (int r = 0; r < 3; r++){
            int l = r + 1;
            P.out[r] = mapB + mapOff[l]; P.bias[r] = bm[l]; P.HW[r] = HWl[l];
            P.base[r] = tot; tot += 2L * 256 * HWl[l];
        }
        for (int r = 0; r < 3; r++){
            int l = r + 1;
            P.out[3 + r] = outp + mapOff[l]; P.bias[3 + r] = bo[l]; P.HW[3 + r] = HWl[l];
            P.base[3 + r] = tot; tot += 2L * 256 * HWl[l];
        }
        P.base[6] = tot;
        k_init_all<<<(int)((tot + 255) / 256), 256>>>(P);
    }
    // ---- launch 1: pack all weights ----
    {
        PackWParams P;
        long tot = 0;
        for (int l = 0; l < 4; l++){
            P.src[l] = wm[l]; P.dst[l] = wmh + wmOff[l]; P.Cin[l] = 801; P.Cpad[l] = 832;
            P.base[l] = tot; tot += 256L * 832;
        }
        for (int l = 0; l < 4; l++){
            P.src[4+l] = wo[l]; P.dst[4+l] = woh + woOff[l]; P.Cin[4+l] = 256; P.Cpad[4+l] = 256;
            P.base[4+l] = tot; tot += 256L * 256;
        }
        P.base[8] = tot;
        k_pack_w_all<<<(int)((tot + 255) / 256), 256>>>(P);
    }
    // ---- launch 2: pack x/rx activation chunks (0-15), hi+lo (lo feeds corr-MMA) ----
    {
        PackMapParams P;
        int base = 0;
        for (int l = 0; l < 4; l++){
            P.x[l] = x[l]; P.rx[l] = rx[l]; P.corr[l] = corrB + corrOff[l];
            P.Ph[l] = amh + amOff[l]; P.Pl[l] = aml + amOff[l];
            P.H[l] = Hl[l]; P.npb[l] = npbl[l];
            P.blkBase[l] = base;
            base += npbl[l] * 16;
        }
        P.blkBase[4] = base;
        P.cBeg = 0;
        P.writeLo = 1;   // corr-MMA consumes x/rx lo planes
        k_pack_map_all<<<base, dim3(32, 8)>>>(P);
    }
    // ---- launch 3: MMA correlation (3-pass, fp32-grade corr) ----
    {
        CorrMMAParams P;
        int base = 0;
        for (int l = 0; l < 4; l++){
            P.Xh[l] = amh + amOff[l];
            P.Xl[l] = aml + amOff[l];
            P.out[l] = corrB + corrOff[l];
            P.H[l] = Hl[l];
            P.chS[l] = 2L * (Hl[l] + 2) * (Hl[l] + 2) * 32;
            P.blkBase[l] = base;
            int RPB = 128 / Hl[l];
            base += 2 * Hl[l] / RPB;
        }
        P.blkBase[4] = base;
        k_corr_mma<<<base, 256, 188416>>>(P);
    }
    // ---- launch 4: pack corr activation chunks (16-25), hi only ----
    {
        PackMapParams P;
        int base = 0;
        for (int l = 0; l < 4; l++){
            P.x[l] = x[l]; P.rx[l] = rx[l]; P.corr[l] = corrB + corrOff[l];
            P.Ph[l] = amh + amOff[l]; P.Pl[l] = aml + amOff[l];
            P.H[l] = Hl[l]; P.npb[l] = npbl[l];
            P.blkBase[l] = base;
            base += npbl[l] * 10;
        }
        P.blkBase[4] = base;
        P.cBeg = 16;
        P.writeLo = 0;   // map GEMM is now fully single-pass
        k_pack_map_all<<<base, dim3(32, 8)>>>(P);
    }
    // ---- launch 5: merged map GEMM (fully single-pass) ----
    {
        GemmParams P;
        P.A = wmh; P.BhB = amh; P.BlB = aml;
        for (int l = 0; l < 4; l++){
            P.out[l] = mapB + mapOff[l]; P.bias[l] = bm[l];
            P.aOff[l] = wmOff[l]; P.bOff[l] = amOff[l];
            P.H[l] = Hl[l]; P.lgW[l] = lgWl[l]; P.zc[l] = zl[l]; P.tpz[l] = tpzl[l];
        }
        for (int i = 0; i < 5; i++) P.blkBase[i] = gemmBase[i];
        P.CH = 26;
        P.loBeg = 26;   // all chunks single-pass
        k_gemm<<<gemmBase[4], 256, 165888>>>(P);
    }
    // ---- launch 6: pack out activations (hi only) with fused upsample cascade ----
    {
        PackOutParams P;
        int base = 0;
        for (int l = 0; l < 4; l++){
            P.map[l] = mapB + mapOff[l];
            P.Ph[l] = aoh + aoOff[l];
            P.H[l] = Hl[l]; P.npb[l] = npbl[l];
            P.blkBase[l] = base;
            base += npbl[l] * 8;
        }
        P.blkBase[4] = base;
        k_pack_out_all<<<base, dim3(32, 8)>>>(P);
    }
    // ---- launch 7: merged out GEMM -> d_out (single-pass) ----
    {
        GemmParams P;
        P.A = woh; P.BhB = aoh; P.BlB = aol;
        for (int l = 0; l < 4; l++){
            P.out[l] = outp + mapOff[l]; P.bias[l] = bo[l];
            P.aOff[l] = woOff[l]; P.bOff[l] = aoOff[l];
            P.H[l] = Hl[l]; P.lgW[l] = lgWl[l]; P.zc[l] = zl[l]; P.tpz[l] = tpzl[l];
        }
        for (int i = 0; i < 5; i++) P.blkBase[i] = gemmBase[i];
        P.CH = 8;
        P.loBeg = 8;   // all chunks single-pass
        k_gemm<<<gemmBase[4], 256, 165888>>>(P);
    }
}

// round 15
// speedup vs baseline: 2.1409x; 1.0356x over previous
#include <cuda_runtime.h>
#include <cuda_fp16.h>
#include <cstdint>
#include <cstddef>

#define PADC 8

// ---------------- static device buffers ----------------
__device__ __align__(256) float g_corr[12577280];
__device__ __align__(256) float g_map [11141120];
__device__ __align__(256) __half g_wm_h[7667712];   // [lvl][chunk26][tap9][co256][ci32] swizzled
__device__ __align__(256) __half g_wo_h[2359296];   // [lvl][chunk8][tap9][co256][ci32]
__device__ __align__(256) __half g_am_h[37832704];  // [lvl][chunk][b][Hp][Wp][32] swizzled
__device__ __align__(256) __half g_am_l[37832704];
__device__ __align__(256) __half g_ao_h[11640832];
__device__ __align__(256) __half g_ao_l[11640832];

// ---------------- PTX helpers (compute_103 baseline-safe) ----------------
__device__ __forceinline__ uint32_t smem_u32(const void* p){
    uint32_t a;
    asm("{ .reg .u64 t; cvta.to.shared.u64 t, %1; cvt.u32.u64 %0, t; }" : "=r"(a) : "l"(p));
    return a;
}
__device__ __forceinline__ void mbar_init(uint32_t a, uint32_t cnt){
    asm volatile("mbarrier.init.shared.b64 [%0], %1;" :: "r"(a), "r"(cnt) : "memory");
}
__device__ __forceinline__ void mbar_expect(uint32_t a, uint32_t bytes){
    asm volatile("mbarrier.arrive.expect_tx.shared.b64 _, [%0], %1;" :: "r"(a), "r"(bytes) : "memory");
}
__device__ __forceinline__ void mbar_wait(uint32_t a, int parity){
    asm volatile(
        "{\n\t.reg .pred P;\n\t"
        "WL_%=:\n\t"
        "mbarrier.try_wait.parity.acquire.cta.shared::cta.b64 P, [%0], %1, 0x989680;\n\t"
        "@P bra WD_%=;\n\t"
        "bra WL_%=;\n\t"
        "WD_%=:\n\t}"
        :: "r"(a), "r"(parity) : "memory");
}
__device__ __forceinline__ void bulk_cp(uint32_t dst, const void* src, uint32_t bytes, uint32_t mbar){
    asm volatile(
        "cp.async.bulk.shared::cluster.global.mbarrier::complete_tx::bytes [%0], [%1], %2, [%3];"
        :: "r"(dst), "l"(src), "r"(bytes), "r"(mbar) : "memory");
}
__device__ __forceinline__ void ldmx4(uint32_t* r, uint32_t addr){
    asm volatile("ldmatrix.sync.aligned.m8n8.x4.shared.b16 {%0,%1,%2,%3}, [%4];"
                 : "=r"(r[0]), "=r"(r[1]), "=r"(r[2]), "=r"(r[3]) : "r"(addr));
}
__device__ __forceinline__ void mma16816(float* c, const uint32_t* a, uint32_t b0, uint32_t b1){
    asm volatile(
        "mma.sync.aligned.m16n8k16.row.col.f32.f16.f16.f32 "
        "{%0,%1,%2,%3}, {%4,%5,%6,%7}, {%8,%9}, {%0,%1,%2,%3};"
        : "+f"(c[0]), "+f"(c[1]), "+f"(c[2]), "+f"(c[3])
        : "r"(a[0]), "r"(a[1]), "r"(a[2]), "r"(a[3]), "r"(b0), "r"(b1));
}

// ================= merged init bias (6 regions) =================
struct InitParams {
    float* out[6];
    const float* bias[6];
    int HW[6];
    long base[7];
};
__global__ void k_init_all(const __grid_constant__ InitParams P){
    long i = (long)blockIdx.x * blockDim.x + threadIdx.x;
    if (i >= P.base[6]) return;
    int r = 0;
    #pragma unroll
    for (int k = 1; k < 6; k++) if (i >= P.base[k]) r = k;
    long loc = i - P.base[r];
    P.out[r][loc] = P.bias[r][(loc / P.HW[r]) & 255];
}

// ================= merged weight pack (8 tensors) =================
struct PackWParams {
    const float* src[8];
    __half* dst[8];
    int Cin[8];
    int Cpad[8];
    long base[9];
};
__global__ void k_pack_w_all(const __grid_constant__ PackWParams P){
    long i = (long)blockIdx.x * 256 + threadIdx.x;
    if (i >= P.base[8]) return;
    int t = 0;
    #pragma unroll
    for (int k = 1; k < 8; k++) if (i >= P.base[k]) t = k;
    long loc = i - P.base[t];
    int Cpad = P.Cpad[t], Cin = P.Cin[t];
    int co = (int)(loc / Cpad), ci = (int)(loc % Cpad);
    int c = ci >> 5, cl = ci & 31;
    int gsw = (cl >> 3) ^ ((co >> 1) & 3);
    const float* w = P.src[t];
    __half* oh = P.dst[t];
    #pragma unroll
    for (int tap = 0; tap < 9; tap++){
        float v = (ci < Cin) ? w[(size_t)(co * Cin + ci) * 9 + tap] : 0.f;
        size_t o = (((size_t)c * 9 + tap) * 256 + co) * 32 + (gsw << 3) + (cl & 7);
        oh[o] = __float2half_rn(v);
    }
}

// ================= MMA correlation: corr[w,dj] = band of X^T R =================
// 2-pass: xh*rh + xl*rh = fp32(x) * fp16(r). B stages carry hi only.
struct CorrMMAParams {
    const __half* Xh[4];
    const __half* Xl[4];
    float* out[4];
    int H[4];
    long chS[4];
    int blkBase[5];
};
__global__ __launch_bounds__(256)
void k_corr_mma(const __grid_constant__ CorrMMAParams P)
{
    extern __shared__ char dsm[];
    __shared__ __align__(8) unsigned long long mb[3];

    const int bid = blockIdx.x;
    int l = 0;
    if (bid >= P.blkBase[1]) l = 1;
    if (bid >= P.blkBase[2]) l = 2;
    if (bid >= P.blkBase[3]) l = 3;
    const int rel = bid - P.blkBase[l];
    const int H = P.H[l], W = H, Hp = H + 2, Wp = W + 2;
    const int WT = W >> 4;
    const int RPB = 8 / WT;
    const int HB = H / RPB;
    const int b  = rel / HB;
    const int h0 = (rel % HB) * RPB;
    const long chS = P.chS[l];
    const __half* Xh = P.Xh[l];
    const __half* Xl = P.Xl[l];
    float* corr = P.out[l];

    const uint32_t sb = smem_u32(dsm);
    const uint32_t BB = sb + 147456u;        // B bufs: 2 x 10240 (hi only)
    const uint32_t MBA = smem_u32(&mb[0]);
    const uint32_t MBB = smem_u32(&mb[1]);

    const int tid = threadIdx.x, wid = tid >> 5, lane = tid & 31;
    const int wt = wid % WT, hl = wid / WT;
    const int w0 = wt * 16;
    const int lr = lane & 7, lm8 = ((lane >> 3) & 1) * 8, lk = lane >> 4;

    if (tid == 0){
        mbar_init(MBA, 1);
        mbar_init(MBB, 1);
        mbar_init(MBB + 8, 1);
    }
    __syncthreads();

    const long pA0 = (long)(b * Hp + h0 + 1) * Wp + 1;
    const uint32_t Abytes = (uint32_t)(((RPB - 1) * Wp + W) * 64);

    if (tid == 0){
        mbar_expect(MBA, 16u * Abytes);
        #pragma unroll
        for (int q = 0; q < 8; q++){
            bulk_cp(sb + (q * 2 + 0) * 9216u, Xh + (size_t)q * chS + pA0 * 32, Abytes, MBA);
            bulk_cp(sb + (q * 2 + 1) * 9216u, Xl + (size_t)q * chS + pA0 * 32, Abytes, MBA);
        }
    }

    auto issueB = [&](int s){
        int dy = s >> 3, q = s & 7;
        int r0 = h0 + dy - 8;
        int rc0 = (r0 < -1) ? -1 : r0;
        int rc1 = r0 + RPB - 1; if (rc1 > H) rc1 = H;
        if (rc1 < rc0){ rc0 = h0; rc1 = h0; }
        long pB0 = (long)(b * Hp + rc0 + 1) * Wp - 7;
        uint32_t Bb = (uint32_t)(((rc1 - rc0) * Wp + W + 16) * 64);
        int buf = s & 1;
        mbar_expect(MBB + buf * 8, Bb);
        bulk_cp(BB + buf * 10240u, Xh + (size_t)(8 + q) * chS + pB0 * 32, Bb, MBB + buf * 8);
    };

    if (tid == 0) issueB(0);
    mbar_wait(MBA, 0);

    const int offA_px = hl * Wp + w0 + lm8 + lr;
    const int xorA = (int)(((pA0 + offA_px) >> 1) & 3);
    const uint32_t aOff = (uint32_t)offA_px * 64u;

    float acc[4][4];
    const int nStages = 17 * 8;

    for (int s = 0; s < nStages; ++s){
        const int dy = s >> 3, q = s & 7;
        if (tid == 0 && s + 1 < nStages) issueB(s + 1);
        mbar_wait(MBB + (s & 1) * 8, (s >> 1) & 1);

        if (q == 0){
            #pragma unroll
            for (int f = 0; f < 4; f++)
                #pragma unroll
                for (int e = 0; e < 4; e++) acc[f][e] = 0.f;
        }

        int r0 = h0 + dy - 8;
        int rc0 = (r0 < -1) ? -1 : r0;
        int rc1 = r0 + RPB - 1; if (rc1 > H) rc1 = H;
        if (rc1 < rc0){ rc0 = h0; rc1 = h0; }
        const int r = h0 + hl + dy - 8;
        const bool valid = (r >= rc0 && r <= rc1);

        if (valid){
            const long pB0 = (long)(b * Hp + rc0 + 1) * Wp - 7;
            const int rowBase = (r - rc0) * Wp;
            const int offB0 = rowBase + w0 + lm8 + lr;
            const int offB1 = offB0 + 16;
            const int xb0 = (int)(((pB0 + offB0) >> 1) & 3);
            const int xb1 = (int)(((pB0 + offB1) >> 1) & 3);
            const uint32_t Bh0 = BB + (s & 1) * 10240u;
            const uint32_t Ah0 = sb + (q * 2 + 0) * 9216u;
            const uint32_t Al0 = sb + (q * 2 + 1) * 9216u;

            #pragma unroll
            for (int ks = 0; ks < 2; ks++){
                const int g = 2 * ks + lk;
                uint32_t ah[4], al[4], bh[2][4];
                ldmx4(ah, Ah0 + aOff + ((uint32_t)(g ^ xorA) << 4));
                ldmx4(al, Al0 + aOff + ((uint32_t)(g ^ xorA) << 4));
                ldmx4(bh[0], Bh0 + (uint32_t)offB0 * 64u + ((uint32_t)(g ^ xb0) << 4));
                ldmx4(bh[1], Bh0 + (uint32_t)offB1 * 64u + ((uint32_t)(g ^ xb1) << 4));
                #pragma unroll
                for (int nf = 0; nf < 2; nf++)
                    #pragma unroll
                    for (int sub = 0; sub < 2; sub++){
                        const int f = nf * 2 + sub;
                        mma16816(acc[f], ah, bh[nf][sub], bh[nf][2 + sub]);
                        mma16816(acc[f], al, bh[nf][sub], bh[nf][2 + sub]);
                    }
            }
        }

        if (q == 7){
            const int h = h0 + hl;
            #pragma unroll
            for (int f = 0; f < 4; f++){
                const int nf = f >> 1, sub = f & 1;
                const int nb = nf * 16 + sub * 8 + (lane & 3) * 2;
                #pragma unroll
                for (int e = 0; e < 2; e++){
                    const int n = nb + e;
                    #pragma unroll
                    for (int mh = 0; mh < 2; mh++){
                        const int m = (lane >> 2) + mh * 8;
                        const int w = w0 + m;
                        const int dj = n - m;
                        const int u = w0 - 8 + n;
                        if (dj >= 0 && dj <= 16){
                            float o = (valid && u >= 0 && u < W) ? acc[f][mh * 2 + e] : 0.f;
                            corr[(((long)b * 289 + dy * 17 + dj) * H + h) * W + w] = o;
                        }
                    }
                }
            }
        }
        __syncthreads();
    }
}

// ================= merged map-act pack (chunk-range, lo for chunks < loEnd) =================
struct PackMapParams {
    const float* x[4];
    const float* rx[4];
    const float* corr[4];
    __half* Ph[4];
    __half* Pl[4];
    int H[4];
    int npb[4];
    int blkBase[5];
    int cBeg;
    int loEnd;   // chunks with index < loEnd also write the lo plane
};
__global__ void k_pack_map_all(const __grid_constant__ PackMapParams P){
    __shared__ float t[32][33];
    const int bid = blockIdx.x;
    int l = 0;
    if (bid >= P.blkBase[1]) l = 1;
    if (bid >= P.blkBase[2]) l = 2;
    if (bid >= P.blkBase[3]) l = 3;
    const int rel = bid - P.blkBase[l];
    const int npb = P.npb[l];
    const int bxp = rel % npb;
    const int chunk = P.cBeg + rel / npb;
    const int c0  = chunk * 32;
    const int H = P.H[l], W = H;
    const int Hp = H + 2, Wp = W + 2, HW = H * W, Np = 2 * Hp * Wp;
    const int p0 = bxp * 32;

    int px = p0 + threadIdx.x;
    int b = 0, pix = 0; bool inter = false;
    if (px < Np){
        b = px / (Hp * Wp); int r = px % (Hp * Wp); int hp = r / Wp, wp = r % Wp;
        if (hp >= 1 && hp <= H && wp >= 1 && wp <= W){ inter = true; pix = (hp - 1) * W + (wp - 1); }
    }
    const float* X  = P.x[l];
    const float* RX = P.rx[l];
    const float* CR = P.corr[l];
    #pragma unroll
    for (int dyy = 0; dyy < 32; dyy += 8){
        int ci = c0 + (int)threadIdx.y + dyy;
        float v = 0.f;
        if (inter){
            if (ci < 256)       v = X [(size_t)(b * 256 + ci) * HW + pix];
            else if (ci < 512)  v = RX[(size_t)(b * 256 + ci - 256) * HW + pix];
            else if (ci < 801)  v = CR[(size_t)(b * 289 + ci - 512) * HW + pix];
        }
        t[threadIdx.y + dyy][threadIdx.x] = v;
    }
    __syncthreads();
    int ft = threadIdx.y * 32 + threadIdx.x;
    int pl = ft >> 3, sub = ft & 7;
    int px2 = p0 + pl;
    if (px2 < Np){
        size_t chStride = (size_t)2 * Hp * Wp * 32;
        int gsw = (sub >> 1) ^ ((px2 >> 1) & 3);
        size_t base = (size_t)chunk * chStride + (size_t)px2 * 32 + (gsw << 3) + (sub & 1) * 4;
        float v0 = t[sub*4+0][pl], v1 = t[sub*4+1][pl], v2 = t[sub*4+2][pl], v3 = t[sub*4+3][pl];
        __half h0 = __float2half_rn(v0), h1 = __float2half_rn(v1);
        __half h2 = __float2half_rn(v2), h3 = __float2half_rn(v3);
        uint32_t uh0 = (uint32_t)__half_as_ushort(h0) | ((uint32_t)__half_as_ushort(h1) << 16);
        uint32_t uh1 = (uint32_t)__half_as_ushort(h2) | ((uint32_t)__half_as_ushort(h3) << 16);
        uint2 wh; wh.x = uh0; wh.y = uh1;
        *reinterpret_cast<uint2*>(P.Ph[l] + base) = wh;
        if (chunk < P.loEnd){
            __half l0 = __float2half_rn(v0 - __half2float(h0));
            __half l1 = __float2half_rn(v1 - __half2float(h1));
            __half l2 = __float2half_rn(v2 - __half2float(h2));
            __half l3 = __float2half_rn(v3 - __half2float(h3));
            uint32_t ul0 = (uint32_t)__half_as_ushort(l0) | ((uint32_t)__half_as_ushort(l1) << 16);
            uint32_t ul1 = (uint32_t)__half_as_ushort(l2) | ((uint32_t)__half_as_ushort(l3) << 16);
            uint2 wl; wl.x = ul0; wl.y = ul1;
            *reinterpret_cast<uint2*>(P.Pl[l] + base) = wl;
        }
    }
}

// ================= merged out-act pack with fused upsample cascade (hi only) =================
struct PackOutParams {
    const float* map[4];
    __half* Ph[4];
    int H[4];
    int npb[4];
    int blkBase[5];
};
__global__ void k_pack_out_all(const __grid_constant__ PackOutParams P){
    __shared__ float t[32][33];
    const int bid = blockIdx.x;
    int l = 0;
    if (bid >= P.blkBase[1]) l = 1;
    if (bid >= P.blkBase[2]) l = 2;
    if (bid >= P.blkBase[3]) l = 3;
    const int rel = bid - P.blkBase[l];
    const int npb = P.npb[l];
    const int bxp = rel % npb;
    const int c0  = (rel / npb) * 32;
    const int H = P.H[l], W = H;
    const int Hp = H + 2, Wp = W + 2, Np = 2 * Hp * Wp;
    const int p0 = bxp * 32;

    int px = p0 + threadIdx.x;
    int b = 0, hh = 0, ww = 0; bool inter = false;
    if (px < Np){
        b = px / (Hp * Wp); int r = px % (Hp * Wp); int hp = r / Wp, wp = r % Wp;
        if (hp >= 1 && hp <= H && wp >= 1 && wp <= W){ inter = true; hh = hp - 1; ww = wp - 1; }
    }
    #pragma unroll
    for (int dyy = 0; dyy < 32; dyy += 8){
        int ci = c0 + (int)threadIdx.y + dyy;
        float v = 0.f;
        if (inter){
            for (int k = l; k < 4; k++){
                int Wk = P.H[k];
                int sh = k - l;
                v += P.map[k][((size_t)(b * 256 + ci) * Wk + (hh >> sh)) * Wk + (ww >> sh)];
            }
        }
        t[threadIdx.y + dyy][threadIdx.x] = v;
    }
    __syncthreads();
    int ft = threadIdx.y * 32 + threadIdx.x;
    int pl = ft >> 3, sub = ft & 7;
    int px2 = p0 + pl;
    if (px2 < Np){
        size_t chStride = (size_t)2 * Hp * Wp * 32;
        int gsw = (sub >> 1) ^ ((px2 >> 1) & 3);
        size_t base = (size_t)(c0 >> 5) * chStride + (size_t)px2 * 32 + (gsw << 3) + (sub & 1) * 4;
        float v0 = t[sub*4+0][pl], v1 = t[sub*4+1][pl], v2 = t[sub*4+2][pl], v3 = t[sub*4+3][pl];
        __half h0 = __float2half_rn(v0), h1 = __float2half_rn(v1);
        __half h2 = __float2half_rn(v2), h3 = __float2half_rn(v3);
        uint32_t uh0 = (uint32_t)__half_as_ushort(h0) | ((uint32_t)__half_as_ushort(h1) << 16);
        uint32_t uh1 = (uint32_t)__half_as_ushort(h2) | ((uint32_t)__half_as_ushort(h3) << 16);
        uint2 wh; wh.x = uh0; wh.y = uh1;
        *reinterpret_cast<uint2*>(P.Ph[l] + base) = wh;
    }
}

// ================= merged multi-level fp16 implicit-conv GEMM =================
struct GemmParams {
    const __half* A;
    const __half* BhB;
    const __half* BlB;
    float*        out[4];
    const float*  bias[4];
    long aOff[4];
    long bOff[4];
    int  H[4];
    int  lgW[4];
    int  zc[4];
    int  tpz[4];
    int  blkBase[5];
    int  CH;
    int  loBeg;
};

__global__ __launch_bounds__(256)
void k_gemm(const __grid_constant__ GemmParams P)
{
    extern __shared__ char dsm[];
    __shared__ __align__(8) unsigned long long mb[6];

    const int bid = blockIdx.x;
    int l = 0;
    if (bid >= P.blkBase[1]) l = 1;
    if (bid >= P.blkBase[2]) l = 2;
    if (bid >= P.blkBase[3]) l = 3;
    const int rel = bid - P.blkBase[l];
    const int zc = P.zc[l], tapsPerZ = P.tpz[l];
    const int zi = rel % zc;
    const int tt = rel / zc;
    const int m0 = (tt & 1) * 128;
    const int nt = tt >> 1;
    const int H = P.H[l], W = H, lgW = P.lgW[l];
    const __half* A  = P.A   + P.aOff[l];
    const __half* Bh = P.BhB + P.bOff[l];
    const __half* Bl = P.BlB + P.bOff[l];
    float* out = P.out[l];
    const float* bias = P.bias[l];
    const int useAtomic = (zc > 1);
    const int tapBeg = zi * tapsPerZ;
    const int CH = P.CH;
    const int loBeg = P.loBeg;

    const uint32_t smemBase = smem_u32(dsm);
    uint32_t A_OFF[4], B_OFF[2];
    #pragma unroll
    for (int s = 0; s < 4; s++) A_OFF[s] = smemBase + s * 8192u;
    B_OFF[0] = smemBase + 32768u;
    B_OFF[1] = smemBase + 32768u + 66560u;
    const uint32_t MBA = smem_u32(&mb[0]);
    const uint32_t MBB = smem_u32(&mb[4]);

    const int tid = threadIdx.x, wid = tid >> 5, lane = tid & 31;
    const int R = 256 >> lgW;
    const int Hp = H + 2, Wp = W + 2;
    const int tilesPerB = H / R;
    const int b  = nt / tilesPerB;
    const int h0 = (nt % tilesPerB) * R;
    const int q0 = (b * Hp + h0) * Wp;
    const uint32_t Bbytes = (uint32_t)(R + 2) * Wp * 64u;
    const size_t chStride = (size_t)2 * Hp * Wp * 32;

    if (tid == 0){
        #pragma unroll
        for (int i = 0; i < 6; i++) mbar_init(MBA + i * 8, 1);
    }
    __syncthreads();

    const int nA = CH * tapsPerZ;

    auto issueA = [&](int ia){
        int c = ia / tapsPerZ, tap = ia % tapsPerZ;
        const __half* src = A + ((((size_t)c * 9 + (tapBeg + tap)) * 256 + m0) << 5);
        int s = ia & 3;
        mbar_expect(MBA + s * 8, 8192u);
        bulk_cp(A_OFF[s], src, 8192u, MBA + s * 8);
    };
    auto issueB = [&](int c){
        int s = c & 1;
        bool lo = (c >= loBeg);
        mbar_expect(MBB + s * 8, lo ? 2u * Bbytes : Bbytes);
        bulk_cp(B_OFF[s], Bh + (size_t)c * chStride + ((size_t)q0 << 5), Bbytes, MBB + s * 8);
        if (lo)
            bulk_cp(B_OFF[s] + 33280u, Bl + (size_t)c * chStride + ((size_t)q0 << 5), Bbytes, MBB + s * 8);
    };

    const int lr  = lane & 7;
    const int lm8 = ((lane >> 3) & 1) * 8;
    const int lk  = lane >> 4;
    const int wm  = wid & 1;
    const int wn  = wid >> 1;
    const int rowA = wm * 64 + lm8 + lr;
    const int xorA = (lr >> 1) & 3;
    int rB[4], wB[4];
    #pragma unroll
    for (int g = 0; g < 4; g++){
        int n = wn * 64 + g * 16 + lm8 + lr;
        rB[g] = n >> lgW;
        wB[g] = n & (W - 1);
    }

    float acc[4][8][4];
    #pragma unroll
    for (int i = 0; i < 4; i++)
        #pragma unroll
        for (int j = 0; j < 8; j++)
            #pragma unroll
            for (int k = 0; k < 4; k++) acc[i][j][k] = 0.f;

    if (tid == 0){
        issueB(0);
        issueA(0);
        if (nA > 1) issueA(1);
        if (nA > 2) issueA(2);
    }

    for (int it = 0; it < nA; ++it){
        int c = it / tapsPerZ, tap = it % tapsPerZ;
        if (tid == 0){
            if (it + 3 < nA) issueA(it + 3);
            if (tap == 0 && c + 1 < CH) issueB(c + 1);
        }
        mbar_wait(MBA + (it & 3) * 8, (it >> 2) & 1);
        if (tap == 0) mbar_wait(MBB + (c & 1) * 8, (c >> 1) & 1);

        const uint32_t Ab = A_OFF[it & 3];
        const uint32_t Bb = B_OFF[c & 1];
        const int tIdx = tapBeg + tap;
        const int dy = tIdx / 3, dx = tIdx - dy * 3;
        const int nPass = (c >= loBeg) ? 2 : 1;

        uint32_t sAdr[4]; int xorB[4];
        #pragma unroll
        for (int g = 0; g < 4; g++){
            int s = (rB[g] + dy) * Wp + wB[g] + dx;
            sAdr[g] = Bb + (uint32_t)s * 64u;
            xorB[g] = ((q0 + s) >> 1) & 3;
        }

        #pragma unroll
        for (int ks = 0; ks < 2; ks++){
            const int gA = (2 * ks + lk) ^ xorA;
            uint32_t a[4][4];
            #pragma unroll
            for (int ma = 0; ma < 4; ma++)
                ldmx4(a[ma], Ab + (uint32_t)(rowA + ma * 16) * 64u + ((uint32_t)gA << 4));
            for (int pass = 0; pass < nPass; pass++){
                uint32_t bb[4][4];
                #pragma unroll
                for (int g = 0; g < 4; g++){
                    int gB = (2 * ks + lk) ^ xorB[g];
                    ldmx4(bb[g], sAdr[g] + (uint32_t)pass * 33280u + ((uint32_t)gB << 4));
                }
                #pragma unroll
                for (int ma = 0; ma < 4; ma++)
                    #pragma unroll
                    for (int na = 0; na < 8; na++)
                        mma16816(acc[ma][na], a[ma], bb[na >> 1][na & 1], bb[na >> 1][2 + (na & 1)]);
            }
        }
        __syncthreads();
    }

    #pragma unroll
    for (int ma = 0; ma < 4; ma++){
        int co0 = m0 + wm * 64 + ma * 16 + (lane >> 2);
        int co1 = co0 + 8;
        float bv0 = useAtomic ? 0.f : bias[co0];
        float bv1 = useAtomic ? 0.f : bias[co1];
        #pragma unroll
        for (int na = 0; na < 8; na++){
            int n = wn * 64 + na * 8 + (lane & 3) * 2;
            int r = h0 + (n >> lgW);
            int w = n & (W - 1);
            size_t i0 = ((size_t)(b * 256 + co0) * H + r) * W + w;
            size_t i1 = ((size_t)(b * 256 + co1) * H + r) * W + w;
            if (useAtomic){
                atomicAdd(&out[i0],     acc[ma][na][0]);
                atomicAdd(&out[i0 + 1], acc[ma][na][1]);
                atomicAdd(&out[i1],     acc[ma][na][2]);
                atomicAdd(&out[i1 + 1], acc[ma][na][3]);
            } else {
                float2 v0; v0.x = acc[ma][na][0] + bv0; v0.y = acc[ma][na][1] + bv0;
                float2 v1; v1.x = acc[ma][na][2] + bv1; v1.y = acc[ma][na][3] + bv1;
                *reinterpret_cast<float2*>(&out[i0]) = v0;
                *reinterpret_cast<float2*>(&out[i1]) = v1;
            }
        }
    }
}

// ---------------- host orchestration (8 launches total) ----------------
extern "C" void kernel_launch(void* const* d_in, const int* in_sizes, int n_in,
                              void* d_out, int out_size)
{
    const float *x[4]={0,0,0,0}, *rx[4]={0,0,0,0};
    const float *wm[4]={0,0,0,0}, *bm[4]={0,0,0,0}, *wo[4]={0,0,0,0}, *bo[4]={0,0,0,0};
    int wmi = 0, woi = 0, bi = 0;
    for (int i = 0; i < n_in; i++){
        int s = in_sizes[i];
        int lvl = -1;
        if      (s == 2*256*128*128) lvl = 0;
        else if (s == 2*256*64*64)   lvl = 1;
        else if (s == 2*256*32*32)   lvl = 2;
        else if (s == 2*256*16*16)   lvl = 3;
        if (lvl >= 0){
            if (!x[lvl]) x[lvl] = (const float*)d_in[i];
            else         rx[lvl] = (const float*)d_in[i];
        }
        else if (s == 1845504) wm[wmi++] = (const float*)d_in[i];
        else if (s ==  589824) wo[woi++] = (const float*)d_in[i];
        else if (s ==     256){
            if ((bi & 1) == 0) bm[bi >> 1] = (const float*)d_in[i];
            else               bo[bi >> 1] = (const float*)d_in[i];
            bi++;
        }
    }

    float *corrB, *mapB;
    __half *wmh, *woh, *amh, *aml, *aoh, *aol;
    cudaGetSymbolAddress((void**)&corrB, g_corr);
    cudaGetSymbolAddress((void**)&mapB,  g_map);
    cudaGetSymbolAddress((void**)&wmh, g_wm_h);
    cudaGetSymbolAddress((void**)&woh, g_wo_h);
    cudaGetSymbolAddress((void**)&amh, g_am_h); cudaGetSymbolAddress((void**)&aml, g_am_l);
    cudaGetSymbolAddress((void**)&aoh, g_ao_h); cudaGetSymbolAddress((void**)&aol, g_ao_l);

    cudaFuncSetAttribute(k_gemm, cudaFuncAttributeMaxDynamicSharedMemorySize, 165888);
    cudaFuncSetAttribute(k_corr_mma, cudaFuncAttributeMaxDynamicSharedMemorySize, 169984);

    const int  Hl[4]      = {128, 64, 32, 16};
    const int  lgWl[4]    = {7, 6, 5, 4};
    const int  HWl[4]     = {16384, 4096, 1024, 256};
    const long corrOff[4] = {0, 9469952, 11837440, 12429312};
    const long mapOff[4]  = {0, 8388608, 10485760, 11010048};
    const long amOff[4]   = {0, 28121600, 35369984, 37293568};
    const long aoOff[4]   = {0, 8652800, 10883072, 11474944};
    const long wmOff[4]   = {0, 1916928, 3833856, 5750784};
    const long woOff[4]   = {0, 589824, 1179648, 1769472};
    const int  zl[4]      = {1, 3, 9, 9};
    const int  tpzl[4]    = {9, 3, 1, 1};
    float* outp = (float*)d_out;

    int gemmBase[5]; gemmBase[0] = 0;
    for (int l = 0; l < 4; l++)
        gemmBase[l + 1] = gemmBase[l] + (2 * HWl[l] / 256) * 2 * zl[l];  // {0,256,448,592,628}

    int npbl[4];
    for (int l = 0; l < 4; l++){
        int Np = 2 * (Hl[l] + 2) * (Hl[l] + 2);
        npbl[l] = (Np + 31) / 32;
    }

    // ---- launch 0: init all atomic output buffers (map+out, levels 1-3) ----
    {
        InitParams P;
        long tot = 0;
        for (int r = 0; r < 3; r++){
            int l = r + 1;
            P.out[r] = mapB + mapOff[l]; P.bias[r] = bm[l]; P.HW[r] = HWl[l];
            P.base[r] = tot; tot += 2L * 256 * HWl[l];
        }
        for (int r = 0; r < 3; r++){
            int l = r + 1;
            P.out[3 + r] = outp + mapOff[l]; P.bias[3 + r] = bo[l]; P.HW[3 + r] = HWl[l];
            P.base[3 + r] = tot; tot += 2L * 256 * HWl[l];
        }
        P.base[6] = tot;
        k_init_all<<<(int)((tot + 255) / 256), 256>>>(P);
    }
    // ---- launch 1: pack all weights ----
    {
        PackWParams P;
        long tot = 0;
        for (int l = 0; l < 4; l++){
            P.src[l] = wm[l]; P.dst[l] = wmh + wmOff[l]; P.Cin[l] = 801; P.Cpad[l] = 832;
            P.base[l] = tot; tot += 256L * 832;
        }
        for (int l = 0; l < 4; l++){
            P.src[4+l] = wo[l]; P.dst[4+l] = woh + woOff[l]; P.Cin[4+l] = 256; P.Cpad[4+l] = 256;
            P.base[4+l] = tot; tot += 256L * 256;
        }
        P.base[8] = tot;
        k_pack_w_all<<<(int)((tot + 255) / 256), 256>>>(P);
    }
    // ---- launch 2: pack x/rx activation chunks (0-15), lo only for x (chunks 0-7) ----
    {
        PackMapParams P;
        int base = 0;
        for (int l = 0; l < 4; l++){
            P.x[l] = x[l]; P.rx[l] = rx[l]; P.corr[l] = corrB + corrOff[l];
            P.Ph[l] = amh + amOff[l]; P.Pl[l] = aml + amOff[l];
            P.H[l] = Hl[l]; P.npb[l] = npbl[l];
            P.blkBase[l] = base;
            base += npbl[l] * 16;
        }
        P.blkBase[4] = base;
        P.cBeg = 0;
        P.loEnd = 8;   // only x-lo needed (corr-MMA A-side)
        k_pack_map_all<<<base, dim3(32, 8)>>>(P);
    }
    // ---- launch 3: MMA correlation (2-pass: fp32(x) * fp16(r)) ----
    {
        CorrMMAParams P;
        int base = 0;
        for (int l = 0; l < 4; l++){
            P.Xh[l] = amh + amOff[l];
            P.Xl[l] = aml + amOff[l];
            P.out[l] = corrB + corrOff[l];
            P.H[l] = Hl[l];
            P.chS[l] = 2L * (Hl[l] + 2) * (Hl[l] + 2) * 32;
            P.blkBase[l] = base;
            int RPB = 128 / Hl[l];
            base += 2 * Hl[l] / RPB;
        }
        P.blkBase[4] = base;
        k_corr_mma<<<base, 256, 169984>>>(P);
    }
    // ---- launch 4: pack corr activation chunks (16-25), hi only ----
    {
        PackMapParams P;
        int base = 0;
        for (int l = 0; l < 4; l++){
            P.x[l] = x[l]; P.rx[l] = rx[l]; P.corr[l] = corrB + corrOff[l];
            P.Ph[l] = amh + amOff[l]; P.Pl[l] = aml + amOff[l];
            P.H[l] = Hl[l]; P.npb[l] = npbl[l];
            P.blkBase[l] = base;
            base += npbl[l] * 10;
        }
        P.blkBase[4] = base;
        P.cBeg = 16;
        P.loEnd = 0;   // map GEMM is fully single-pass
        k_pack_map_all<<<base, dim3(32, 8)>>>(P);
    }
    // ---- launch 5: merged map GEMM (fully single-pass) ----
    {
        GemmParams P;
        P.A = wmh; P.BhB = amh; P.BlB = aml;
        for (int l = 0; l < 4; l++){
            P.out[l] = mapB + mapOff[l]; P.bias[l] = bm[l];
            P.aOff[l] = wmOff[l]; P.bOff[l] = amOff[l];
            P.H[l] = Hl[l]; P.lgW[l] = lgWl[l]; P.zc[l] = zl[l]; P.tpz[l] = tpzl[l];
        }
        for (int i = 0; i < 5; i++) P.blkBase[i] = gemmBase[i];
        P.CH = 26;
        P.loBeg = 26;
        k_gemm<<<gemmBase[4], 256, 165888>>>(P);
    }
    // ---- launch 6: pack out activations (hi only) with fused upsample cascade ----
    {
        PackOutParams P;
        int base = 0;
        for (int l = 0; l < 4; l++){
            P.map[l] = mapB + mapOff[l];
            P.Ph[l] = aoh + aoOff[l];
            P.H[l] = Hl[l]; P.npb[l] = npbl[l];
            P.blkBase[l] = base;
            base += npbl[l] * 8;
        }
        P.blkBase[4] = base;
        k_pack_out_all<<<base, dim3(32, 8)>>>(P);
    }
    // ---- launch 7: merged out GEMM -> d_out (single-pass) ----
    {
        GemmParams P;
        P.A = woh; P.BhB = aoh; P.BlB = aol;
        for (int l = 0; l < 4; l++){
            P.out[l] = outp + mapOff[l]; P.bias[l] = bo[l];
            P.aOff[l] = woOff[l]; P.bOff[l] = aoOff[l];
            P.H[l] = Hl[l]; P.lgW[l] = lgWl[l]; P.zc[l] = zl[l]; P.tpz[l] = tpzl[l];
        }
        for (int i = 0; i < 5; i++) P.blkBase[i] = gemmBase[i];
        P.CH = 8;
        P.loBeg = 8;
        k_gemm<<<gemmBase[4], 256, 165888>>>(P);
    }
}

// round 16
// speedup vs baseline: 2.2356x; 1.0443x over previous
#include <cuda_runtime.h>
#include <cuda_fp16.h>
#include <cstdint>
#include <cstddef>

#define PADC 8

// ---------------- static device buffers ----------------
__device__ __align__(256) float g_corr[12577280];
__device__ __align__(256) float g_map [11141120];
__device__ __align__(256) __half g_wm_h[7667712];   // [lvl][chunk26][tap9][co256][ci32] swizzled
__device__ __align__(256) __half g_wo_h[2359296];   // [lvl][chunk8][tap9][co256][ci32]
__device__ __align__(256) __half g_am_h[37832704];  // [lvl][chunk][b][Hp][Wp][32] swizzled
__device__ __align__(256) __half g_am_l[37832704];
__device__ __align__(256) __half g_ao_h[11640832];
__device__ __align__(256) __half g_ao_l[11640832];

// ---------------- PTX helpers (compute_103 baseline-safe) ----------------
__device__ __forceinline__ uint32_t smem_u32(const void* p){
    uint32_t a;
    asm("{ .reg .u64 t; cvta.to.shared.u64 t, %1; cvt.u32.u64 %0, t; }" : "=r"(a) : "l"(p));
    return a;
}
__device__ __forceinline__ void mbar_init(uint32_t a, uint32_t cnt){
    asm volatile("mbarrier.init.shared.b64 [%0], %1;" :: "r"(a), "r"(cnt) : "memory");
}
__device__ __forceinline__ void mbar_expect(uint32_t a, uint32_t bytes){
    asm volatile("mbarrier.arrive.expect_tx.shared.b64 _, [%0], %1;" :: "r"(a), "r"(bytes) : "memory");
}
__device__ __forceinline__ void mbar_wait(uint32_t a, int parity){
    asm volatile(
        "{\n\t.reg .pred P;\n\t"
        "WL_%=:\n\t"
        "mbarrier.try_wait.parity.acquire.cta.shared::cta.b64 P, [%0], %1, 0x989680;\n\t"
        "@P bra WD_%=;\n\t"
        "bra WL_%=;\n\t"
        "WD_%=:\n\t}"
        :: "r"(a), "r"(parity) : "memory");
}
__device__ __forceinline__ void bulk_cp(uint32_t dst, const void* src, uint32_t bytes, uint32_t mbar){
    asm volatile(
        "cp.async.bulk.shared::cluster.global.mbarrier::complete_tx::bytes [%0], [%1], %2, [%3];"
        :: "r"(dst), "l"(src), "r"(bytes), "r"(mbar) : "memory");
}
__device__ __forceinline__ void ldmx4(uint32_t* r, uint32_t addr){
    asm volatile("ldmatrix.sync.aligned.m8n8.x4.shared.b16 {%0,%1,%2,%3}, [%4];"
                 : "=r"(r[0]), "=r"(r[1]), "=r"(r[2]), "=r"(r[3]) : "r"(addr));
}
__device__ __forceinline__ void mma16816(float* c, const uint32_t* a, uint32_t b0, uint32_t b1){
    asm volatile(
        "mma.sync.aligned.m16n8k16.row.col.f32.f16.f16.f32 "
        "{%0,%1,%2,%3}, {%4,%5,%6,%7}, {%8,%9}, {%0,%1,%2,%3};"
        : "+f"(c[0]), "+f"(c[1]), "+f"(c[2]), "+f"(c[3])
        : "r"(a[0]), "r"(a[1]), "r"(a[2]), "r"(a[3]), "r"(b0), "r"(b1));
}

// ================= merged init bias (6 regions) =================
struct InitParams {
    float* out[6];
    const float* bias[6];
    int HW[6];
    long base[7];
};
__global__ void k_init_all(const __grid_constant__ InitParams P){
    long i = (long)blockIdx.x * blockDim.x + threadIdx.x;
    if (i >= P.base[6]) return;
    int r = 0;
    #pragma unroll
    for (int k = 1; k < 6; k++) if (i >= P.base[k]) r = k;
    long loc = i - P.base[r];
    P.out[r][loc] = P.bias[r][(loc / P.HW[r]) & 255];
}

// ================= merged weight pack (8 tensors) =================
struct PackWParams {
    const float* src[8];
    __half* dst[8];
    int Cin[8];
    int Cpad[8];
    long base[9];
};
__global__ void k_pack_w_all(const __grid_constant__ PackWParams P){
    long i = (long)blockIdx.x * 256 + threadIdx.x;
    if (i >= P.base[8]) return;
    int t = 0;
    #pragma unroll
    for (int k = 1; k < 8; k++) if (i >= P.base[k]) t = k;
    long loc = i - P.base[t];
    int Cpad = P.Cpad[t], Cin = P.Cin[t];
    int co = (int)(loc / Cpad), ci = (int)(loc % Cpad);
    int c = ci >> 5, cl = ci & 31;
    int gsw = (cl >> 3) ^ ((co >> 1) & 3);
    const float* w = P.src[t];
    __half* oh = P.dst[t];
    #pragma unroll
    for (int tap = 0; tap < 9; tap++){
        float v = (ci < Cin) ? w[(size_t)(co * Cin + ci) * 9 + tap] : 0.f;
        size_t o = (((size_t)c * 9 + tap) * 256 + co) * 32 + (gsw << 3) + (cl & 7);
        oh[o] = __float2half_rn(v);
    }
}

// ================= MMA correlation: corr[w,dj] = band of X^T R =================
// 2-pass (fp32(x) * fp16(r)), TWO ci-chunks per pipeline stage (17*4 stages).
struct CorrMMAParams {
    const __half* Xh[4];
    const __half* Xl[4];
    float* out[4];
    int H[4];
    long chS[4];
    int blkBase[5];
};
__global__ __launch_bounds__(256)
void k_corr_mma(const __grid_constant__ CorrMMAParams P)
{
    extern __shared__ char dsm[];
    __shared__ __align__(8) unsigned long long mb[3];

    const int bid = blockIdx.x;
    int l = 0;
    if (bid >= P.blkBase[1]) l = 1;
    if (bid >= P.blkBase[2]) l = 2;
    if (bid >= P.blkBase[3]) l = 3;
    const int rel = bid - P.blkBase[l];
    const int H = P.H[l], W = H, Hp = H + 2, Wp = W + 2;
    const int WT = W >> 4;
    const int RPB = 8 / WT;
    const int HB = H / RPB;
    const int b  = rel / HB;
    const int h0 = (rel % HB) * RPB;
    const long chS = P.chS[l];
    const __half* Xh = P.Xh[l];
    const __half* Xl = P.Xl[l];
    float* corr = P.out[l];

    const uint32_t sb = smem_u32(dsm);
    const uint32_t BB = sb + 147456u;        // B bufs: 2 x 20480 (2 hi planes each)
    const uint32_t MBA = smem_u32(&mb[0]);
    const uint32_t MBB = smem_u32(&mb[1]);

    const int tid = threadIdx.x, wid = tid >> 5, lane = tid & 31;
    const int wt = wid % WT, hl = wid / WT;
    const int w0 = wt * 16;
    const int lr = lane & 7, lm8 = ((lane >> 3) & 1) * 8, lk = lane >> 4;

    if (tid == 0){
        mbar_init(MBA, 1);
        mbar_init(MBB, 1);
        mbar_init(MBB + 8, 1);
    }
    __syncthreads();

    const long pA0 = (long)(b * Hp + h0 + 1) * Wp + 1;
    const uint32_t Abytes = (uint32_t)(((RPB - 1) * Wp + W) * 64);

    if (tid == 0){
        mbar_expect(MBA, 16u * Abytes);
        #pragma unroll
        for (int q = 0; q < 8; q++){
            bulk_cp(sb + (q * 2 + 0) * 9216u, Xh + (size_t)q * chS + pA0 * 32, Abytes, MBA);
            bulk_cp(sb + (q * 2 + 1) * 9216u, Xl + (size_t)q * chS + pA0 * 32, Abytes, MBA);
        }
    }

    // stage s: dy = s>>2, chunk pair q2 = s&3 -> chunks {2*q2, 2*q2+1}
    auto issueB = [&](int s){
        int dy = s >> 2, q2 = s & 3;
        int r0 = h0 + dy - 8;
        int rc0 = (r0 < -1) ? -1 : r0;
        int rc1 = r0 + RPB - 1; if (rc1 > H) rc1 = H;
        if (rc1 < rc0){ rc0 = h0; rc1 = h0; }
        long pB0 = (long)(b * Hp + rc0 + 1) * Wp - 7;
        uint32_t Bb = (uint32_t)(((rc1 - rc0) * Wp + W + 16) * 64);
        int buf = s & 1;
        mbar_expect(MBB + buf * 8, 2u * Bb);
        bulk_cp(BB + buf * 20480u,           Xh + (size_t)(8 + 2 * q2)     * chS + pB0 * 32, Bb, MBB + buf * 8);
        bulk_cp(BB + buf * 20480u + 10240u,  Xh + (size_t)(8 + 2 * q2 + 1) * chS + pB0 * 32, Bb, MBB + buf * 8);
    };

    if (tid == 0) issueB(0);
    mbar_wait(MBA, 0);

    const int offA_px = hl * Wp + w0 + lm8 + lr;
    const int xorA = (int)(((pA0 + offA_px) >> 1) & 3);
    const uint32_t aOff = (uint32_t)offA_px * 64u;

    float acc[4][4];
    const int nStages = 17 * 4;

    for (int s = 0; s < nStages; ++s){
        const int dy = s >> 2, q2 = s & 3;
        if (tid == 0 && s + 1 < nStages) issueB(s + 1);
        mbar_wait(MBB + (s & 1) * 8, (s >> 1) & 1);

        if (q2 == 0){
            #pragma unroll
            for (int f = 0; f < 4; f++)
                #pragma unroll
                for (int e = 0; e < 4; e++) acc[f][e] = 0.f;
        }

        int r0 = h0 + dy - 8;
        int rc0 = (r0 < -1) ? -1 : r0;
        int rc1 = r0 + RPB - 1; if (rc1 > H) rc1 = H;
        if (rc1 < rc0){ rc0 = h0; rc1 = h0; }
        const int r = h0 + hl + dy - 8;
        const bool valid = (r >= rc0 && r <= rc1);

        if (valid){
            const long pB0 = (long)(b * Hp + rc0 + 1) * Wp - 7;
            const int rowBase = (r - rc0) * Wp;
            const int offB0 = rowBase + w0 + lm8 + lr;
            const int offB1 = offB0 + 16;
            const int xb0 = (int)(((pB0 + offB0) >> 1) & 3);
            const int xb1 = (int)(((pB0 + offB1) >> 1) & 3);

            #pragma unroll
            for (int sc = 0; sc < 2; sc++){
                const int qq = 2 * q2 + sc;
                const uint32_t Bh0 = BB + (s & 1) * 20480u + (uint32_t)sc * 10240u;
                const uint32_t Ah0 = sb + (qq * 2 + 0) * 9216u;
                const uint32_t Al0 = sb + (qq * 2 + 1) * 9216u;
                #pragma unroll
                for (int ks = 0; ks < 2; ks++){
                    const int g = 2 * ks + lk;
                    uint32_t ah[4], al[4], bh[2][4];
                    ldmx4(ah, Ah0 + aOff + ((uint32_t)(g ^ xorA) << 4));
                    ldmx4(al, Al0 + aOff + ((uint32_t)(g ^ xorA) << 4));
                    ldmx4(bh[0], Bh0 + (uint32_t)offB0 * 64u + ((uint32_t)(g ^ xb0) << 4));
                    ldmx4(bh[1], Bh0 + (uint32_t)offB1 * 64u + ((uint32_t)(g ^ xb1) << 4));
                    #pragma unroll
                    for (int nf = 0; nf < 2; nf++)
                        #pragma unroll
                        for (int sub = 0; sub < 2; sub++){
                            const int f = nf * 2 + sub;
                            mma16816(acc[f], ah, bh[nf][sub], bh[nf][2 + sub]);
                            mma16816(acc[f], al, bh[nf][sub], bh[nf][2 + sub]);
                        }
                }
            }
        }

        if (q2 == 3){
            const int h = h0 + hl;
            #pragma unroll
            for (int f = 0; f < 4; f++){
                const int nf = f >> 1, sub = f & 1;
                const int nb = nf * 16 + sub * 8 + (lane & 3) * 2;
                #pragma unroll
                for (int e = 0; e < 2; e++){
                    const int n = nb + e;
                    #pragma unroll
                    for (int mh = 0; mh < 2; mh++){
                        const int m = (lane >> 2) + mh * 8;
                        const int w = w0 + m;
                        const int dj = n - m;
                        const int u = w0 - 8 + n;
                        if (dj >= 0 && dj <= 16){
                            float o = (valid && u >= 0 && u < W) ? acc[f][mh * 2 + e] : 0.f;
                            corr[(((long)b * 289 + dy * 17 + dj) * H + h) * W + w] = o;
                        }
                    }
                }
            }
        }
        __syncthreads();
    }
}

// ================= merged map-act pack (chunk-range, lo for chunks < loEnd) =================
struct PackMapParams {
    const float* x[4];
    const float* rx[4];
    const float* corr[4];
    __half* Ph[4];
    __half* Pl[4];
    int H[4];
    int npb[4];
    int blkBase[5];
    int cBeg;
    int loEnd;
};
__global__ void k_pack_map_all(const __grid_constant__ PackMapParams P){
    __shared__ float t[32][33];
    const int bid = blockIdx.x;
    int l = 0;
    if (bid >= P.blkBase[1]) l = 1;
    if (bid >= P.blkBase[2]) l = 2;
    if (bid >= P.blkBase[3]) l = 3;
    const int rel = bid - P.blkBase[l];
    const int npb = P.npb[l];
    const int bxp = rel % npb;
    const int chunk = P.cBeg + rel / npb;
    const int c0  = chunk * 32;
    const int H = P.H[l], W = H;
    const int Hp = H + 2, Wp = W + 2, HW = H * W, Np = 2 * Hp * Wp;
    const int p0 = bxp * 32;

    int px = p0 + threadIdx.x;
    int b = 0, pix = 0; bool inter = false;
    if (px < Np){
        b = px / (Hp * Wp); int r = px % (Hp * Wp); int hp = r / Wp, wp = r % Wp;
        if (hp >= 1 && hp <= H && wp >= 1 && wp <= W){ inter = true; pix = (hp - 1) * W + (wp - 1); }
    }
    const float* X  = P.x[l];
    const float* RX = P.rx[l];
    const float* CR = P.corr[l];
    #pragma unroll
    for (int dyy = 0; dyy < 32; dyy += 8){
        int ci = c0 + (int)threadIdx.y + dyy;
        float v = 0.f;
        if (inter){
            if (ci < 256)       v = X [(size_t)(b * 256 + ci) * HW + pix];
            else if (ci < 512)  v = RX[(size_t)(b * 256 + ci - 256) * HW + pix];
            else if (ci < 801)  v = CR[(size_t)(b * 289 + ci - 512) * HW + pix];
        }
        t[threadIdx.y + dyy][threadIdx.x] = v;
    }
    __syncthreads();
    int ft = threadIdx.y * 32 + threadIdx.x;
    int pl = ft >> 3, sub = ft & 7;
    int px2 = p0 + pl;
    if (px2 < Np){
        size_t chStride = (size_t)2 * Hp * Wp * 32;
        int gsw = (sub >> 1) ^ ((px2 >> 1) & 3);
        size_t base = (size_t)chunk * chStride + (size_t)px2 * 32 + (gsw << 3) + (sub & 1) * 4;
        float v0 = t[sub*4+0][pl], v1 = t[sub*4+1][pl], v2 = t[sub*4+2][pl], v3 = t[sub*4+3][pl];
        __half h0 = __float2half_rn(v0), h1 = __float2half_rn(v1);
        __half h2 = __float2half_rn(v2), h3 = __float2half_rn(v3);
        uint32_t uh0 = (uint32_t)__half_as_ushort(h0) | ((uint32_t)__half_as_ushort(h1) << 16);
        uint32_t uh1 = (uint32_t)__half_as_ushort(h2) | ((uint32_t)__half_as_ushort(h3) << 16);
        uint2 wh; wh.x = uh0; wh.y = uh1;
        *reinterpret_cast<uint2*>(P.Ph[l] + base) = wh;
        if (chunk < P.loEnd){
            __half l0 = __float2half_rn(v0 - __half2float(h0));
            __half l1 = __float2half_rn(v1 - __half2float(h1));
            __half l2 = __float2half_rn(v2 - __half2float(h2));
            __half l3 = __float2half_rn(v3 - __half2float(h3));
            uint32_t ul0 = (uint32_t)__half_as_ushort(l0) | ((uint32_t)__half_as_ushort(l1) << 16);
            uint32_t ul1 = (uint32_t)__half_as_ushort(l2) | ((uint32_t)__half_as_ushort(l3) << 16);
            uint2 wl; wl.x = ul0; wl.y = ul1;
            *reinterpret_cast<uint2*>(P.Pl[l] + base) = wl;
        }
    }
}

// ================= merged out-act pack with fused upsample cascade (hi only) =================
struct PackOutParams {
    const float* map[4];
    __half* Ph[4];
    int H[4];
    int npb[4];
    int blkBase[5];
};
__global__ void k_pack_out_all(const __grid_constant__ PackOutParams P){
    __shared__ float t[32][33];
    const int bid = blockIdx.x;
    int l = 0;
    if (bid >= P.blkBase[1]) l = 1;
    if (bid >= P.blkBase[2]) l = 2;
    if (bid >= P.blkBase[3]) l = 3;
    const int rel = bid - P.blkBase[l];
    const int npb = P.npb[l];
    const int bxp = rel % npb;
    const int c0  = (rel / npb) * 32;
    const int H = P.H[l], W = H;
    const int Hp = H + 2, Wp = W + 2, Np = 2 * Hp * Wp;
    const int p0 = bxp * 32;

    int px = p0 + threadIdx.x;
    int b = 0, hh = 0, ww = 0; bool inter = false;
    if (px < Np){
        b = px / (Hp * Wp); int r = px % (Hp * Wp); int hp = r / Wp, wp = r % Wp;
        if (hp >= 1 && hp <= H && wp >= 1 && wp <= W){ inter = true; hh = hp - 1; ww = wp - 1; }
    }
    #pragma unroll
    for (int dyy = 0; dyy < 32; dyy += 8){
        int ci = c0 + (int)threadIdx.y + dyy;
        float v = 0.f;
        if (inter){
            for (int k = l; k < 4; k++){
                int Wk = P.H[k];
                int sh = k - l;
                v += P.map[k][((size_t)(b * 256 + ci) * Wk + (hh >> sh)) * Wk + (ww >> sh)];
            }
        }
        t[threadIdx.y + dyy][threadIdx.x] = v;
    }
    __syncthreads();
    int ft = threadIdx.y * 32 + threadIdx.x;
    int pl = ft >> 3, sub = ft & 7;
    int px2 = p0 + pl;
    if (px2 < Np){
        size_t chStride = (size_t)2 * Hp * Wp * 32;
        int gsw = (sub >> 1) ^ ((px2 >> 1) & 3);
        size_t base = (size_t)(c0 >> 5) * chStride + (size_t)px2 * 32 + (gsw << 3) + (sub & 1) * 4;
        float v0 = t[sub*4+0][pl], v1 = t[sub*4+1][pl], v2 = t[sub*4+2][pl], v3 = t[sub*4+3][pl];
        __half h0 = __float2half_rn(v0), h1 = __float2half_rn(v1);
        __half h2 = __float2half_rn(v2), h3 = __float2half_rn(v3);
        uint32_t uh0 = (uint32_t)__half_as_ushort(h0) | ((uint32_t)__half_as_ushort(h1) << 16);
        uint32_t uh1 = (uint32_t)__half_as_ushort(h2) | ((uint32_t)__half_as_ushort(h3) << 16);
        uint2 wh; wh.x = uh0; wh.y = uh1;
        *reinterpret_cast<uint2*>(P.Ph[l] + base) = wh;
    }
}

// ================= merged multi-level fp16 implicit-conv GEMM =================
struct GemmParams {
    const __half* A;
    const __half* BhB;
    const __half* BlB;
    float*        out[4];
    const float*  bias[4];
    long aOff[4];
    long bOff[4];
    int  H[4];
    int  lgW[4];
    int  zc[4];
    int  tpz[4];
    int  blkBase[5];
    int  CH;
    int  loBeg;
};

__global__ __launch_bounds__(256)
void k_gemm(const __grid_constant__ GemmParams P)
{
    extern __shared__ char dsm[];
    __shared__ __align__(8) unsigned long long mb[6];

    const int bid = blockIdx.x;
    int l = 0;
    if (bid >= P.blkBase[1]) l = 1;
    if (bid >= P.blkBase[2]) l = 2;
    if (bid >= P.blkBase[3]) l = 3;
    const int rel = bid - P.blkBase[l];
    const int zc = P.zc[l], tapsPerZ = P.tpz[l];
    const int zi = rel % zc;
    const int tt = rel / zc;
    const int m0 = (tt & 1) * 128;
    const int nt = tt >> 1;
    const int H = P.H[l], W = H, lgW = P.lgW[l];
    const __half* A  = P.A   + P.aOff[l];
    const __half* Bh = P.BhB + P.bOff[l];
    const __half* Bl = P.BlB + P.bOff[l];
    float* out = P.out[l];
    const float* bias = P.bias[l];
    const int useAtomic = (zc > 1);
    const int tapBeg = zi * tapsPerZ;
    const int CH = P.CH;
    const int loBeg = P.loBeg;

    const uint32_t smemBase = smem_u32(dsm);
    uint32_t A_OFF[4], B_OFF[2];
    #pragma unroll
    for (int s = 0; s < 4; s++) A_OFF[s] = smemBase + s * 8192u;
    B_OFF[0] = smemBase + 32768u;
    B_OFF[1] = smemBase + 32768u + 66560u;
    const uint32_t MBA = smem_u32(&mb[0]);
    const uint32_t MBB = smem_u32(&mb[4]);

    const int tid = threadIdx.x, wid = tid >> 5, lane = tid & 31;
    const int R = 256 >> lgW;
    const int Hp = H + 2, Wp = W + 2;
    const int tilesPerB = H / R;
    const int b  = nt / tilesPerB;
    const int h0 = (nt % tilesPerB) * R;
    const int q0 = (b * Hp + h0) * Wp;
    const uint32_t Bbytes = (uint32_t)(R + 2) * Wp * 64u;
    const size_t chStride = (size_t)2 * Hp * Wp * 32;

    if (tid == 0){
        #pragma unroll
        for (int i = 0; i < 6; i++) mbar_init(MBA + i * 8, 1);
    }
    __syncthreads();

    const int nA = CH * tapsPerZ;

    auto issueA = [&](int ia){
        int c = ia / tapsPerZ, tap = ia % tapsPerZ;
        const __half* src = A + ((((size_t)c * 9 + (tapBeg + tap)) * 256 + m0) << 5);
        int s = ia & 3;
        mbar_expect(MBA + s * 8, 8192u);
        bulk_cp(A_OFF[s], src, 8192u, MBA + s * 8);
    };
    auto issueB = [&](int c){
        int s = c & 1;
        bool lo = (c >= loBeg);
        mbar_expect(MBB + s * 8, lo ? 2u * Bbytes : Bbytes);
        bulk_cp(B_OFF[s], Bh + (size_t)c * chStride + ((size_t)q0 << 5), Bbytes, MBB + s * 8);
        if (lo)
            bulk_cp(B_OFF[s] + 33280u, Bl + (size_t)c * chStride + ((size_t)q0 << 5), Bbytes, MBB + s * 8);
    };

    const int lr  = lane & 7;
    const int lm8 = ((lane >> 3) & 1) * 8;
    const int lk  = lane >> 4;
    const int wm  = wid & 1;
    const int wn  = wid >> 1;
    const int rowA = wm * 64 + lm8 + lr;
    const int xorA = (lr >> 1) & 3;
    int rB[4], wB[4];
    #pragma unroll
    for (int g = 0; g < 4; g++){
        int n = wn * 64 + g * 16 + lm8 + lr;
        rB[g] = n >> lgW;
        wB[g] = n & (W - 1);
    }

    float acc[4][8][4];
    #pragma unroll
    for (int i = 0; i < 4; i++)
        #pragma unroll
        for (int j = 0; j < 8; j++)
            #pragma unroll
            for (int k = 0; k < 4; k++) acc[i][j][k] = 0.f;

    if (tid == 0){
        issueB(0);
        issueA(0);
        if (nA > 1) issueA(1);
        if (nA > 2) issueA(2);
    }

    for (int it = 0; it < nA; ++it){
        int c = it / tapsPerZ, tap = it % tapsPerZ;
        if (tid == 0){
            if (it + 3 < nA) issueA(it + 3);
            if (tap == 0 && c + 1 < CH) issueB(c + 1);
        }
        mbar_wait(MBA + (it & 3) * 8, (it >> 2) & 1);
        if (tap == 0) mbar_wait(MBB + (c & 1) * 8, (c >> 1) & 1);

        const uint32_t Ab = A_OFF[it & 3];
        const uint32_t Bb = B_OFF[c & 1];
        const int tIdx = tapBeg + tap;
        const int dy = tIdx / 3, dx = tIdx - dy * 3;
        const int nPass = (c >= loBeg) ? 2 : 1;

        uint32_t sAdr[4]; int xorB[4];
        #pragma unroll
        for (int g = 0; g < 4; g++){
            int s = (rB[g] + dy) * Wp + wB[g] + dx;
            sAdr[g] = Bb + (uint32_t)s * 64u;
            xorB[g] = ((q0 + s) >> 1) & 3;
        }

        #pragma unroll
        for (int ks = 0; ks < 2; ks++){
            const int gA = (2 * ks + lk) ^ xorA;
            uint32_t a[4][4];
            #pragma unroll
            for (int ma = 0; ma < 4; ma++)
                ldmx4(a[ma], Ab + (uint32_t)(rowA + ma * 16) * 64u + ((uint32_t)gA << 4));
            for (int pass = 0; pass < nPass; pass++){
                uint32_t bb[4][4];
                #pragma unroll
                for (int g = 0; g < 4; g++){
                    int gB = (2 * ks + lk) ^ xorB[g];
                    ldmx4(bb[g], sAdr[g] + (uint32_t)pass * 33280u + ((uint32_t)gB << 4));
                }
                #pragma unroll
                for (int ma = 0; ma < 4; ma++)
                    #pragma unroll
                    for (int na = 0; na < 8; na++)
                        mma16816(acc[ma][na], a[ma], bb[na >> 1][na & 1], bb[na >> 1][2 + (na & 1)]);
            }
        }
        __syncthreads();
    }

    #pragma unroll
    for (int ma = 0; ma < 4; ma++){
        int co0 = m0 + wm * 64 + ma * 16 + (lane >> 2);
        int co1 = co0 + 8;
        float bv0 = useAtomic ? 0.f : bias[co0];
        float bv1 = useAtomic ? 0.f : bias[co1];
        #pragma unroll
        for (int na = 0; na < 8; na++){
            int n = wn * 64 + na * 8 + (lane & 3) * 2;
            int r = h0 + (n >> lgW);
            int w = n & (W - 1);
            size_t i0 = ((size_t)(b * 256 + co0) * H + r) * W + w;
            size_t i1 = ((size_t)(b * 256 + co1) * H + r) * W + w;
            if (useAtomic){
                atomicAdd(&out[i0],     acc[ma][na][0]);
                atomicAdd(&out[i0 + 1], acc[ma][na][1]);
                atomicAdd(&out[i1],     acc[ma][na][2]);
                atomicAdd(&out[i1 + 1], acc[ma][na][3]);
            } else {
                float2 v0; v0.x = acc[ma][na][0] + bv0; v0.y = acc[ma][na][1] + bv0;
                float2 v1; v1.x = acc[ma][na][2] + bv1; v1.y = acc[ma][na][3] + bv1;
                *reinterpret_cast<float2*>(&out[i0]) = v0;
                *reinterpret_cast<float2*>(&out[i1]) = v1;
            }
        }
    }
}

// ---------------- host orchestration (8 launches total) ----------------
extern "C" void kernel_launch(void* const* d_in, const int* in_sizes, int n_in,
                              void* d_out, int out_size)
{
    const float *x[4]={0,0,0,0}, *rx[4]={0,0,0,0};
    const float *wm[4]={0,0,0,0}, *bm[4]={0,0,0,0}, *wo[4]={0,0,0,0}, *bo[4]={0,0,0,0};
    int wmi = 0, woi = 0, bi = 0;
    for (int i = 0; i < n_in; i++){
        int s = in_sizes[i];
        int lvl = -1;
        if      (s == 2*256*128*128) lvl = 0;
        else if (s == 2*256*64*64)   lvl = 1;
        else if (s == 2*256*32*32)   lvl = 2;
        else if (s == 2*256*16*16)   lvl = 3;
        if (lvl >= 0){
            if (!x[lvl]) x[lvl] = (const float*)d_in[i];
            else         rx[lvl] = (const float*)d_in[i];
        }
        else if (s == 1845504) wm[wmi++] = (const float*)d_in[i];
        else if (s ==  589824) wo[woi++] = (const float*)d_in[i];
        else if (s ==     256){
            if ((bi & 1) == 0) bm[bi >> 1] = (const float*)d_in[i];
            else               bo[bi >> 1] = (const float*)d_in[i];
            bi++;
        }
    }

    float *corrB, *mapB;
    __half *wmh, *woh, *amh, *aml, *aoh, *aol;
    cudaGetSymbolAddress((void**)&corrB, g_corr);
    cudaGetSymbolAddress((void**)&mapB,  g_map);
    cudaGetSymbolAddress((void**)&wmh, g_wm_h);
    cudaGetSymbolAddress((void**)&woh, g_wo_h);
    cudaGetSymbolAddress((void**)&amh, g_am_h); cudaGetSymbolAddress((void**)&aml, g_am_l);
    cudaGetSymbolAddress((void**)&aoh, g_ao_h); cudaGetSymbolAddress((void**)&aol, g_ao_l);

    cudaFuncSetAttribute(k_gemm, cudaFuncAttributeMaxDynamicSharedMemorySize, 165888);
    cudaFuncSetAttribute(k_corr_mma, cudaFuncAttributeMaxDynamicSharedMemorySize, 188416);

    const int  Hl[4]      = {128, 64, 32, 16};
    const int  lgWl[4]    = {7, 6, 5, 4};
    const int  HWl[4]     = {16384, 4096, 1024, 256};
    const long corrOff[4] = {0, 9469952, 11837440, 12429312};
    const long mapOff[4]  = {0, 8388608, 10485760, 11010048};
    const long amOff[4]   = {0, 28121600, 35369984, 37293568};
    const long aoOff[4]   = {0, 8652800, 10883072, 11474944};
    const long wmOff[4]   = {0, 1916928, 3833856, 5750784};
    const long woOff[4]   = {0, 589824, 1179648, 1769472};
    const int  zl[4]      = {1, 3, 9, 9};
    const int  tpzl[4]    = {9, 3, 1, 1};
    float* outp = (float*)d_out;

    int gemmBase[5]; gemmBase[0] = 0;
    for (int l = 0; l < 4; l++)
        gemmBase[l + 1] = gemmBase[l] + (2 * HWl[l] / 256) * 2 * zl[l];  // {0,256,448,592,628}

    int npbl[4];
    for (int l = 0; l < 4; l++){
        int Np = 2 * (Hl[l] + 2) * (Hl[l] + 2);
        npbl[l] = (Np + 31) / 32;
    }

    // ---- launch 0: init all atomic output buffers (map+out, levels 1-3) ----
    {
        InitParams P;
        long tot = 0;
        for (int r = 0; r < 3; r++){
            int l = r + 1;
            P.out[r] = mapB + mapOff[l]; P.bias[r] = bm[l]; P.HW[r] = HWl[l];
            P.base[r] = tot; tot += 2L * 256 * HWl[l];
        }
        for (int r = 0; r < 3; r++){
            int l = r + 1;
            P.out[3 + r] = outp + mapOff[l]; P.bias[3 + r] = bo[l]; P.HW[3 + r] = HWl[l];
            P.base[3 + r] = tot; tot += 2L * 256 * HWl[l];
        }
        P.base[6] = tot;
        k_init_all<<<(int)((tot + 255) / 256), 256>>>(P);
    }
    // ---- launch 1: pack all weights ----
    {
        PackWParams P;
        long tot = 0;
        for (int l = 0; l < 4; l++){
            P.src[l] = wm[l]; P.dst[l] = wmh + wmOff[l]; P.Cin[l] = 801; P.Cpad[l] = 832;
            P.base[l] = tot; tot += 256L * 832;
        }
        for (int l = 0; l < 4; l++){
            P.src[4+l] = wo[l]; P.dst[4+l] = woh + woOff[l]; P.Cin[4+l] = 256; P.Cpad[4+l] = 256;
            P.base[4+l] = tot; tot += 256L * 256;
        }
        P.base[8] = tot;
        k_pack_w_all<<<(int)((tot + 255) / 256), 256>>>(P);
    }
    // ---- launch 2: pack x/rx activation chunks (0-15), lo only for x (chunks 0-7) ----
    {
        PackMapParams P;
        int base = 0;
        for (int l = 0; l < 4; l++){
            P.x[l] = x[l]; P.rx[l] = rx[l]; P.corr[l] = corrB + corrOff[l];
            P.Ph[l] = amh + amOff[l]; P.Pl[l] = aml + amOff[l];
            P.H[l] = Hl[l]; P.npb[l] = npbl[l];
            P.blkBase[l] = base;
            base += npbl[l] * 16;
        }
        P.blkBase[4] = base;
        P.cBeg = 0;
        P.loEnd = 8;
        k_pack_map_all<<<base, dim3(32, 8)>>>(P);
    }
    // ---- launch 3: MMA correlation (2-pass, 2 chunks/stage) ----
    {
        CorrMMAParams P;
        int base = 0;
        for (int l = 0; l < 4; l++){
            P.Xh[l] = amh + amOff[l];
            P.Xl[l] = aml + amOff[l];
            P.out[l] = corrB + corrOff[l];
            P.H[l] = Hl[l];
            P.chS[l] = 2L * (Hl[l] + 2) * (Hl[l] + 2) * 32;
            P.blkBase[l] = base;
            int RPB = 128 / Hl[l];
            base += 2 * Hl[l] / RPB;
        }
        P.blkBase[4] = base;
        k_corr_mma<<<base, 256, 188416>>>(P);
    }
    // ---- launch 4: pack corr activation chunks (16-25), hi only ----
    {
        PackMapParams P;
        int base = 0;
        for (int l = 0; l < 4; l++){
            P.x[l] = x[l]; P.rx[l] = rx[l]; P.corr[l] = corrB + corrOff[l];
            P.Ph[l] = amh + amOff[l]; P.Pl[l] = aml + amOff[l];
            P.H[l] = Hl[l]; P.npb[l] = npbl[l];
            P.blkBase[l] = base;
            base += npbl[l] * 10;
        }
        P.blkBase[4] = base;
        P.cBeg = 16;
        P.loEnd = 0;
        k_pack_map_all<<<base, dim3(32, 8)>>>(P);
    }
    // ---- launch 5: merged map GEMM (fully single-pass) ----
    {
        GemmParams P;
        P.A = wmh; P.BhB = amh; P.BlB = aml;
        for (int l = 0; l < 4; l++){
            P.out[l] = mapB + mapOff[l]; P.bias[l] = bm[l];
            P.aOff[l] = wmOff[l]; P.bOff[l] = amOff[l];
            P.H[l] = Hl[l]; P.lgW[l] = lgWl[l]; P.zc[l] = zl[l]; P.tpz[l] = tpzl[l];
        }
        for (int i = 0; i < 5; i++) P.blkBase[i] = gemmBase[i];
        P.CH = 26;
        P.loBeg = 26;
        k_gemm<<<gemmBase[4], 256, 165888>>>(P);
    }
    // ---- launch 6: pack out activations (hi only) with fused upsample cascade ----
    {
        PackOutParams P;
        int base = 0;
        for (int l = 0; l < 4; l++){
            P.map[l] = mapB + mapOff[l];
            P.Ph[l] = aoh + aoOff[l];
            P.H[l] = Hl[l]; P.npb[l] = npbl[l];
            P.blkBase[l] = base;
            base += npbl[l] * 8;
        }
        P.blkBase[4] = base;
        k_pack_out_all<<<base, dim3(32, 8)>>>(P);
    }
    // ---- launch 7: merged out GEMM -> d_out (single-pass) ----
    {
        GemmParams P;
        P.A = woh; P.BhB = aoh; P.BlB = aol;
        for (int l = 0; l < 4; l++){
            P.out[l] = outp + mapOff[l]; P.bias[l] = bo[l];
            P.aOff[l] = woOff[l]; P.bOff[l] = aoOff[l];
            P.H[l] = Hl[l]; P.lgW[l] = lgWl[l]; P.zc[l] = zl[l]; P.tpz[l] = tpzl[l];
        }
        for (int i = 0; i < 5; i++) P.blkBase[i] = gemmBase[i];
        P.CH = 8;
        P.loBeg = 8;
        k_gemm<<<gemmBase[4], 256, 165888>>>(P);
    }
}

// round 17
// speedup vs baseline: 2.2758x; 1.0179x over previous
#include <cuda_runtime.h>
#include <cuda_fp16.h>
#include <cstdint>
#include <cstddef>

#define PADC 8

// ---------------- static device buffers ----------------
__device__ __align__(256) float g_corr[12577280];
__device__ __align__(256) float g_map [11141120];
__device__ __align__(256) __half g_wm_h[7667712];   // [lvl][chunk26][tap9][co256][ci32] swizzled
__device__ __align__(256) __half g_wo_h[2359296];   // [lvl][chunk8][tap9][co256][ci32]
__device__ __align__(256) __half g_am_h[37832704];  // [lvl][chunk][b][Hp][Wp][32] swizzled
__device__ __align__(256) __half g_am_l[37832704];
__device__ __align__(256) __half g_ao_h[11640832];
__device__ __align__(256) __half g_ao_l[11640832];

// ---------------- PTX helpers (compute_103 baseline-safe) ----------------
__device__ __forceinline__ uint32_t smem_u32(const void* p){
    uint32_t a;
    asm("{ .reg .u64 t; cvta.to.shared.u64 t, %1; cvt.u32.u64 %0, t; }" : "=r"(a) : "l"(p));
    return a;
}
__device__ __forceinline__ void mbar_init(uint32_t a, uint32_t cnt){
    asm volatile("mbarrier.init.shared.b64 [%0], %1;" :: "r"(a), "r"(cnt) : "memory");
}
__device__ __forceinline__ void mbar_expect(uint32_t a, uint32_t bytes){
    asm volatile("mbarrier.arrive.expect_tx.shared.b64 _, [%0], %1;" :: "r"(a), "r"(bytes) : "memory");
}
__device__ __forceinline__ void mbar_wait(uint32_t a, int parity){
    asm volatile(
        "{\n\t.reg .pred P;\n\t"
        "WL_%=:\n\t"
        "mbarrier.try_wait.parity.acquire.cta.shared::cta.b64 P, [%0], %1, 0x989680;\n\t"
        "@P bra WD_%=;\n\t"
        "bra WL_%=;\n\t"
        "WD_%=:\n\t}"
        :: "r"(a), "r"(parity) : "memory");
}
__device__ __forceinline__ void bulk_cp(uint32_t dst, const void* src, uint32_t bytes, uint32_t mbar){
    asm volatile(
        "cp.async.bulk.shared::cluster.global.mbarrier::complete_tx::bytes [%0], [%1], %2, [%3];"
        :: "r"(dst), "l"(src), "r"(bytes), "r"(mbar) : "memory");
}
__device__ __forceinline__ void ldmx4(uint32_t* r, uint32_t addr){
    asm volatile("ldmatrix.sync.aligned.m8n8.x4.shared.b16 {%0,%1,%2,%3}, [%4];"
                 : "=r"(r[0]), "=r"(r[1]), "=r"(r[2]), "=r"(r[3]) : "r"(addr));
}
__device__ __forceinline__ void mma16816(float* c, const uint32_t* a, uint32_t b0, uint32_t b1){
    asm volatile(
        "mma.sync.aligned.m16n8k16.row.col.f32.f16.f16.f32 "
        "{%0,%1,%2,%3}, {%4,%5,%6,%7}, {%8,%9}, {%0,%1,%2,%3};"
        : "+f"(c[0]), "+f"(c[1]), "+f"(c[2]), "+f"(c[3])
        : "r"(a[0]), "r"(a[1]), "r"(a[2]), "r"(a[3]), "r"(b0), "r"(b1));
}

// ================= merged init bias (6 regions) =================
struct InitParams {
    float* out[6];
    const float* bias[6];
    int HW[6];
    long base[7];
};
__global__ void k_init_all(const __grid_constant__ InitParams P){
    long i = (long)blockIdx.x * blockDim.x + threadIdx.x;
    if (i >= P.base[6]) return;
    int r = 0;
    #pragma unroll
    for (int k = 1; k < 6; k++) if (i >= P.base[k]) r = k;
    long loc = i - P.base[r];
    P.out[r][loc] = P.bias[r][(loc / P.HW[r]) & 255];
}

// ================= merged weight pack (8 tensors) =================
struct PackWParams {
    const float* src[8];
    __half* dst[8];
    int Cin[8];
    int Cpad[8];
    long base[9];
};
__global__ void k_pack_w_all(const __grid_constant__ PackWParams P){
    long i = (long)blockIdx.x * 256 + threadIdx.x;
    if (i >= P.base[8]) return;
    int t = 0;
    #pragma unroll
    for (int k = 1; k < 8; k++) if (i >= P.base[k]) t = k;
    long loc = i - P.base[t];
    int Cpad = P.Cpad[t], Cin = P.Cin[t];
    int co = (int)(loc / Cpad), ci = (int)(loc % Cpad);
    int c = ci >> 5, cl = ci & 31;
    int gsw = (cl >> 3) ^ ((co >> 1) & 3);
    const float* w = P.src[t];
    __half* oh = P.dst[t];
    #pragma unroll
    for (int tap = 0; tap < 9; tap++){
        float v = (ci < Cin) ? w[(size_t)(co * Cin + ci) * 9 + tap] : 0.f;
        size_t o = (((size_t)c * 9 + tap) * 256 + co) * 32 + (gsw << 3) + (cl & 7);
        oh[o] = __float2half_rn(v);
    }
}

// ================= MMA correlation: corr[w,dj] = band of X^T R =================
// 2-pass (fp32(x) * fp16(r)), FOUR ci-chunks per pipeline stage (17*2 stages).
struct CorrMMAParams {
    const __half* Xh[4];
    const __half* Xl[4];
    float* out[4];
    int H[4];
    long chS[4];
    int blkBase[5];
};
__global__ __launch_bounds__(256)
void k_corr_mma(const __grid_constant__ CorrMMAParams P)
{
    extern __shared__ char dsm[];
    __shared__ __align__(8) unsigned long long mb[3];

    const int bid = blockIdx.x;
    int l = 0;
    if (bid >= P.blkBase[1]) l = 1;
    if (bid >= P.blkBase[2]) l = 2;
    if (bid >= P.blkBase[3]) l = 3;
    const int rel = bid - P.blkBase[l];
    const int H = P.H[l], W = H, Hp = H + 2, Wp = W + 2;
    const int WT = W >> 4;
    const int RPB = 8 / WT;
    const int HB = H / RPB;
    const int b  = rel / HB;
    const int h0 = (rel % HB) * RPB;
    const long chS = P.chS[l];
    const __half* Xh = P.Xh[l];
    const __half* Xl = P.Xl[l];
    float* corr = P.out[l];

    const uint32_t sb = smem_u32(dsm);
    const uint32_t BB = sb + 147456u;        // B bufs: 2 x 40960 (4 hi planes each)
    const uint32_t MBA = smem_u32(&mb[0]);
    const uint32_t MBB = smem_u32(&mb[1]);

    const int tid = threadIdx.x, wid = tid >> 5, lane = tid & 31;
    const int wt = wid % WT, hl = wid / WT;
    const int w0 = wt * 16;
    const int lr = lane & 7, lm8 = ((lane >> 3) & 1) * 8, lk = lane >> 4;

    if (tid == 0){
        mbar_init(MBA, 1);
        mbar_init(MBB, 1);
        mbar_init(MBB + 8, 1);
    }
    __syncthreads();

    const long pA0 = (long)(b * Hp + h0 + 1) * Wp + 1;
    const uint32_t Abytes = (uint32_t)(((RPB - 1) * Wp + W) * 64);

    if (tid == 0){
        mbar_expect(MBA, 16u * Abytes);
        #pragma unroll
        for (int q = 0; q < 8; q++){
            bulk_cp(sb + (q * 2 + 0) * 9216u, Xh + (size_t)q * chS + pA0 * 32, Abytes, MBA);
            bulk_cp(sb + (q * 2 + 1) * 9216u, Xl + (size_t)q * chS + pA0 * 32, Abytes, MBA);
        }
    }

    // stage s: dy = s>>1, half h4 = s&1 -> chunks {4*h4 .. 4*h4+3}
    auto issueB = [&](int s){
        int dy = s >> 1, h4 = s & 1;
        int r0 = h0 + dy - 8;
        int rc0 = (r0 < -1) ? -1 : r0;
        int rc1 = r0 + RPB - 1; if (rc1 > H) rc1 = H;
        if (rc1 < rc0){ rc0 = h0; rc1 = h0; }
        long pB0 = (long)(b * Hp + rc0 + 1) * Wp - 7;
        uint32_t Bb = (uint32_t)(((rc1 - rc0) * Wp + W + 16) * 64);
        int buf = s & 1;
        mbar_expect(MBB + buf * 8, 4u * Bb);
        #pragma unroll
        for (int sc = 0; sc < 4; sc++)
            bulk_cp(BB + buf * 40960u + sc * 10240u,
                    Xh + (size_t)(8 + 4 * h4 + sc) * chS + pB0 * 32, Bb, MBB + buf * 8);
    };

    if (tid == 0) issueB(0);
    mbar_wait(MBA, 0);

    const int offA_px = hl * Wp + w0 + lm8 + lr;
    const int xorA = (int)(((pA0 + offA_px) >> 1) & 3);
    const uint32_t aOff = (uint32_t)offA_px * 64u;

    float acc[4][4];
    const int nStages = 17 * 2;

    for (int s = 0; s < nStages; ++s){
        const int dy = s >> 1, h4 = s & 1;
        if (tid == 0 && s + 1 < nStages) issueB(s + 1);
        mbar_wait(MBB + (s & 1) * 8, (s >> 1) & 1);

        if (h4 == 0){
            #pragma unroll
            for (int f = 0; f < 4; f++)
                #pragma unroll
                for (int e = 0; e < 4; e++) acc[f][e] = 0.f;
        }

        int r0 = h0 + dy - 8;
        int rc0 = (r0 < -1) ? -1 : r0;
        int rc1 = r0 + RPB - 1; if (rc1 > H) rc1 = H;
        if (rc1 < rc0){ rc0 = h0; rc1 = h0; }
        const int r = h0 + hl + dy - 8;
        const bool valid = (r >= rc0 && r <= rc1);

        if (valid){
            const long pB0 = (long)(b * Hp + rc0 + 1) * Wp - 7;
            const int rowBase = (r - rc0) * Wp;
            const int offB0 = rowBase + w0 + lm8 + lr;
            const int offB1 = offB0 + 16;
            const int xb0 = (int)(((pB0 + offB0) >> 1) & 3);
            const int xb1 = (int)(((pB0 + offB1) >> 1) & 3);

            #pragma unroll
            for (int sc = 0; sc < 4; sc++){
                const int qq = 4 * h4 + sc;
                const uint32_t Bh0 = BB + (s & 1) * 40960u + (uint32_t)sc * 10240u;
                const uint32_t Ah0 = sb + (qq * 2 + 0) * 9216u;
                const uint32_t Al0 = sb + (qq * 2 + 1) * 9216u;
                #pragma unroll
                for (int ks = 0; ks < 2; ks++){
                    const int g = 2 * ks + lk;
                    uint32_t ah[4], al[4], bh[2][4];
                    ldmx4(ah, Ah0 + aOff + ((uint32_t)(g ^ xorA) << 4));
                    ldmx4(al, Al0 + aOff + ((uint32_t)(g ^ xorA) << 4));
                    ldmx4(bh[0], Bh0 + (uint32_t)offB0 * 64u + ((uint32_t)(g ^ xb0) << 4));
                    ldmx4(bh[1], Bh0 + (uint32_t)offB1 * 64u + ((uint32_t)(g ^ xb1) << 4));
                    #pragma unroll
                    for (int nf = 0; nf < 2; nf++)
                        #pragma unroll
                        for (int sub = 0; sub < 2; sub++){
                            const int f = nf * 2 + sub;
                            mma16816(acc[f], ah, bh[nf][sub], bh[nf][2 + sub]);
                            mma16816(acc[f], al, bh[nf][sub], bh[nf][2 + sub]);
                        }
                }
            }
        }

        if (h4 == 1){
            const int h = h0 + hl;
            #pragma unroll
            for (int f = 0; f < 4; f++){
                const int nf = f >> 1, sub = f & 1;
                const int nb = nf * 16 + sub * 8 + (lane & 3) * 2;
                #pragma unroll
                for (int e = 0; e < 2; e++){
                    const int n = nb + e;
                    #pragma unroll
                    for (int mh = 0; mh < 2; mh++){
                        const int m = (lane >> 2) + mh * 8;
                        const int w = w0 + m;
                        const int dj = n - m;
                        const int u = w0 - 8 + n;
                        if (dj >= 0 && dj <= 16){
                            float o = (valid && u >= 0 && u < W) ? acc[f][mh * 2 + e] : 0.f;
                            corr[(((long)b * 289 + dy * 17 + dj) * H + h) * W + w] = o;
                        }
                    }
                }
            }
        }
        __syncthreads();
    }
}

// ================= merged map-act pack (chunk-range, lo for chunks < loEnd) =================
struct PackMapParams {
    const float* x[4];
    const float* rx[4];
    const float* corr[4];
    __half* Ph[4];
    __half* Pl[4];
    int H[4];
    int npb[4];
    int blkBase[5];
    int cBeg;
    int loEnd;
};
__global__ void k_pack_map_all(const __grid_constant__ PackMapParams P){
    __shared__ float t[32][33];
    const int bid = blockIdx.x;
    int l = 0;
    if (bid >= P.blkBase[1]) l = 1;
    if (bid >= P.blkBase[2]) l = 2;
    if (bid >= P.blkBase[3]) l = 3;
    const int rel = bid - P.blkBase[l];
    const int npb = P.npb[l];
    const int bxp = rel % npb;
    const int chunk = P.cBeg + rel / npb;
    const int c0  = chunk * 32;
    const int H = P.H[l], W = H;
    const int Hp = H + 2, Wp = W + 2, HW = H * W, Np = 2 * Hp * Wp;
    const int p0 = bxp * 32;

    int px = p0 + threadIdx.x;
    int b = 0, pix = 0; bool inter = false;
    if (px < Np){
        b = px / (Hp * Wp); int r = px % (Hp * Wp); int hp = r / Wp, wp = r % Wp;
        if (hp >= 1 && hp <= H && wp >= 1 && wp <= W){ inter = true; pix = (hp - 1) * W + (wp - 1); }
    }
    const float* X  = P.x[l];
    const float* RX = P.rx[l];
    const float* CR = P.corr[l];
    #pragma unroll
    for (int dyy = 0; dyy < 32; dyy += 8){
        int ci = c0 + (int)threadIdx.y + dyy;
        float v = 0.f;
        if (inter){
            if (ci < 256)       v = X [(size_t)(b * 256 + ci) * HW + pix];
            else if (ci < 512)  v = RX[(size_t)(b * 256 + ci - 256) * HW + pix];
            else if (ci < 801)  v = CR[(size_t)(b * 289 + ci - 512) * HW + pix];
        }
        t[threadIdx.y + dyy][threadIdx.x] = v;
    }
    __syncthreads();
    int ft = threadIdx.y * 32 + threadIdx.x;
    int pl = ft >> 3, sub = ft & 7;
    int px2 = p0 + pl;
    if (px2 < Np){
        size_t chStride = (size_t)2 * Hp * Wp * 32;
        int gsw = (sub >> 1) ^ ((px2 >> 1) & 3);
        size_t base = (size_t)chunk * chStride + (size_t)px2 * 32 + (gsw << 3) + (sub & 1) * 4;
        float v0 = t[sub*4+0][pl], v1 = t[sub*4+1][pl], v2 = t[sub*4+2][pl], v3 = t[sub*4+3][pl];
        __half h0 = __float2half_rn(v0), h1 = __float2half_rn(v1);
        __half h2 = __float2half_rn(v2), h3 = __float2half_rn(v3);
        uint32_t uh0 = (uint32_t)__half_as_ushort(h0) | ((uint32_t)__half_as_ushort(h1) << 16);
        uint32_t uh1 = (uint32_t)__half_as_ushort(h2) | ((uint32_t)__half_as_ushort(h3) << 16);
        uint2 wh; wh.x = uh0; wh.y = uh1;
        *reinterpret_cast<uint2*>(P.Ph[l] + base) = wh;
        if (chunk < P.loEnd){
            __half l0 = __float2half_rn(v0 - __half2float(h0));
            __half l1 = __float2half_rn(v1 - __half2float(h1));
            __half l2 = __float2half_rn(v2 - __half2float(h2));
            __half l3 = __float2half_rn(v3 - __half2float(h3));
            uint32_t ul0 = (uint32_t)__half_as_ushort(l0) | ((uint32_t)__half_as_ushort(l1) << 16);
            uint32_t ul1 = (uint32_t)__half_as_ushort(l2) | ((uint32_t)__half_as_ushort(l3) << 16);
            uint2 wl; wl.x = ul0; wl.y = ul1;
            *reinterpret_cast<uint2*>(P.Pl[l] + base) = wl;
        }
    }
}

// ================= merged out-act pack with fused upsample cascade (hi only) =================
struct PackOutParams {
    const float* map[4];
    __half* Ph[4];
    int H[4];
    int npb[4];
    int blkBase[5];
};
__global__ void k_pack_out_all(const __grid_constant__ PackOutParams P){
    __shared__ float t[32][33];
    const int bid = blockIdx.x;
    int l = 0;
    if (bid >= P.blkBase[1]) l = 1;
    if (bid >= P.blkBase[2]) l = 2;
    if (bid >= P.blkBase[3]) l = 3;
    const int rel = bid - P.blkBase[l];
    const int npb = P.npb[l];
    const int bxp = rel % npb;
    const int c0  = (rel / npb) * 32;
    const int H = P.H[l], W = H;
    const int Hp = H + 2, Wp = W + 2, Np = 2 * Hp * Wp;
    const int p0 = bxp * 32;

    int px = p0 + threadIdx.x;
    int b = 0, hh = 0, ww = 0; bool inter = false;
    if (px < Np){
        b = px / (Hp * Wp); int r = px % (Hp * Wp); int hp = r / Wp, wp = r % Wp;
        if (hp >= 1 && hp <= H && wp >= 1 && wp <= W){ inter = true; hh = hp - 1; ww = wp - 1; }
    }
    #pragma unroll
    for (int dyy = 0; dyy < 32; dyy += 8){
        int ci = c0 + (int)threadIdx.y + dyy;
        float v = 0.f;
        if (inter){
            for (int k = l; k < 4; k++){
                int Wk = P.H[k];
                int sh = k - l;
                v += P.map[k][((size_t)(b * 256 + ci) * Wk + (hh >> sh)) * Wk + (ww >> sh)];
            }
        }
        t[threadIdx.y + dyy][threadIdx.x] = v;
    }
    __syncthreads();
    int ft = threadIdx.y * 32 + threadIdx.x;
    int pl = ft >> 3, sub = ft & 7;
    int px2 = p0 + pl;
    if (px2 < Np){
        size_t chStride = (size_t)2 * Hp * Wp * 32;
        int gsw = (sub >> 1) ^ ((px2 >> 1) & 3);
        size_t base = (size_t)(c0 >> 5) * chStride + (size_t)px2 * 32 + (gsw << 3) + (sub & 1) * 4;
        float v0 = t[sub*4+0][pl], v1 = t[sub*4+1][pl], v2 = t[sub*4+2][pl], v3 = t[sub*4+3][pl];
        __half h0 = __float2half_rn(v0), h1 = __float2half_rn(v1);
        __half h2 = __float2half_rn(v2), h3 = __float2half_rn(v3);
        uint32_t uh0 = (uint32_t)__half_as_ushort(h0) | ((uint32_t)__half_as_ushort(h1) << 16);
        uint32_t uh1 = (uint32_t)__half_as_ushort(h2) | ((uint32_t)__half_as_ushort(h3) << 16);
        uint2 wh; wh.x = uh0; wh.y = uh1;
        *reinterpret_cast<uint2*>(P.Ph[l] + base) = wh;
    }
}

// ================= merged multi-level fp16 implicit-conv GEMM =================
struct GemmParams {
    const __half* A;
    const __half* BhB;
    const __half* BlB;
    float*        out[4];
    const float*  bias[4];
    long aOff[4];
    long bOff[4];
    int  H[4];
    int  lgW[4];
    int  zc[4];
    int  tpz[4];
    int  blkBase[5];
    int  CH;
    int  loBeg;
};

__global__ __launch_bounds__(256)
void k_gemm(const __grid_constant__ GemmParams P)
{
    extern __shared__ char dsm[];
    __shared__ __align__(8) unsigned long long mb[6];

    const int bid = blockIdx.x;
    int l = 0;
    if (bid >= P.blkBase[1]) l = 1;
    if (bid >= P.blkBase[2]) l = 2;
    if (bid >= P.blkBase[3]) l = 3;
    const int rel = bid - P.blkBase[l];
    const int zc = P.zc[l], tapsPerZ = P.tpz[l];
    const int zi = rel % zc;
    const int tt = rel / zc;
    const int m0 = (tt & 1) * 128;
    const int nt = tt >> 1;
    const int H = P.H[l], W = H, lgW = P.lgW[l];
    const __half* A  = P.A   + P.aOff[l];
    const __half* Bh = P.BhB + P.bOff[l];
    const __half* Bl = P.BlB + P.bOff[l];
    float* out = P.out[l];
    const float* bias = P.bias[l];
    const int useAtomic = (zc > 1);
    const int tapBeg = zi * tapsPerZ;
    const int CH = P.CH;
    const int loBeg = P.loBeg;

    const uint32_t smemBase = smem_u32(dsm);
    uint32_t A_OFF[4], B_OFF[2];
    #pragma unroll
    for (int s = 0; s < 4; s++) A_OFF[s] = smemBase + s * 8192u;
    B_OFF[0] = smemBase + 32768u;
    B_OFF[1] = smemBase + 32768u + 66560u;
    const uint32_t MBA = smem_u32(&mb[0]);
    const uint32_t MBB = smem_u32(&mb[4]);

    const int tid = threadIdx.x, wid = tid >> 5, lane = tid & 31;
    const int R = 256 >> lgW;
    const int Hp = H + 2, Wp = W + 2;
    const int tilesPerB = H / R;
    const int b  = nt / tilesPerB;
    const int h0 = (nt % tilesPerB) * R;
    const int q0 = (b * Hp + h0) * Wp;
    const uint32_t Bbytes = (uint32_t)(R + 2) * Wp * 64u;
    const size_t chStride = (size_t)2 * Hp * Wp * 32;

    if (tid == 0){
        #pragma unroll
        for (int i = 0; i < 6; i++) mbar_init(MBA + i * 8, 1);
    }
    __syncthreads();

    const int nA = CH * tapsPerZ;

    auto issueA = [&](int ia){
        int c = ia / tapsPerZ, tap = ia % tapsPerZ;
        const __half* src = A + ((((size_t)c * 9 + (tapBeg + tap)) * 256 + m0) << 5);
        int s = ia & 3;
        mbar_expect(MBA + s * 8, 8192u);
        bulk_cp(A_OFF[s], src, 8192u, MBA + s * 8);
    };
    auto issueB = [&](int c){
        int s = c & 1;
        bool lo = (c >= loBeg);
        mbar_expect(MBB + s * 8, lo ? 2u * Bbytes : Bbytes);
        bulk_cp(B_OFF[s], Bh + (size_t)c * chStride + ((size_t)q0 << 5), Bbytes, MBB + s * 8);
        if (lo)
            bulk_cp(B_OFF[s] + 33280u, Bl + (size_t)c * chStride + ((size_t)q0 << 5), Bbytes, MBB + s * 8);
    };

    const int lr  = lane & 7;
    const int lm8 = ((lane >> 3) & 1) * 8;
    const int lk  = lane >> 4;
    const int wm  = wid & 1;
    const int wn  = wid >> 1;
    const int rowA = wm * 64 + lm8 + lr;
    const int xorA = (lr >> 1) & 3;
    int rB[4], wB[4];
    #pragma unroll
    for (int g = 0; g < 4; g++){
        int n = wn * 64 + g * 16 + lm8 + lr;
        rB[g] = n >> lgW;
        wB[g] = n & (W - 1);
    }

    float acc[4][8][4];
    #pragma unroll
    for (int i = 0; i < 4; i++)
        #pragma unroll
        for (int j = 0; j < 8; j++)
            #pragma unroll
            for (int k = 0; k < 4; k++) acc[i][j][k] = 0.f;

    if (tid == 0){
        issueB(0);
        issueA(0);
        if (nA > 1) issueA(1);
        if (nA > 2) issueA(2);
    }

    for (int it = 0; it < nA; ++it){
        int c = it / tapsPerZ, tap = it % tapsPerZ;
        if (tid == 0){
            if (it + 3 < nA) issueA(it + 3);
            if (tap == 0 && c + 1 < CH) issueB(c + 1);
        }
        mbar_wait(MBA + (it & 3) * 8, (it >> 2) & 1);
        if (tap == 0) mbar_wait(MBB + (c & 1) * 8, (c >> 1) & 1);

        const uint32_t Ab = A_OFF[it & 3];
        const uint32_t Bb = B_OFF[c & 1];
        const int tIdx = tapBeg + tap;
        const int dy = tIdx / 3, dx = tIdx - dy * 3;
        const int nPass = (c >= loBeg) ? 2 : 1;

        uint32_t sAdr[4]; int xorB[4];
        #pragma unroll
        for (int g = 0; g < 4; g++){
            int s = (rB[g] + dy) * Wp + wB[g] + dx;
            sAdr[g] = Bb + (uint32_t)s * 64u;
            xorB[g] = ((q0 + s) >> 1) & 3;
        }

        #pragma unroll
        for (int ks = 0; ks < 2; ks++){
            const int gA = (2 * ks + lk) ^ xorA;
            uint32_t a[4][4];
            #pragma unroll
            for (int ma = 0; ma < 4; ma++)
                ldmx4(a[ma], Ab + (uint32_t)(rowA + ma * 16) * 64u + ((uint32_t)gA << 4));
            for (int pass = 0; pass < nPass; pass++){
                uint32_t bb[4][4];
                #pragma unroll
                for (int g = 0; g < 4; g++){
                    int gB = (2 * ks + lk) ^ xorB[g];
                    ldmx4(bb[g], sAdr[g] + (uint32_t)pass * 33280u + ((uint32_t)gB << 4));
                }
                #pragma unroll
                for (int ma = 0; ma < 4; ma++)
                    #pragma unroll
                    for (int na = 0; na < 8; na++)
                        mma16816(acc[ma][na], a[ma], bb[na >> 1][na & 1], bb[na >> 1][2 + (na & 1)]);
            }
        }
        __syncthreads();
    }

    #pragma unroll
    for (int ma = 0; ma < 4; ma++){
        int co0 = m0 + wm * 64 + ma * 16 + (lane >> 2);
        int co1 = co0 + 8;
        float bv0 = useAtomic ? 0.f : bias[co0];
        float bv1 = useAtomic ? 0.f : bias[co1];
        #pragma unroll
        for (int na = 0; na < 8; na++){
            int n = wn * 64 + na * 8 + (lane & 3) * 2;
            int r = h0 + (n >> lgW);
            int w = n & (W - 1);
            size_t i0 = ((size_t)(b * 256 + co0) * H + r) * W + w;
            size_t i1 = ((size_t)(b * 256 + co1) * H + r) * W + w;
            if (useAtomic){
                atomicAdd(&out[i0],     acc[ma][na][0]);
                atomicAdd(&out[i0 + 1], acc[ma][na][1]);
                atomicAdd(&out[i1],     acc[ma][na][2]);
                atomicAdd(&out[i1 + 1], acc[ma][na][3]);
            } else {
                float2 v0; v0.x = acc[ma][na][0] + bv0; v0.y = acc[ma][na][1] + bv0;
                float2 v1; v1.x = acc[ma][na][2] + bv1; v1.y = acc[ma][na][3] + bv1;
                *reinterpret_cast<float2*>(&out[i0]) = v0;
                *reinterpret_cast<float2*>(&out[i1]) = v1;
            }
        }
    }
}

// ---------------- host orchestration (8 launches total) ----------------
extern "C" void kernel_launch(void* const* d_in, const int* in_sizes, int n_in,
                              void* d_out, int out_size)
{
    const float *x[4]={0,0,0,0}, *rx[4]={0,0,0,0};
    const float *wm[4]={0,0,0,0}, *bm[4]={0,0,0,0}, *wo[4]={0,0,0,0}, *bo[4]={0,0,0,0};
    int wmi = 0, woi = 0, bi = 0;
    for (int i = 0; i < n_in; i++){
        int s = in_sizes[i];
        int lvl = -1;
        if      (s == 2*256*128*128) lvl = 0;
        else if (s == 2*256*64*64)   lvl = 1;
        else if (s == 2*256*32*32)   lvl = 2;
        else if (s == 2*256*16*16)   lvl = 3;
        if (lvl >= 0){
            if (!x[lvl]) x[lvl] = (const float*)d_in[i];
            else         rx[lvl] = (const float*)d_in[i];
        }
        else if (s == 1845504) wm[wmi++] = (const float*)d_in[i];
        else if (s ==  589824) wo[woi++] = (const float*)d_in[i];
        else if (s ==     256){
            if ((bi & 1) == 0) bm[bi >> 1] = (const float*)d_in[i];
            else               bo[bi >> 1] = (const float*)d_in[i];
            bi++;
        }
    }

    float *corrB, *mapB;
    __half *wmh, *woh, *amh, *aml, *aoh, *aol;
    cudaGetSymbolAddress((void**)&corrB, g_corr);
    cudaGetSymbolAddress((void**)&mapB,  g_map);
    cudaGetSymbolAddress((void**)&wmh, g_wm_h);
    cudaGetSymbolAddress((void**)&woh, g_wo_h);
    cudaGetSymbolAddress((void**)&amh, g_am_h); cudaGetSymbolAddress((void**)&aml, g_am_l);
    cudaGetSymbolAddress((void**)&aoh, g_ao_h); cudaGetSymbolAddress((void**)&aol, g_ao_l);

    cudaFuncSetAttribute(k_gemm, cudaFuncAttributeMaxDynamicSharedMemorySize, 165888);
    cudaFuncSetAttribute(k_corr_mma, cudaFuncAttributeMaxDynamicSharedMemorySize, 229376);

    const int  Hl[4]      = {128, 64, 32, 16};
    const int  lgWl[4]    = {7, 6, 5, 4};
    const int  HWl[4]     = {16384, 4096, 1024, 256};
    const long corrOff[4] = {0, 9469952, 11837440, 12429312};
    const long mapOff[4]  = {0, 8388608, 10485760, 11010048};
    const long amOff[4]   = {0, 28121600, 35369984, 37293568};
    const long aoOff[4]   = {0, 8652800, 10883072, 11474944};
    const long wmOff[4]   = {0, 1916928, 3833856, 5750784};
    const long woOff[4]   = {0, 589824, 1179648, 1769472};
    const int  zl[4]      = {1, 3, 9, 9};
    const int  tpzl[4]    = {9, 3, 1, 1};
    float* outp = (float*)d_out;

    int gemmBase[5]; gemmBase[0] = 0;
    for (int l = 0; l < 4; l++)
        gemmBase[l + 1] = gemmBase[l] + (2 * HWl[l] / 256) * 2 * zl[l];  // {0,256,448,592,628}

    int npbl[4];
    for (int l = 0; l < 4; l++){
        int Np = 2 * (Hl[l] + 2) * (Hl[l] + 2);
        npbl[l] = (Np + 31) / 32;
    }

    // ---- launch 0: init all atomic output buffers (map+out, levels 1-3) ----
    {
        InitParams P;
        long tot = 0;
        for (int r = 0; r < 3; r++){
            int l = r + 1;
            P.out[r] = mapB + mapOff[l]; P.bias[r] = bm[l]; P.HW[r] = HWl[l];
            P.base[r] = tot; tot += 2L * 256 * HWl[l];
        }
        for (int r = 0; r < 3; r++){
            int l = r + 1;
            P.out[3 + r] = outp + mapOff[l]; P.bias[3 + r] = bo[l]; P.HW[3 + r] = HWl[l];
            P.base[3 + r] = tot; tot += 2L * 256 * HWl[l];
        }
        P.base[6] = tot;
        k_init_all<<<(int)((tot + 255) / 256), 256>>>(P);
    }
    // ---- launch 1: pack all weights ----
    {
        PackWParams P;
        long tot = 0;
        for (int l = 0; l < 4; l++){
            P.src[l] = wm[l]; P.dst[l] = wmh + wmOff[l]; P.Cin[l] = 801; P.Cpad[l] = 832;
            P.base[l] = tot; tot += 256L * 832;
        }
        for (int l = 0; l < 4; l++){
            P.src[4+l] = wo[l]; P.dst[4+l] = woh + woOff[l]; P.Cin[4+l] = 256; P.Cpad[4+l] = 256;
            P.base[4+l] = tot; tot += 256L * 256;
        }
        P.base[8] = tot;
        k_pack_w_all<<<(int)((tot + 255) / 256), 256>>>(P);
    }
    // ---- launch 2: pack x/rx activation chunks (0-15), lo only for x (chunks 0-7) ----
    {
        PackMapParams P;
        int base = 0;
        for (int l = 0; l < 4; l++){
            P.x[l] = x[l]; P.rx[l] = rx[l]; P.corr[l] = corrB + corrOff[l];
            P.Ph[l] = amh + amOff[l]; P.Pl[l] = aml + amOff[l];
            P.H[l] = Hl[l]; P.npb[l] = npbl[l];
            P.blkBase[l] = base;
            base += npbl[l] * 16;
        }
        P.blkBase[4] = base;
        P.cBeg = 0;
        P.loEnd = 8;
        k_pack_map_all<<<base, dim3(32, 8)>>>(P);
    }
    // ---- launch 3: MMA correlation (2-pass, 4 chunks/stage) ----
    {
        CorrMMAParams P;
        int base = 0;
        for (int l = 0; l < 4; l++){
            P.Xh[l] = amh + amOff[l];
            P.Xl[l] = aml + amOff[l];
            P.out[l] = corrB + corrOff[l];
            P.H[l] = Hl[l];
            P.chS[l] = 2L * (Hl[l] + 2) * (Hl[l] + 2) * 32;
            P.blkBase[l] = base;
            int RPB = 128 / Hl[l];
            base += 2 * Hl[l] / RPB;
        }
        P.blkBase[4] = base;
        k_corr_mma<<<base, 256, 229376>>>(P);
    }
    // ---- launch 4: pack corr activation chunks (16-25), hi only ----
    {
        PackMapParams P;
        int base = 0;
        for (int l = 0; l < 4; l++){
            P.x[l] = x[l]; P.rx[l] = rx[l]; P.corr[l] = corrB + corrOff[l];
            P.Ph[l] = amh + amOff[l]; P.Pl[l] = aml + amOff[l];
            P.H[l] = Hl[l]; P.npb[l] = npbl[l];
            P.blkBase[l] = base;
            base += npbl[l] * 10;
        }
        P.blkBase[4] = base;
        P.cBeg = 16;
        P.loEnd = 0;
        k_pack_map_all<<<base, dim3(32, 8)>>>(P);
    }
    // ---- launch 5: merged map GEMM (fully single-pass) ----
    {
        GemmParams P;
        P.A = wmh; P.BhB = amh; P.BlB = aml;
        for (int l = 0; l < 4; l++){
            P.out[l] = mapB + mapOff[l]; P.bias[l] = bm[l];
            P.aOff[l] = wmOff[l]; P.bOff[l] = amOff[l];
            P.H[l] = Hl[l]; P.lgW[l] = lgWl[l]; P.zc[l] = zl[l]; P.tpz[l] = tpzl[l];
        }
        for (int i = 0; i < 5; i++) P.blkBase[i] = gemmBase[i];
        P.CH = 26;
        P.loBeg = 26;
        k_gemm<<<gemmBase[4], 256, 165888>>>(P);
    }
    // ---- launch 6: pack out activations (hi only) with fused upsample cascade ----
    {
        PackOutParams P;
        int base = 0;
        for (int l = 0; l < 4; l++){
            P.map[l] = mapB + mapOff[l];
            P.Ph[l] = aoh + aoOff[l];
            P.H[l] = Hl[l]; P.npb[l] = npbl[l];
            P.blkBase[l] = base;
            base += npbl[l] * 8;
        }
        P.blkBase[4] = base;
        k_pack_out_all<<<base, dim3(32, 8)>>>(P);
    }
    // ---- launch 7: merged out GEMM -> d_out (single-pass) ----
    {
        GemmParams P;
        P.A = woh; P.BhB = aoh; P.BlB = aol;
        for (int l = 0; l < 4; l++){
            P.out[l] = outp + mapOff[l]; P.bias[l] = bo[l];
            P.aOff[l] = woOff[l]; P.bOff[l] = aoOff[l];
            P.H[l] = Hl[l]; P.lgW[l] = lgWl[l]; P.zc[l] = zl[l]; P.tpz[l] = tpzl[l];
        }
        for (int i = 0; i < 5; i++) P.blkBase[i] = gemmBase[i];
        P.CH = 8;
        P.loBeg = 8;
        k_gemm<<<gemmBase[4], 256, 165888>>>(P);
    }
}